// round 5
// baseline (speedup 1.0000x reference)
#include <cuda_runtime.h>
#include <cuda_bf16.h>
#include <math.h>
#include <stdint.h>

#define B_  4
#define S_  2048
#define SV_ 50
#define E_  1024
#define VP_ 256   // padded v rows per batch

typedef __nv_bfloat16 bf16;

// ---------------- scratch (device globals) ----------------------------------
__device__ float g_q [B_*S_*E_];
__device__ float g_k [B_*S_*E_];
__device__ float g_q2[B_*S_*E_];
__device__ float g_k2[B_*S_*E_];
__device__ float g_cs [B_*E_];
__device__ float g_cs2[B_*E_];

__device__ bf16 g_Qs_h[B_*S_*E_], g_Qs_l[B_*S_*E_];
__device__ bf16 g_Ks_h[B_*S_*E_], g_Ks_l[B_*S_*E_];
__device__ bf16 g_WqT_h[E_*E_],  g_WqT_l[E_*E_];
__device__ bf16 g_WkT_h[E_*E_],  g_WkT_l[E_*E_];
__device__ bf16 g_WvT_h[E_*E_],  g_WvT_l[E_*E_];
__device__ bf16 g_WvqT_h[E_*64], g_WvqT_l[E_*64];
__device__ bf16 g_WvkT_h[E_*64], g_WvkT_l[E_*64];
__device__ bf16 g_Vp_h[B_*VP_*E_], g_Vp_l[B_*VP_*E_];
__device__ bf16 g_vh[B_*VP_*E_],  g_vl[B_*VP_*E_];
__device__ bf16 g_qh[B_*S_*E_],  g_ql[B_*S_*E_];
__device__ bf16 g_kh[B_*S_*E_],  g_kl[B_*S_*E_];
__device__ bf16 g_qTh[B_*S_*E_], g_qTl[B_*S_*E_];
__device__ bf16 g_kTh[B_*S_*E_], g_kTl[B_*S_*E_];
__device__ bf16 g_vqh[B_*S_*VP_], g_vql[B_*S_*VP_];
__device__ bf16 g_vkh[B_*S_*VP_], g_vkl[B_*S_*VP_];
__device__ bf16 g_fh[(size_t)B_*S_*S_], g_fl[(size_t)B_*S_*S_];
__device__ bf16 g_q2Th[B_*S_*E_], g_q2Tl[B_*S_*E_];
__device__ bf16 g_k2Th[B_*S_*E_], g_k2Tl[B_*S_*E_];

// ---------------- PTX helpers ------------------------------------------------
__device__ __forceinline__ uint32_t smem_u32(const void* p) {
    uint32_t a;
    asm("{ .reg .u64 t; cvta.to.shared.u64 t, %1; cvt.u32.u64 %0, t; }"
        : "=r"(a) : "l"(p));
    return a;
}
__device__ __forceinline__ void cp_async16(uint32_t dst, const void* src) {
    asm volatile("cp.async.cg.shared.global [%0], [%1], 16;"
                 :: "r"(dst), "l"(src) : "memory");
}
#define CP_COMMIT() asm volatile("cp.async.commit_group;" ::: "memory")
#define CP_WAIT(n)  asm volatile("cp.async.wait_group %0;" :: "n"(n) : "memory")

#define LDMATRIX_X4(r0, r1, r2, r3, addr) \
    asm volatile("ldmatrix.sync.aligned.m8n8.x4.shared.b16 {%0,%1,%2,%3}, [%4];" \
        : "=r"(r0), "=r"(r1), "=r"(r2), "=r"(r3) : "r"(addr))

#define MMA_BF16(d, a, b) \
    asm volatile("mma.sync.aligned.m16n8k16.row.col.f32.bf16.bf16.f32 " \
        "{%0,%1,%2,%3},{%4,%5,%6,%7},{%8,%9},{%0,%1,%2,%3};" \
        : "+f"((d)[0]), "+f"((d)[1]), "+f"((d)[2]), "+f"((d)[3]) \
        : "r"((a)[0]), "r"((a)[1]), "r"((a)[2]), "r"((a)[3]), \
          "r"((b)[0]), "r"((b)[1]))

// ---------------- bf16x3 HMMA NT GEMM ----------------------------------------
// C[z] = alpha * (Ah+Al)[M,K] @ (Bh+Bl)[N,K]^T (+beta*C) (+bias[n])
// OUTM: 0 = fp32 C; 1 = fp32 C + bf16 split (Oh/Ol); 2 = bf16 split only.
// Requires M%128==0, N%256==0, K%32==0 (all call sites satisfy).
// SMEM stage: Ah 8K | Al 8K | Bh 16K | Bl 16K = 48K; 3 stages = 144K.
constexpr int HG_STAGE = 49152;
constexpr int HG_SMEM  = 3 * HG_STAGE;

template<int OUTM, bool BETA, bool BIAS>
__global__ void __launch_bounds__(256, 1)
hmma_nt(const bf16* __restrict__ Ah, const bf16* __restrict__ Al,
        const bf16* __restrict__ Bh, const bf16* __restrict__ Bl,
        float* __restrict__ C, bf16* __restrict__ Oh, bf16* __restrict__ Ol,
        const float* __restrict__ bias,
        int M, int N, int K, int lda, int ldb, int ldc,
        long long sA, long long sB, long long sC, long long sBias,
        float alpha, float beta)
{
    extern __shared__ char sm[];
    const uint32_t sbase = smem_u32(sm);

    Ah += blockIdx.z * sA;  Al += blockIdx.z * sA;
    Bh += blockIdx.z * sB;  Bl += blockIdx.z * sB;
    const long long co = blockIdx.z * sC;
    const float* bp = BIAS ? (bias + blockIdx.z * sBias) : nullptr;

    const int tid = threadIdx.x;
    const int warp = tid >> 5, lane = tid & 31;
    const int wm = warp & 1, wn = warp >> 1;      // 2x4 warps: 64m x 64n each
    const int bm = blockIdx.y * 128;
    const int bn = blockIdx.x * 256;
    const int NT = K / 32;

    auto issue = [&](int it) {
        if (it >= NT) return;
        const uint32_t sb0 = sbase + (uint32_t)(it % 3) * HG_STAGE;
        const long long ko = (long long)it * 32;
#pragma unroll
        for (int j = 0; j < 2; j++) {              // A: 512 chunks per half
            int c = tid * 2 + j;
            int r = c >> 2, cc = c & 3;
            uint32_t dst = sb0 + (uint32_t)(r * 64 + ((cc ^ ((r >> 1) & 3)) << 4));
            long long src = (long long)(bm + r) * lda + ko + cc * 8;
            cp_async16(dst,        Ah + src);
            cp_async16(dst + 8192, Al + src);
        }
#pragma unroll
        for (int j = 0; j < 4; j++) {              // B: 1024 chunks per half
            int c = tid * 4 + j;
            int r = c >> 2, cc = c & 3;
            uint32_t dst = sb0 + 16384u + (uint32_t)(r * 64 + ((cc ^ ((r >> 1) & 3)) << 4));
            long long src = (long long)(bn + r) * ldb + ko + cc * 8;
            cp_async16(dst,         Bh + src);
            cp_async16(dst + 16384, Bl + src);
        }
    };

    float acc[4][8][4];
#pragma unroll
    for (int m = 0; m < 4; m++)
#pragma unroll
        for (int n = 0; n < 8; n++)
#pragma unroll
            for (int j = 0; j < 4; j++) acc[m][n][j] = 0.f;

    issue(0); CP_COMMIT();
    issue(1); CP_COMMIT();
    issue(2); CP_COMMIT();

    const int lr = lane & 15, lh2 = lane >> 4;

    for (int kt = 0; kt < NT; ++kt) {
        CP_WAIT(2);
        __syncthreads();
        const uint32_t sb0 = sbase + (uint32_t)(kt % 3) * HG_STAGE;
#pragma unroll
        for (int ks = 0; ks < 2; ks++) {
            uint32_t fAh[4][4], fAl[4][4], fB[8][2];
#pragma unroll
            for (int t = 0; t < 4; t++) {
                int row = wm * 64 + t * 16 + lr;
                int cch = (ks * 2 + lh2) ^ ((row >> 1) & 3);
                uint32_t a = sb0 + (uint32_t)(row * 64 + (cch << 4));
                LDMATRIX_X4(fAh[t][0], fAh[t][1], fAh[t][2], fAh[t][3], a);
                LDMATRIX_X4(fAl[t][0], fAl[t][1], fAl[t][2], fAl[t][3], a + 8192);
            }
#pragma unroll
            for (int p = 0; p < 4; p++) {
                int row = wn * 64 + p * 16 + lr;
                int cch = (ks * 2 + lh2) ^ ((row >> 1) & 3);
                uint32_t a = sb0 + 16384u + (uint32_t)(row * 64 + (cch << 4));
                uint32_t r0, r1, r2, r3;
                LDMATRIX_X4(r0, r1, r2, r3, a);
                fB[p*2][0]   = r0; fB[p*2][1]   = r2;
                fB[p*2+1][0] = r1; fB[p*2+1][1] = r3;
            }
            // hh + lh
#pragma unroll
            for (int m = 0; m < 4; m++)
#pragma unroll
                for (int n = 0; n < 8; n++) MMA_BF16(acc[m][n], fAh[m], fB[n]);
#pragma unroll
            for (int m = 0; m < 4; m++)
#pragma unroll
                for (int n = 0; n < 8; n++) MMA_BF16(acc[m][n], fAl[m], fB[n]);
            // B lo
#pragma unroll
            for (int p = 0; p < 4; p++) {
                int row = wn * 64 + p * 16 + lr;
                int cch = (ks * 2 + lh2) ^ ((row >> 1) & 3);
                uint32_t a = sb0 + 32768u + (uint32_t)(row * 64 + (cch << 4));
                uint32_t r0, r1, r2, r3;
                LDMATRIX_X4(r0, r1, r2, r3, a);
                fB[p*2][0]   = r0; fB[p*2][1]   = r2;
                fB[p*2+1][0] = r1; fB[p*2+1][1] = r3;
            }
#pragma unroll
            for (int m = 0; m < 4; m++)
#pragma unroll
                for (int n = 0; n < 8; n++) MMA_BF16(acc[m][n], fAh[m], fB[n]);
        }
        __syncthreads();
        issue(kt + 3); CP_COMMIT();
    }

    // epilogue
    const int qr = lane >> 2, qc = (lane & 3) * 2;
#pragma unroll
    for (int mt = 0; mt < 4; mt++) {
#pragma unroll
        for (int nt = 0; nt < 8; nt++) {
            const int col = bn + wn * 64 + nt * 8 + qc;
#pragma unroll
            for (int h = 0; h < 2; h++) {
                const int row = bm + wm * 64 + mt * 16 + qr + h * 8;
                const long long o = co + (long long)row * ldc + col;
                float2 v;
                v.x = alpha * acc[mt][nt][h*2 + 0];
                v.y = alpha * acc[mt][nt][h*2 + 1];
                if (BETA) {
                    float2 c0v = *(const float2*)(C + o);
                    v.x += beta * c0v.x; v.y += beta * c0v.y;
                }
                if (BIAS) { v.x += bp[col]; v.y += bp[col + 1]; }
                if (OUTM == 0 || OUTM == 1) *(float2*)(C + o) = v;
                if (OUTM == 1 || OUTM == 2) {
                    bf16 hx = __float2bfloat16(v.x), hy = __float2bfloat16(v.y);
                    bf16 lx = __float2bfloat16(v.x - __bfloat162float(hx));
                    bf16 ly = __float2bfloat16(v.y - __bfloat162float(hy));
                    *(__nv_bfloat162*)(Oh + o) = __nv_bfloat162(hx, hy);
                    *(__nv_bfloat162*)(Ol + o) = __nv_bfloat162(lx, ly);
                }
            }
        }
    }
}

// ---------------- split kernels ----------------------------------------------
template<bool TANH>
__global__ void split_k(const float* __restrict__ x, bf16* __restrict__ h,
                        bf16* __restrict__ l, long long n)
{
    long long i = ((long long)blockIdx.x * blockDim.x + threadIdx.x) * 4;
    if (i >= n) return;
    float4 v = *(const float4*)(x + i);
    if (TANH) { v.x = tanhf(v.x); v.y = tanhf(v.y); v.z = tanhf(v.z); v.w = tanhf(v.w); }
    bf16 h0 = __float2bfloat16(v.x), h1 = __float2bfloat16(v.y);
    bf16 h2 = __float2bfloat16(v.z), h3 = __float2bfloat16(v.w);
    bf16 l0 = __float2bfloat16(v.x - __bfloat162float(h0));
    bf16 l1 = __float2bfloat16(v.y - __bfloat162float(h1));
    bf16 l2 = __float2bfloat16(v.z - __bfloat162float(h2));
    bf16 l3 = __float2bfloat16(v.w - __bfloat162float(h3));
    __nv_bfloat162* hp = (__nv_bfloat162*)(h + i);
    __nv_bfloat162* lp = (__nv_bfloat162*)(l + i);
    hp[0] = __nv_bfloat162(h0, h1); hp[1] = __nv_bfloat162(h2, h3);
    lp[0] = __nv_bfloat162(l0, l1); lp[1] = __nv_bfloat162(l2, l3);
}

// tanh + pad + split: V [B,SV,E] -> Vp [B,VP,E], rows >= SV are zero
__global__ void padsplitV_k(const float* __restrict__ V, bf16* __restrict__ h,
                            bf16* __restrict__ l)
{
    long long i = ((long long)blockIdx.x * blockDim.x + threadIdx.x) * 4;
    int b = (int)(i / (VP_ * E_));
    int rem = (int)(i % (VP_ * E_));
    int r = rem / E_, e = rem % E_;
    float4 v = make_float4(0.f, 0.f, 0.f, 0.f);
    if (r < SV_) {
        v = *(const float4*)(V + ((long long)(b * SV_ + r)) * E_ + e);
        v.x = tanhf(v.x); v.y = tanhf(v.y); v.z = tanhf(v.z); v.w = tanhf(v.w);
    }
    bf16 h0 = __float2bfloat16(v.x), h1 = __float2bfloat16(v.y);
    bf16 h2 = __float2bfloat16(v.z), h3 = __float2bfloat16(v.w);
    bf16 l0 = __float2bfloat16(v.x - __bfloat162float(h0));
    bf16 l1 = __float2bfloat16(v.y - __bfloat162float(h1));
    bf16 l2 = __float2bfloat16(v.z - __bfloat162float(h2));
    bf16 l3 = __float2bfloat16(v.w - __bfloat162float(h3));
    __nv_bfloat162* hp = (__nv_bfloat162*)(h + i);
    __nv_bfloat162* lp = (__nv_bfloat162*)(l + i);
    hp[0] = __nv_bfloat162(h0, h1); hp[1] = __nv_bfloat162(h2, h3);
    lp[0] = __nv_bfloat162(l0, l1); lp[1] = __nv_bfloat162(l2, l3);
}

// transpose + split: in [R,C] -> out [C,Rpad] bf16 hi/lo; rows >= R read as 0
__global__ void splitT_k(const float* __restrict__ x, bf16* __restrict__ h,
                         bf16* __restrict__ l, int R, int C, int Rpad,
                         long long sIn, long long sOut)
{
    __shared__ float t[32][33];
    const float* xb = x + blockIdx.z * sIn;
    int r0 = blockIdx.y * 32, c0 = blockIdx.x * 32;
#pragma unroll
    for (int i = 0; i < 4; i++) {
        int r = r0 + threadIdx.y + i * 8;
        t[threadIdx.y + i * 8][threadIdx.x] =
            (r < R) ? xb[(long long)r * C + c0 + threadIdx.x] : 0.f;
    }
    __syncthreads();
#pragma unroll
    for (int i = 0; i < 4; i++) {
        int c = c0 + threadIdx.y + i * 8;
        float v = t[threadIdx.x][threadIdx.y + i * 8];
        long long o = blockIdx.z * sOut + (long long)c * Rpad + r0 + threadIdx.x;
        bf16 hh = __float2bfloat16(v);
        h[o] = hh;
        l[o] = __float2bfloat16(v - __bfloat162float(hh));
    }
}

// ---------------- softmax (+ fused split) / colsum ---------------------------
__global__ void softmax_split(float* __restrict__ x, bf16* __restrict__ h,
                              bf16* __restrict__ l, int cols)
{
    long long r = blockIdx.x;
    float* p = x + r * (long long)cols;
    __shared__ float red[256];
    int t = threadIdx.x;
    float mx = -INFINITY;
    for (int c = t; c < cols; c += 256) mx = fmaxf(mx, p[c]);
    red[t] = mx; __syncthreads();
    for (int s = 128; s > 0; s >>= 1) { if (t < s) red[t] = fmaxf(red[t], red[t + s]); __syncthreads(); }
    mx = red[0]; __syncthreads();
    float sum = 0.f;
    for (int c = t; c < cols; c += 256) { float e = expf(p[c] - mx); p[c] = e; sum += e; }
    red[t] = sum; __syncthreads();
    for (int s = 128; s > 0; s >>= 1) { if (t < s) red[t] += red[t + s]; __syncthreads(); }
    float inv = 1.f / red[0];
    long long base = r * (long long)cols;
    for (int c = t; c < cols; c += 256) {
        float val = p[c] * inv;
        p[c] = val;
        bf16 hh = __float2bfloat16(val);
        h[base + c] = hh;
        l[base + c] = __float2bfloat16(val - __bfloat162float(hh));
    }
}

__global__ void colsum_kernel(const float* __restrict__ x, float* __restrict__ out,
                              int T, int E)
{
    int e = blockIdx.x * blockDim.x + threadIdx.x;
    int b = blockIdx.y;
    const float* p = x + (long long)b * T * E + e;
    float s = 0.f;
    for (int t = 0; t < T; t++) s += p[(long long)t * E];
    out[(long long)b * E + e] = s;
}

// ---------------- host launcher ----------------------------------------------
extern "C" void kernel_launch(void* const* d_in, const int* in_sizes, int n_in,
                              void* d_out, int out_size)
{
    const float* Q    = (const float*)d_in[0];
    const float* K    = (const float*)d_in[1];
    const float* V    = (const float*)d_in[2];
    const float* W_Q  = (const float*)d_in[3];
    const float* W_K  = (const float*)d_in[4];
    const float* W_v  = (const float*)d_in[5];
    const float* W_vq = (const float*)d_in[6];
    const float* W_vk = (const float*)d_in[7];

    float* out  = (float*)d_out;
    float* outQ = out;
    float* outK = out + (long long)B_ * S_ * E_;
    float* f    = out + 2ll * B_ * S_ * E_;

    float *q, *k, *q2, *k2, *cs, *cs2;
    cudaGetSymbolAddress((void**)&q,   g_q);
    cudaGetSymbolAddress((void**)&k,   g_k);
    cudaGetSymbolAddress((void**)&q2,  g_q2);
    cudaGetSymbolAddress((void**)&k2,  g_k2);
    cudaGetSymbolAddress((void**)&cs,  g_cs);
    cudaGetSymbolAddress((void**)&cs2, g_cs2);

    bf16 *Qsh,*Qsl,*Ksh,*Ksl,*WqTh,*WqTl,*WkTh,*WkTl,*WvTh,*WvTl;
    bf16 *WvqTh,*WvqTl,*WvkTh,*WvkTl,*Vph,*Vpl,*vh,*vl;
    bf16 *qh,*ql,*kh,*kl,*qTh,*qTl,*kTh,*kTl;
    bf16 *vqh,*vql,*vkh,*vkl,*fh,*fl,*q2Th,*q2Tl,*k2Th,*k2Tl;
    cudaGetSymbolAddress((void**)&Qsh,  g_Qs_h);  cudaGetSymbolAddress((void**)&Qsl,  g_Qs_l);
    cudaGetSymbolAddress((void**)&Ksh,  g_Ks_h);  cudaGetSymbolAddress((void**)&Ksl,  g_Ks_l);
    cudaGetSymbolAddress((void**)&WqTh, g_WqT_h); cudaGetSymbolAddress((void**)&WqTl, g_WqT_l);
    cudaGetSymbolAddress((void**)&WkTh, g_WkT_h); cudaGetSymbolAddress((void**)&WkTl, g_WkT_l);
    cudaGetSymbolAddress((void**)&WvTh, g_WvT_h); cudaGetSymbolAddress((void**)&WvTl, g_WvT_l);
    cudaGetSymbolAddress((void**)&WvqTh,g_WvqT_h);cudaGetSymbolAddress((void**)&WvqTl,g_WvqT_l);
    cudaGetSymbolAddress((void**)&WvkTh,g_WvkT_h);cudaGetSymbolAddress((void**)&WvkTl,g_WvkT_l);
    cudaGetSymbolAddress((void**)&Vph,  g_Vp_h);  cudaGetSymbolAddress((void**)&Vpl,  g_Vp_l);
    cudaGetSymbolAddress((void**)&vh,   g_vh);    cudaGetSymbolAddress((void**)&vl,   g_vl);
    cudaGetSymbolAddress((void**)&qh,   g_qh);    cudaGetSymbolAddress((void**)&ql,   g_ql);
    cudaGetSymbolAddress((void**)&kh,   g_kh);    cudaGetSymbolAddress((void**)&kl,   g_kl);
    cudaGetSymbolAddress((void**)&qTh,  g_qTh);   cudaGetSymbolAddress((void**)&qTl,  g_qTl);
    cudaGetSymbolAddress((void**)&kTh,  g_kTh);   cudaGetSymbolAddress((void**)&kTl,  g_kTl);
    cudaGetSymbolAddress((void**)&vqh,  g_vqh);   cudaGetSymbolAddress((void**)&vql,  g_vql);
    cudaGetSymbolAddress((void**)&vkh,  g_vkh);   cudaGetSymbolAddress((void**)&vkl,  g_vkl);
    cudaGetSymbolAddress((void**)&fh,   g_fh);    cudaGetSymbolAddress((void**)&fl,   g_fl);
    cudaGetSymbolAddress((void**)&q2Th, g_q2Th);  cudaGetSymbolAddress((void**)&q2Tl, g_q2Tl);
    cudaGetSymbolAddress((void**)&k2Th, g_k2Th);  cudaGetSymbolAddress((void**)&k2Tl, g_k2Tl);

    cudaFuncSetAttribute(hmma_nt<0,false,false>, cudaFuncAttributeMaxDynamicSharedMemorySize, HG_SMEM);
    cudaFuncSetAttribute(hmma_nt<0,false,true >, cudaFuncAttributeMaxDynamicSharedMemorySize, HG_SMEM);
    cudaFuncSetAttribute(hmma_nt<0,true, false>, cudaFuncAttributeMaxDynamicSharedMemorySize, HG_SMEM);
    cudaFuncSetAttribute(hmma_nt<1,false,false>, cudaFuncAttributeMaxDynamicSharedMemorySize, HG_SMEM);
    cudaFuncSetAttribute(hmma_nt<2,false,false>, cudaFuncAttributeMaxDynamicSharedMemorySize, HG_SMEM);

    const float inv = 1.0f / 32.0f;  // 1/sqrt(1024)
    const long long sQE = (long long)S_ * E_;
    const long long sSS = (long long)S_ * S_;
    const long long sVE = (long long)VP_ * E_;
    const long long sSV = (long long)S_ * VP_;
    const long long nQE = (long long)B_ * S_ * E_;

    // ---- stage 0: input splits ---------------------------------------------
    split_k<true><<<(int)(nQE/4/256), 256>>>(Q, Qsh, Qsl, nQE);
    split_k<true><<<(int)(nQE/4/256), 256>>>(K, Ksh, Ksl, nQE);
    splitT_k<<<dim3(32,32,1), dim3(32,8)>>>(W_Q,  WqTh,  WqTl,  E_, E_, E_, 0, 0);
    splitT_k<<<dim3(32,32,1), dim3(32,8)>>>(W_K,  WkTh,  WkTl,  E_, E_, E_, 0, 0);
    splitT_k<<<dim3(32,32,1), dim3(32,8)>>>(W_v,  WvTh,  WvTl,  E_, E_, E_, 0, 0);
    splitT_k<<<dim3(32,2,1),  dim3(32,8)>>>(W_vq, WvqTh, WvqTl, SV_, E_, 64, 0, 0);
    splitT_k<<<dim3(32,2,1),  dim3(32,8)>>>(W_vk, WvkTh, WvkTl, SV_, E_, 64, 0, 0);
    padsplitV_k<<<(int)(B_*VP_*E_/4/256), 256>>>(V, Vph, Vpl);

    // ---- stage 1: projections + v ------------------------------------------
    hmma_nt<1,false,false><<<dim3(4,64,1), 256, HG_SMEM>>>(
        Qsh,Qsl, WqTh,WqTl, q, qh,ql, nullptr,
        B_*S_, E_, E_, E_, E_, E_, 0,0,0,0, 1.f, 0.f);
    hmma_nt<1,false,false><<<dim3(4,64,1), 256, HG_SMEM>>>(
        Ksh,Ksl, WkTh,WkTl, k, kh,kl, nullptr,
        B_*S_, E_, E_, E_, E_, E_, 0,0,0,0, 1.f, 0.f);
    hmma_nt<2,false,false><<<dim3(4,8,1), 256, HG_SMEM>>>(
        Vph,Vpl, WvTh,WvTl, nullptr, vh,vl, nullptr,
        B_*VP_, E_, E_, E_, E_, E_, 0,0,0,0, 1.f, 0.f);

    // ---- stage 2: q/k transposed splits, colsum(k) -------------------------
    splitT_k<<<dim3(32,64,B_), dim3(32,8)>>>(q, qTh, qTl, S_, E_, S_, sQE, sQE);
    splitT_k<<<dim3(32,64,B_), dim3(32,8)>>>(k, kTh, kTl, S_, E_, S_, sQE, sQE);
    colsum_kernel<<<dim3(E_/256,B_), 256>>>(k, cs, S_, E_);

    // ---- stage 3: f = softmax(q@k^T/32) (+ fused split) --------------------
    hmma_nt<0,false,false><<<dim3(8,16,B_), 256, HG_SMEM>>>(
        qh,ql, kh,kl, f, nullptr,nullptr, nullptr,
        S_, S_, E_, E_, E_, S_, sQE, sQE, sSS, 0, inv, 0.f);
    softmax_split<<<B_*S_, 256>>>(f, fh, fl, S_);

    // ---- vq/vk + q2/k2 base ------------------------------------------------
    hmma_nt<2,false,false><<<dim3(1,16,B_), 256, HG_SMEM>>>(
        qh,ql, vh,vl, nullptr, vqh,vql, nullptr,
        S_, VP_, E_, E_, E_, VP_, sQE, sVE, sSV, 0, inv, 0.f);
    hmma_nt<2,false,false><<<dim3(1,16,B_), 256, HG_SMEM>>>(
        kh,kl, vh,vl, nullptr, vkh,vkl, nullptr,
        S_, VP_, E_, E_, E_, VP_, sQE, sVE, sSV, 0, inv, 0.f);
    hmma_nt<0,false,false><<<dim3(4,16,B_), 256, HG_SMEM>>>(
        vqh,vql, WvqTh,WvqTl, q2, nullptr,nullptr, nullptr,
        S_, E_, 64, VP_, 64, E_, sSV, 0, sQE, 0, 1.f, 0.f);
    hmma_nt<0,false,true><<<dim3(4,16,B_), 256, HG_SMEM>>>(
        vkh,vkl, WvkTh,WvkTl, k2, nullptr,nullptr, cs,
        S_, E_, 64, VP_, 64, E_, sSV, 0, sQE, E_, 1.f, 0.f);

    // ---- stage 4: q2 += f@q ; k2 -= f@k ------------------------------------
    hmma_nt<0,true,false><<<dim3(4,16,B_), 256, HG_SMEM>>>(
        fh,fl, qTh,qTl, q2, nullptr,nullptr, nullptr,
        S_, E_, S_, S_, S_, E_, sSS, sQE, sQE, 0, 1.f, 1.f);
    hmma_nt<0,true,false><<<dim3(4,16,B_), 256, HG_SMEM>>>(
        fh,fl, kTh,kTl, k2, nullptr,nullptr, nullptr,
        S_, E_, S_, S_, S_, E_, sSS, sQE, sQE, 0, -1.f, 1.f);

    // ---- stage 5: outputs ---------------------------------------------------
    splitT_k<<<dim3(32,64,B_), dim3(32,8)>>>(q2, q2Th, q2Tl, S_, E_, S_, sQE, sQE);
    splitT_k<<<dim3(32,64,B_), dim3(32,8)>>>(k2, k2Th, k2Tl, S_, E_, S_, sQE, sQE);
    colsum_kernel<<<dim3(E_/256,B_), 256>>>(k2, cs2, S_, E_);

    hmma_nt<0,false,false><<<dim3(4,16,B_), 256, HG_SMEM>>>(
        fh,fl, q2Th,q2Tl, outQ, nullptr,nullptr, nullptr,
        S_, E_, S_, S_, S_, E_, sSS, sQE, sQE, 0, 1.f, 0.f);
    hmma_nt<0,false,true><<<dim3(4,16,B_), 256, HG_SMEM>>>(
        fh,fl, k2Th,k2Tl, outK, nullptr,nullptr, cs2,
        S_, E_, S_, S_, S_, E_, sSS, sQE, sQE, E_, -1.f, 0.f);

    (void)in_sizes; (void)n_in; (void)out_size;
}

// round 6
// speedup vs baseline: 1.2999x; 1.2999x over previous
#include <cuda_runtime.h>
#include <cuda_bf16.h>
#include <math.h>
#include <stdint.h>

#define B_  4
#define S_  2048
#define SV_ 50
#define E_  1024
#define VP_ 256   // padded v rows per batch

typedef __nv_bfloat16 bf16;

// ---------------- scratch (device globals) ----------------------------------
__device__ float g_q [B_*S_*E_];
__device__ float g_k [B_*S_*E_];
__device__ float g_q2[B_*S_*E_];
__device__ float g_k2[B_*S_*E_];
__device__ float g_cs [B_*E_];
__device__ float g_cs2[B_*E_];

__device__ bf16 g_Qs_h[B_*S_*E_], g_Qs_l[B_*S_*E_];
__device__ bf16 g_Ks_h[B_*S_*E_], g_Ks_l[B_*S_*E_];
__device__ bf16 g_WqT_h[E_*E_],  g_WqT_l[E_*E_];
__device__ bf16 g_WkT_h[E_*E_],  g_WkT_l[E_*E_];
__device__ bf16 g_WvT_h[E_*E_],  g_WvT_l[E_*E_];
__device__ bf16 g_WvqT_h[E_*64], g_WvqT_l[E_*64];
__device__ bf16 g_WvkT_h[E_*64], g_WvkT_l[E_*64];
__device__ bf16 g_Vp_h[B_*VP_*E_], g_Vp_l[B_*VP_*E_];
__device__ bf16 g_vh[B_*VP_*E_],  g_vl[B_*VP_*E_];
__device__ bf16 g_qh[B_*S_*E_],  g_ql[B_*S_*E_];
__device__ bf16 g_kh[B_*S_*E_],  g_kl[B_*S_*E_];
__device__ bf16 g_qTh[B_*S_*E_], g_qTl[B_*S_*E_];
__device__ bf16 g_kTh[B_*S_*E_], g_kTl[B_*S_*E_];
__device__ bf16 g_vqh[B_*S_*VP_], g_vql[B_*S_*VP_];
__device__ bf16 g_vkh[B_*S_*VP_], g_vkl[B_*S_*VP_];
__device__ bf16 g_fh[(size_t)B_*S_*S_], g_fl[(size_t)B_*S_*S_];
__device__ bf16 g_q2Th[B_*S_*E_], g_q2Tl[B_*S_*E_];
__device__ bf16 g_k2Th[B_*S_*E_], g_k2Tl[B_*S_*E_];

// ---------------- PTX helpers ------------------------------------------------
__device__ __forceinline__ uint32_t smem_u32(const void* p) {
    uint32_t a;
    asm("{ .reg .u64 t; cvta.to.shared.u64 t, %1; cvt.u32.u64 %0, t; }"
        : "=r"(a) : "l"(p));
    return a;
}
__device__ __forceinline__ void cp_async16(uint32_t dst, const void* src) {
    asm volatile("cp.async.cg.shared.global [%0], [%1], 16;"
                 :: "r"(dst), "l"(src) : "memory");
}
#define CP_COMMIT() asm volatile("cp.async.commit_group;" ::: "memory")
#define CP_WAIT(n)  asm volatile("cp.async.wait_group %0;" :: "n"(n) : "memory")

#define LDMATRIX_X4(r0, r1, r2, r3, addr) \
    asm volatile("ldmatrix.sync.aligned.m8n8.x4.shared.b16 {%0,%1,%2,%3}, [%4];" \
        : "=r"(r0), "=r"(r1), "=r"(r2), "=r"(r3) : "r"(addr))

#define MMA_BF16(d, a, b) \
    asm volatile("mma.sync.aligned.m16n8k16.row.col.f32.bf16.bf16.f32 " \
        "{%0,%1,%2,%3},{%4,%5,%6,%7},{%8,%9},{%0,%1,%2,%3};" \
        : "+f"((d)[0]), "+f"((d)[1]), "+f"((d)[2]), "+f"((d)[3]) \
        : "r"((a)[0]), "r"((a)[1]), "r"((a)[2]), "r"((a)[3]), \
          "r"((b)[0]), "r"((b)[1]))

// ---------------- bf16x3 HMMA NT GEMM (Round-4 core + OUTM epilogues) --------
// C[z] = alpha * (Ah+Al)[M,K] @ (Bh+Bl)[N,K]^T (+beta*C) (+bias[n])
// OUTM: 0 = fp32 C; 1 = fp32 C + bf16 split (Oh/Ol); 2 = bf16 split only.
// Requires M%128==0, N%128==0, K%32==0 (all call sites satisfy).
constexpr int HM_BM = 128, HM_BN = 128, HM_BK = 32;
constexpr int HM_LDS = HM_BK + 8;            // padded row (elements)
constexpr int HM_TILE = HM_BM * HM_LDS;      // 5120 elems per tensor-half
constexpr int HM_BUF = 4 * HM_TILE;          // Ah,Al,Bh,Bl per buffer
constexpr int HM_SMEM_BYTES = 2 * HM_BUF * 2; // 81920

template<int OUTM, bool BETA, bool BIAS>
__global__ void __launch_bounds__(256, 2)
hmma_nt(const bf16* __restrict__ Ah, const bf16* __restrict__ Al,
        const bf16* __restrict__ Bh, const bf16* __restrict__ Bl,
        float* __restrict__ C, bf16* __restrict__ Oh, bf16* __restrict__ Ol,
        const float* __restrict__ bias,
        int M, int N, int K, int lda, int ldb, int ldc,
        long long sA, long long sB, long long sC, long long sBias,
        float alpha, float beta)
{
    extern __shared__ bf16 sm[];
    const uint32_t sbase = smem_u32(sm);

    Ah += blockIdx.z * sA;  Al += blockIdx.z * sA;
    Bh += blockIdx.z * sB;  Bl += blockIdx.z * sB;
    const long long co = blockIdx.z * sC;
    const float* bp = BIAS ? (bias + blockIdx.z * sBias) : nullptr;

    const int tid = threadIdx.x;
    const int warp = tid >> 5, lane = tid & 31;
    const int wm = warp & 3, wn = warp >> 2;         // 4x2 warps: 32m x 64n each
    const int bm = blockIdx.y * HM_BM;
    const int bn = blockIdx.x * HM_BN;

    // chunk mapping for cp.async: 512 chunks (16B) per tensor-half per buffer
    const int c0 = tid, c1 = tid + 256;
    const int r0c = c0 >> 2, e0c = (c0 & 3) * 8;
    const int r1c = c1 >> 2, e1c = (c1 & 3) * 8;

    auto issue = [&](int it, int buf) {
        const long long ko = (long long)it * HM_BK;
        const uint32_t bofs = (uint32_t)buf * HM_BUF;
        {
            uint32_t d0 = sbase + (bofs + r0c * HM_LDS + e0c) * 2;
            uint32_t d1 = sbase + (bofs + r1c * HM_LDS + e1c) * 2;
            cp_async16(d0,             Ah + (long long)(bm + r0c) * lda + ko + e0c);
            cp_async16(d1,             Ah + (long long)(bm + r1c) * lda + ko + e1c);
            cp_async16(d0 + HM_TILE*2, Al + (long long)(bm + r0c) * lda + ko + e0c);
            cp_async16(d1 + HM_TILE*2, Al + (long long)(bm + r1c) * lda + ko + e1c);
        }
        {
            uint32_t d0 = sbase + (bofs + 2*HM_TILE + r0c * HM_LDS + e0c) * 2;
            uint32_t d1 = sbase + (bofs + 2*HM_TILE + r1c * HM_LDS + e1c) * 2;
            cp_async16(d0,             Bh + (long long)(bn + r0c) * ldb + ko + e0c);
            cp_async16(d1,             Bh + (long long)(bn + r1c) * ldb + ko + e1c);
            cp_async16(d0 + HM_TILE*2, Bl + (long long)(bn + r0c) * ldb + ko + e0c);
            cp_async16(d1 + HM_TILE*2, Bl + (long long)(bn + r1c) * ldb + ko + e1c);
        }
    };

    float acc[2][8][4];
#pragma unroll
    for (int m = 0; m < 2; m++)
#pragma unroll
        for (int n = 0; n < 8; n++)
#pragma unroll
            for (int j = 0; j < 4; j++) acc[m][n][j] = 0.f;

    const int NT = K / HM_BK;
    issue(0, 0); CP_COMMIT();

    const int lr  = lane & 15;
    const int lc8 = (lane >> 4) << 3;

    for (int kt = 0; kt < NT; ++kt) {
        const int buf = kt & 1;
        if (kt + 1 < NT) { issue(kt + 1, buf ^ 1); CP_COMMIT(); CP_WAIT(1); }
        else             { CP_WAIT(0); }
        __syncthreads();

        const uint32_t aofs = (uint32_t)buf * HM_BUF;
#pragma unroll
        for (int ks = 0; ks < 2; ks++) {
            const int k0 = ks * 16;
            uint32_t fAh[2][4], fAl[2][4], fB[8][2];
#pragma unroll
            for (int t = 0; t < 2; t++) {
                uint32_t a = sbase + (aofs + (uint32_t)(wm*32 + t*16 + lr) * HM_LDS + k0 + lc8) * 2;
                LDMATRIX_X4(fAh[t][0], fAh[t][1], fAh[t][2], fAh[t][3], a);
            }
#pragma unroll
            for (int p = 0; p < 4; p++) {
                uint32_t a = sbase + (aofs + 2*HM_TILE + (uint32_t)(wn*64 + p*16 + lr) * HM_LDS + k0 + lc8) * 2;
                uint32_t r0, r1, r2, r3;
                LDMATRIX_X4(r0, r1, r2, r3, a);
                fB[p*2][0]   = r0; fB[p*2][1]   = r2;
                fB[p*2+1][0] = r1; fB[p*2+1][1] = r3;
            }
            // hh
#pragma unroll
            for (int m = 0; m < 2; m++)
#pragma unroll
                for (int n = 0; n < 8; n++) MMA_BF16(acc[m][n], fAh[m], fB[n]);
            // A lo + lh
#pragma unroll
            for (int t = 0; t < 2; t++) {
                uint32_t a = sbase + (aofs + HM_TILE + (uint32_t)(wm*32 + t*16 + lr) * HM_LDS + k0 + lc8) * 2;
                LDMATRIX_X4(fAl[t][0], fAl[t][1], fAl[t][2], fAl[t][3], a);
            }
#pragma unroll
            for (int m = 0; m < 2; m++)
#pragma unroll
                for (int n = 0; n < 8; n++) MMA_BF16(acc[m][n], fAl[m], fB[n]);
            // B lo + hl
#pragma unroll
            for (int p = 0; p < 4; p++) {
                uint32_t a = sbase + (aofs + 3*HM_TILE + (uint32_t)(wn*64 + p*16 + lr) * HM_LDS + k0 + lc8) * 2;
                uint32_t r0, r1, r2, r3;
                LDMATRIX_X4(r0, r1, r2, r3, a);
                fB[p*2][0]   = r0; fB[p*2][1]   = r2;
                fB[p*2+1][0] = r1; fB[p*2+1][1] = r3;
            }
#pragma unroll
            for (int m = 0; m < 2; m++)
#pragma unroll
                for (int n = 0; n < 8; n++) MMA_BF16(acc[m][n], fAh[m], fB[n]);
        }
        __syncthreads();
    }

    // epilogue
    const int qr = lane >> 2, qc = (lane & 3) * 2;
#pragma unroll
    for (int mt = 0; mt < 2; mt++) {
#pragma unroll
        for (int nt = 0; nt < 8; nt++) {
            const int col = bn + wn*64 + nt*8 + qc;
#pragma unroll
            for (int h = 0; h < 2; h++) {
                const int row = bm + wm*32 + mt*16 + qr + h*8;
                const long long o = co + (long long)row * ldc + col;
                float2 v;
                v.x = alpha * acc[mt][nt][h*2 + 0];
                v.y = alpha * acc[mt][nt][h*2 + 1];
                if (BETA) {
                    float2 c0v = *(const float2*)(C + o);
                    v.x += beta * c0v.x; v.y += beta * c0v.y;
                }
                if (BIAS) { v.x += bp[col]; v.y += bp[col + 1]; }
                if (OUTM == 0 || OUTM == 1) *(float2*)(C + o) = v;
                if (OUTM == 1 || OUTM == 2) {
                    bf16 hx = __float2bfloat16(v.x), hy = __float2bfloat16(v.y);
                    bf16 lx = __float2bfloat16(v.x - __bfloat162float(hx));
                    bf16 ly = __float2bfloat16(v.y - __bfloat162float(hy));
                    *(__nv_bfloat162*)(Oh + o) = __nv_bfloat162(hx, hy);
                    *(__nv_bfloat162*)(Ol + o) = __nv_bfloat162(lx, ly);
                }
            }
        }
    }
}

// ---------------- split kernels ----------------------------------------------
template<bool TANH>
__global__ void split_k(const float* __restrict__ x, bf16* __restrict__ h,
                        bf16* __restrict__ l, long long n)
{
    long long i = ((long long)blockIdx.x * blockDim.x + threadIdx.x) * 4;
    if (i >= n) return;
    float4 v = *(const float4*)(x + i);
    if (TANH) { v.x = tanhf(v.x); v.y = tanhf(v.y); v.z = tanhf(v.z); v.w = tanhf(v.w); }
    bf16 h0 = __float2bfloat16(v.x), h1 = __float2bfloat16(v.y);
    bf16 h2 = __float2bfloat16(v.z), h3 = __float2bfloat16(v.w);
    bf16 l0 = __float2bfloat16(v.x - __bfloat162float(h0));
    bf16 l1 = __float2bfloat16(v.y - __bfloat162float(h1));
    bf16 l2 = __float2bfloat16(v.z - __bfloat162float(h2));
    bf16 l3 = __float2bfloat16(v.w - __bfloat162float(h3));
    __nv_bfloat162* hp = (__nv_bfloat162*)(h + i);
    __nv_bfloat162* lp = (__nv_bfloat162*)(l + i);
    hp[0] = __nv_bfloat162(h0, h1); hp[1] = __nv_bfloat162(h2, h3);
    lp[0] = __nv_bfloat162(l0, l1); lp[1] = __nv_bfloat162(l2, l3);
}

// tanh + pad + split: V [B,SV,E] -> Vp [B,VP,E], rows >= SV are zero
__global__ void padsplitV_k(const float* __restrict__ V, bf16* __restrict__ h,
                            bf16* __restrict__ l)
{
    long long i = ((long long)blockIdx.x * blockDim.x + threadIdx.x) * 4;
    int b = (int)(i / (VP_ * E_));
    int rem = (int)(i % (VP_ * E_));
    int r = rem / E_, e = rem % E_;
    float4 v = make_float4(0.f, 0.f, 0.f, 0.f);
    if (r < SV_) {
        v = *(const float4*)(V + ((long long)(b * SV_ + r)) * E_ + e);
        v.x = tanhf(v.x); v.y = tanhf(v.y); v.z = tanhf(v.z); v.w = tanhf(v.w);
    }
    bf16 h0 = __float2bfloat16(v.x), h1 = __float2bfloat16(v.y);
    bf16 h2 = __float2bfloat16(v.z), h3 = __float2bfloat16(v.w);
    bf16 l0 = __float2bfloat16(v.x - __bfloat162float(h0));
    bf16 l1 = __float2bfloat16(v.y - __bfloat162float(h1));
    bf16 l2 = __float2bfloat16(v.z - __bfloat162float(h2));
    bf16 l3 = __float2bfloat16(v.w - __bfloat162float(h3));
    __nv_bfloat162* hp = (__nv_bfloat162*)(h + i);
    __nv_bfloat162* lp = (__nv_bfloat162*)(l + i);
    hp[0] = __nv_bfloat162(h0, h1); hp[1] = __nv_bfloat162(h2, h3);
    lp[0] = __nv_bfloat162(l0, l1); lp[1] = __nv_bfloat162(l2, l3);
}

// transpose + split: in [R,C] -> out [C,Rpad] bf16 hi/lo; rows >= R read as 0
__global__ void splitT_k(const float* __restrict__ x, bf16* __restrict__ h,
                         bf16* __restrict__ l, int R, int C, int Rpad,
                         long long sIn, long long sOut)
{
    __shared__ float t[32][33];
    const float* xb = x + blockIdx.z * sIn;
    int r0 = blockIdx.y * 32, c0 = blockIdx.x * 32;
#pragma unroll
    for (int i = 0; i < 4; i++) {
        int r = r0 + threadIdx.y + i * 8;
        t[threadIdx.y + i * 8][threadIdx.x] =
            (r < R) ? xb[(long long)r * C + c0 + threadIdx.x] : 0.f;
    }
    __syncthreads();
#pragma unroll
    for (int i = 0; i < 4; i++) {
        int c = c0 + threadIdx.y + i * 8;
        float v = t[threadIdx.x][threadIdx.y + i * 8];
        long long o = blockIdx.z * sOut + (long long)c * Rpad + r0 + threadIdx.x;
        bf16 hh = __float2bfloat16(v);
        h[o] = hh;
        l[o] = __float2bfloat16(v - __bfloat162float(hh));
    }
}

// ---------------- softmax (+ fused split) / colsum ---------------------------
__global__ void softmax_split(float* __restrict__ x, bf16* __restrict__ h,
                              bf16* __restrict__ l, int cols)
{
    long long r = blockIdx.x;
    float* p = x + r * (long long)cols;
    __shared__ float red[256];
    int t = threadIdx.x;
    float mx = -INFINITY;
    for (int c = t; c < cols; c += 256) mx = fmaxf(mx, p[c]);
    red[t] = mx; __syncthreads();
    for (int s = 128; s > 0; s >>= 1) { if (t < s) red[t] = fmaxf(red[t], red[t + s]); __syncthreads(); }
    mx = red[0]; __syncthreads();
    float sum = 0.f;
    for (int c = t; c < cols; c += 256) { float e = expf(p[c] - mx); p[c] = e; sum += e; }
    red[t] = sum; __syncthreads();
    for (int s = 128; s > 0; s >>= 1) { if (t < s) red[t] += red[t + s]; __syncthreads(); }
    float inv = 1.f / red[0];
    long long base = r * (long long)cols;
    for (int c = t; c < cols; c += 256) {
        float val = p[c] * inv;
        p[c] = val;
        bf16 hh = __float2bfloat16(val);
        h[base + c] = hh;
        l[base + c] = __float2bfloat16(val - __bfloat162float(hh));
    }
}

__global__ void colsum_kernel(const float* __restrict__ x, float* __restrict__ out,
                              int T, int E)
{
    int e = blockIdx.x * blockDim.x + threadIdx.x;
    int b = blockIdx.y;
    const float* p = x + (long long)b * T * E + e;
    float s = 0.f;
    for (int t = 0; t < T; t++) s += p[(long long)t * E];
    out[(long long)b * E + e] = s;
}

// ---------------- host launcher ----------------------------------------------
extern "C" void kernel_launch(void* const* d_in, const int* in_sizes, int n_in,
                              void* d_out, int out_size)
{
    const float* Q    = (const float*)d_in[0];
    const float* K    = (const float*)d_in[1];
    const float* V    = (const float*)d_in[2];
    const float* W_Q  = (const float*)d_in[3];
    const float* W_K  = (const float*)d_in[4];
    const float* W_v  = (const float*)d_in[5];
    const float* W_vq = (const float*)d_in[6];
    const float* W_vk = (const float*)d_in[7];

    float* out  = (float*)d_out;
    float* outQ = out;
    float* outK = out + (long long)B_ * S_ * E_;
    float* f    = out + 2ll * B_ * S_ * E_;

    float *q, *k, *q2, *k2, *cs, *cs2;
    cudaGetSymbolAddress((void**)&q,   g_q);
    cudaGetSymbolAddress((void**)&k,   g_k);
    cudaGetSymbolAddress((void**)&q2,  g_q2);
    cudaGetSymbolAddress((void**)&k2,  g_k2);
    cudaGetSymbolAddress((void**)&cs,  g_cs);
    cudaGetSymbolAddress((void**)&cs2, g_cs2);

    bf16 *Qsh,*Qsl,*Ksh,*Ksl,*WqTh,*WqTl,*WkTh,*WkTl,*WvTh,*WvTl;
    bf16 *WvqTh,*WvqTl,*WvkTh,*WvkTl,*Vph,*Vpl,*vh,*vl;
    bf16 *qh,*ql,*kh,*kl,*qTh,*qTl,*kTh,*kTl;
    bf16 *vqh,*vql,*vkh,*vkl,*fh,*fl,*q2Th,*q2Tl,*k2Th,*k2Tl;
    cudaGetSymbolAddress((void**)&Qsh,  g_Qs_h);  cudaGetSymbolAddress((void**)&Qsl,  g_Qs_l);
    cudaGetSymbolAddress((void**)&Ksh,  g_Ks_h);  cudaGetSymbolAddress((void**)&Ksl,  g_Ks_l);
    cudaGetSymbolAddress((void**)&WqTh, g_WqT_h); cudaGetSymbolAddress((void**)&WqTl, g_WqT_l);
    cudaGetSymbolAddress((void**)&WkTh, g_WkT_h); cudaGetSymbolAddress((void**)&WkTl, g_WkT_l);
    cudaGetSymbolAddress((void**)&WvTh, g_WvT_h); cudaGetSymbolAddress((void**)&WvTl, g_WvT_l);
    cudaGetSymbolAddress((void**)&WvqTh,g_WvqT_h);cudaGetSymbolAddress((void**)&WvqTl,g_WvqT_l);
    cudaGetSymbolAddress((void**)&WvkTh,g_WvkT_h);cudaGetSymbolAddress((void**)&WvkTl,g_WvkT_l);
    cudaGetSymbolAddress((void**)&Vph,  g_Vp_h);  cudaGetSymbolAddress((void**)&Vpl,  g_Vp_l);
    cudaGetSymbolAddress((void**)&vh,   g_vh);    cudaGetSymbolAddress((void**)&vl,   g_vl);
    cudaGetSymbolAddress((void**)&qh,   g_qh);    cudaGetSymbolAddress((void**)&ql,   g_ql);
    cudaGetSymbolAddress((void**)&kh,   g_kh);    cudaGetSymbolAddress((void**)&kl,   g_kl);
    cudaGetSymbolAddress((void**)&qTh,  g_qTh);   cudaGetSymbolAddress((void**)&qTl,  g_qTl);
    cudaGetSymbolAddress((void**)&kTh,  g_kTh);   cudaGetSymbolAddress((void**)&kTl,  g_kTl);
    cudaGetSymbolAddress((void**)&vqh,  g_vqh);   cudaGetSymbolAddress((void**)&vql,  g_vql);
    cudaGetSymbolAddress((void**)&vkh,  g_vkh);   cudaGetSymbolAddress((void**)&vkl,  g_vkl);
    cudaGetSymbolAddress((void**)&fh,   g_fh);    cudaGetSymbolAddress((void**)&fl,   g_fl);
    cudaGetSymbolAddress((void**)&q2Th, g_q2Th);  cudaGetSymbolAddress((void**)&q2Tl, g_q2Tl);
    cudaGetSymbolAddress((void**)&k2Th, g_k2Th);  cudaGetSymbolAddress((void**)&k2Tl, g_k2Tl);

    cudaFuncSetAttribute(hmma_nt<0,false,false>, cudaFuncAttributeMaxDynamicSharedMemorySize, HM_SMEM_BYTES);
    cudaFuncSetAttribute(hmma_nt<0,false,true >, cudaFuncAttributeMaxDynamicSharedMemorySize, HM_SMEM_BYTES);
    cudaFuncSetAttribute(hmma_nt<0,true, false>, cudaFuncAttributeMaxDynamicSharedMemorySize, HM_SMEM_BYTES);
    cudaFuncSetAttribute(hmma_nt<1,false,false>, cudaFuncAttributeMaxDynamicSharedMemorySize, HM_SMEM_BYTES);
    cudaFuncSetAttribute(hmma_nt<2,false,false>, cudaFuncAttributeMaxDynamicSharedMemorySize, HM_SMEM_BYTES);

    const float inv = 1.0f / 32.0f;  // 1/sqrt(1024)
    const long long sQE = (long long)S_ * E_;
    const long long sSS = (long long)S_ * S_;
    const long long sVE = (long long)VP_ * E_;
    const long long sSV = (long long)S_ * VP_;
    const long long nQE = (long long)B_ * S_ * E_;

    // ---- stage 0: input splits ---------------------------------------------
    split_k<true><<<(int)(nQE/4/256), 256>>>(Q, Qsh, Qsl, nQE);
    split_k<true><<<(int)(nQE/4/256), 256>>>(K, Ksh, Ksl, nQE);
    splitT_k<<<dim3(32,32,1), dim3(32,8)>>>(W_Q,  WqTh,  WqTl,  E_, E_, E_, 0, 0);
    splitT_k<<<dim3(32,32,1), dim3(32,8)>>>(W_K,  WkTh,  WkTl,  E_, E_, E_, 0, 0);
    splitT_k<<<dim3(32,32,1), dim3(32,8)>>>(W_v,  WvTh,  WvTl,  E_, E_, E_, 0, 0);
    splitT_k<<<dim3(32,2,1),  dim3(32,8)>>>(W_vq, WvqTh, WvqTl, SV_, E_, 64, 0, 0);
    splitT_k<<<dim3(32,2,1),  dim3(32,8)>>>(W_vk, WvkTh, WvkTl, SV_, E_, 64, 0, 0);
    padsplitV_k<<<(int)(B_*VP_*E_/4/256), 256>>>(V, Vph, Vpl);

    // ---- stage 1: projections + v (fused bf16 split in epilogue) -----------
    hmma_nt<1,false,false><<<dim3(8,64,1), 256, HM_SMEM_BYTES>>>(
        Qsh,Qsl, WqTh,WqTl, q, qh,ql, nullptr,
        B_*S_, E_, E_, E_, E_, E_, 0,0,0,0, 1.f, 0.f);
    hmma_nt<1,false,false><<<dim3(8,64,1), 256, HM_SMEM_BYTES>>>(
        Ksh,Ksl, WkTh,WkTl, k, kh,kl, nullptr,
        B_*S_, E_, E_, E_, E_, E_, 0,0,0,0, 1.f, 0.f);
    hmma_nt<2,false,false><<<dim3(8,8,1), 256, HM_SMEM_BYTES>>>(
        Vph,Vpl, WvTh,WvTl, nullptr, vh,vl, nullptr,
        B_*VP_, E_, E_, E_, E_, E_, 0,0,0,0, 1.f, 0.f);

    // ---- stage 2: q/k transposed splits, colsum(k) -------------------------
    splitT_k<<<dim3(32,64,B_), dim3(32,8)>>>(q, qTh, qTl, S_, E_, S_, sQE, sQE);
    splitT_k<<<dim3(32,64,B_), dim3(32,8)>>>(k, kTh, kTl, S_, E_, S_, sQE, sQE);
    colsum_kernel<<<dim3(E_/256,B_), 256>>>(k, cs, S_, E_);

    // ---- stage 3: f = softmax(q@k^T/32) (+ fused split) --------------------
    hmma_nt<0,false,false><<<dim3(16,16,B_), 256, HM_SMEM_BYTES>>>(
        qh,ql, kh,kl, f, nullptr,nullptr, nullptr,
        S_, S_, E_, E_, E_, S_, sQE, sQE, sSS, 0, inv, 0.f);
    softmax_split<<<B_*S_, 256>>>(f, fh, fl, S_);

    // ---- vq/vk + q2/k2 base ------------------------------------------------
    hmma_nt<2,false,false><<<dim3(2,16,B_), 256, HM_SMEM_BYTES>>>(
        qh,ql, vh,vl, nullptr, vqh,vql, nullptr,
        S_, VP_, E_, E_, E_, VP_, sQE, sVE, sSV, 0, inv, 0.f);
    hmma_nt<2,false,false><<<dim3(2,16,B_), 256, HM_SMEM_BYTES>>>(
        kh,kl, vh,vl, nullptr, vkh,vkl, nullptr,
        S_, VP_, E_, E_, E_, VP_, sQE, sVE, sSV, 0, inv, 0.f);
    hmma_nt<0,false,false><<<dim3(8,16,B_), 256, HM_SMEM_BYTES>>>(
        vqh,vql, WvqTh,WvqTl, q2, nullptr,nullptr, nullptr,
        S_, E_, 64, VP_, 64, E_, sSV, 0, sQE, 0, 1.f, 0.f);
    hmma_nt<0,false,true><<<dim3(8,16,B_), 256, HM_SMEM_BYTES>>>(
        vkh,vkl, WvkTh,WvkTl, k2, nullptr,nullptr, cs,
        S_, E_, 64, VP_, 64, E_, sSV, 0, sQE, E_, 1.f, 0.f);

    // ---- stage 4: q2 += f@q ; k2 -= f@k ------------------------------------
    hmma_nt<0,true,false><<<dim3(8,16,B_), 256, HM_SMEM_BYTES>>>(
        fh,fl, qTh,qTl, q2, nullptr,nullptr, nullptr,
        S_, E_, S_, S_, S_, E_, sSS, sQE, sQE, 0, 1.f, 1.f);
    hmma_nt<0,true,false><<<dim3(8,16,B_), 256, HM_SMEM_BYTES>>>(
        fh,fl, kTh,kTl, k2, nullptr,nullptr, nullptr,
        S_, E_, S_, S_, S_, E_, sSS, sQE, sQE, 0, -1.f, 1.f);

    // ---- stage 5: outputs ---------------------------------------------------
    splitT_k<<<dim3(32,64,B_), dim3(32,8)>>>(q2, q2Th, q2Tl, S_, E_, S_, sQE, sQE);
    splitT_k<<<dim3(32,64,B_), dim3(32,8)>>>(k2, k2Th, k2Tl, S_, E_, S_, sQE, sQE);
    colsum_kernel<<<dim3(E_/256,B_), 256>>>(k2, cs2, S_, E_);

    hmma_nt<0,false,false><<<dim3(8,16,B_), 256, HM_SMEM_BYTES>>>(
        fh,fl, q2Th,q2Tl, outQ, nullptr,nullptr, nullptr,
        S_, E_, S_, S_, S_, E_, sSS, sQE, sQE, 0, 1.f, 0.f);
    hmma_nt<0,false,true><<<dim3(8,16,B_), 256, HM_SMEM_BYTES>>>(
        fh,fl, k2Th,k2Tl, outK, nullptr,nullptr, cs2,
        S_, E_, S_, S_, S_, E_, sSS, sQE, sQE, E_, -1.f, 0.f);

    (void)in_sizes; (void)n_in; (void)out_size;
}

// round 7
// speedup vs baseline: 1.7494x; 1.3458x over previous
#include <cuda_runtime.h>
#include <cuda_fp16.h>
#include <math.h>
#include <stdint.h>

#define B_  4
#define S_  2048
#define SV_ 50
#define E_  1024
#define VP_ 256   // padded v rows per batch

typedef __half fp16;

// ---------------- scratch (device globals) ----------------------------------
__device__ float g_q [B_*S_*E_];
__device__ float g_k [B_*S_*E_];
__device__ float g_q2[B_*S_*E_];
__device__ float g_k2[B_*S_*E_];
__device__ float g_cs [B_*E_];
__device__ float g_cs2[B_*E_];

__device__ fp16 g_Qs_h[B_*S_*E_], g_Qs_l[B_*S_*E_];
__device__ fp16 g_Ks_h[B_*S_*E_], g_Ks_l[B_*S_*E_];
__device__ fp16 g_WqT_h[E_*E_];
__device__ fp16 g_WkT_h[E_*E_];
__device__ fp16 g_WvT_h[E_*E_];
__device__ fp16 g_WvqT_h[E_*64];
__device__ fp16 g_WvkT_h[E_*64];
__device__ fp16 g_Vp_h[B_*VP_*E_], g_Vp_l[B_*VP_*E_];
__device__ fp16 g_vh[B_*VP_*E_],  g_vl[B_*VP_*E_];   // vl = scratch (unused as B)
__device__ fp16 g_qh[B_*S_*E_],  g_ql[B_*S_*E_];
__device__ fp16 g_kh[B_*S_*E_],  g_kl[B_*S_*E_];
__device__ fp16 g_qTh[B_*S_*E_];
__device__ fp16 g_kTh[B_*S_*E_];
__device__ fp16 g_vqh[B_*S_*VP_], g_vql[B_*S_*VP_];
__device__ fp16 g_vkh[B_*S_*VP_], g_vkl[B_*S_*VP_];
__device__ fp16 g_fh[(size_t)B_*S_*S_], g_fl[(size_t)B_*S_*S_];
__device__ fp16 g_q2Th[B_*S_*E_];
__device__ fp16 g_k2Th[B_*S_*E_];

// ---------------- PTX helpers ------------------------------------------------
__device__ __forceinline__ uint32_t smem_u32(const void* p) {
    uint32_t a;
    asm("{ .reg .u64 t; cvta.to.shared.u64 t, %1; cvt.u32.u64 %0, t; }"
        : "=r"(a) : "l"(p));
    return a;
}
__device__ __forceinline__ void cp_async16(uint32_t dst, const void* src) {
    asm volatile("cp.async.cg.shared.global [%0], [%1], 16;"
                 :: "r"(dst), "l"(src) : "memory");
}
#define CP_COMMIT() asm volatile("cp.async.commit_group;" ::: "memory")
#define CP_WAIT(n)  asm volatile("cp.async.wait_group %0;" :: "n"(n) : "memory")

#define LDMATRIX_X4(r0, r1, r2, r3, addr) \
    asm volatile("ldmatrix.sync.aligned.m8n8.x4.shared.b16 {%0,%1,%2,%3}, [%4];" \
        : "=r"(r0), "=r"(r1), "=r"(r2), "=r"(r3) : "r"(addr))

#define MMA_F16(d, a, b) \
    asm volatile("mma.sync.aligned.m16n8k16.row.col.f32.f16.f16.f32 " \
        "{%0,%1,%2,%3},{%4,%5,%6,%7},{%8,%9},{%0,%1,%2,%3};" \
        : "+f"((d)[0]), "+f"((d)[1]), "+f"((d)[2]), "+f"((d)[3]) \
        : "r"((a)[0]), "r"((a)[1]), "r"((a)[2]), "r"((a)[3]), \
          "r"((b)[0]), "r"((b)[1]))

// ---------------- fp16x2 HMMA NT GEMM ----------------------------------------
// C[z] = alpha * (Ah+Al)[M,K] @ Bh[N,K]^T (+beta*C) (+bias[n])
// A is fp16 hi/lo split; B single fp16 (error ~2^-12, well under 1e-3 gate).
// OUTM: 0 = fp32 C; 1 = fp32 C + fp16 split (Oh/Ol); 2 = fp16 split only.
// Requires M%128==0, N%128==0, K%32==0 (all call sites satisfy).
constexpr int HM_BM = 128, HM_BN = 128, HM_BK = 32;
constexpr int HM_LDS = HM_BK + 8;              // padded row (elements)
constexpr int HM_TILE = HM_BM * HM_LDS;        // 5120 elems per tile
constexpr int HM_TILE_B = HM_TILE * 2;         // 10240 bytes
constexpr int HM_STAGE_B = 3 * HM_TILE_B;      // Ah | Al | Bh = 30720 bytes
constexpr int HM_SMEM_BYTES = 3 * HM_STAGE_B;  // 3-stage ring = 92160

template<int OUTM, bool BETA, bool BIAS>
__global__ void __launch_bounds__(256, 2)
hmma_nt(const fp16* __restrict__ Ah, const fp16* __restrict__ Al,
        const fp16* __restrict__ Bh,
        float* __restrict__ C, fp16* __restrict__ Oh, fp16* __restrict__ Ol,
        const float* __restrict__ bias,
        int M, int N, int K, int lda, int ldb, int ldc,
        long long sA, long long sB, long long sC, long long sBias,
        float alpha, float beta)
{
    extern __shared__ fp16 sm[];
    const uint32_t sbase = smem_u32(sm);

    Ah += blockIdx.z * sA;  Al += blockIdx.z * sA;
    Bh += blockIdx.z * sB;
    const long long co = blockIdx.z * sC;
    const float* bp = BIAS ? (bias + blockIdx.z * sBias) : nullptr;

    const int tid = threadIdx.x;
    const int warp = tid >> 5, lane = tid & 31;
    const int wm = warp & 3, wn = warp >> 2;         // 4x2 warps: 32m x 64n each
    const int bm = blockIdx.y * HM_BM;
    const int bn = blockIdx.x * HM_BN;
    const int NT = K / HM_BK;

    // chunk mapping: 512 x 16B chunks per tile; 2 chunks/thread/tile
    const int c0 = tid, c1 = tid + 256;
    const int r0c = c0 >> 2, e0c = (c0 & 3) * 8;
    const int r1c = c1 >> 2, e1c = (c1 & 3) * 8;

    auto issue = [&](int it) {
        if (it >= NT) return;
        const uint32_t sb0 = sbase + (uint32_t)(it % 3) * HM_STAGE_B;
        const long long ko = (long long)it * HM_BK;
        uint32_t d0 = sb0 + (uint32_t)(r0c * HM_LDS + e0c) * 2;
        uint32_t d1 = sb0 + (uint32_t)(r1c * HM_LDS + e1c) * 2;
        const long long a0 = (long long)(bm + r0c) * lda + ko + e0c;
        const long long a1 = (long long)(bm + r1c) * lda + ko + e1c;
        cp_async16(d0,              Ah + a0);
        cp_async16(d1,              Ah + a1);
        cp_async16(d0 + HM_TILE_B,  Al + a0);
        cp_async16(d1 + HM_TILE_B,  Al + a1);
        cp_async16(d0 + 2*HM_TILE_B, Bh + (long long)(bn + r0c) * ldb + ko + e0c);
        cp_async16(d1 + 2*HM_TILE_B, Bh + (long long)(bn + r1c) * ldb + ko + e1c);
    };

    float acc[2][8][4];
#pragma unroll
    for (int m = 0; m < 2; m++)
#pragma unroll
        for (int n = 0; n < 8; n++)
#pragma unroll
            for (int j = 0; j < 4; j++) acc[m][n][j] = 0.f;

    issue(0); CP_COMMIT();
    issue(1); CP_COMMIT();
    issue(2); CP_COMMIT();

    const int lr  = lane & 15;
    const int lc8 = (lane >> 4) << 3;

    for (int kt = 0; kt < NT; ++kt) {
        CP_WAIT(2);
        __syncthreads();
        const uint32_t sb0 = sbase + (uint32_t)(kt % 3) * HM_STAGE_B;
#pragma unroll
        for (int ks = 0; ks < 2; ks++) {
            const int k0 = ks * 16;
            uint32_t fAh[2][4], fAl[2][4], fB[8][2];
#pragma unroll
            for (int t = 0; t < 2; t++) {
                uint32_t a = sb0 + (uint32_t)((wm*32 + t*16 + lr) * HM_LDS + k0 + lc8) * 2;
                LDMATRIX_X4(fAh[t][0], fAh[t][1], fAh[t][2], fAh[t][3], a);
            }
#pragma unroll
            for (int p = 0; p < 4; p++) {
                uint32_t a = sb0 + 2*HM_TILE_B
                           + (uint32_t)((wn*64 + p*16 + lr) * HM_LDS + k0 + lc8) * 2;
                uint32_t r0, r1, r2, r3;
                LDMATRIX_X4(r0, r1, r2, r3, a);
                fB[p*2][0]   = r0; fB[p*2][1]   = r2;
                fB[p*2+1][0] = r1; fB[p*2+1][1] = r3;
            }
            // hh
#pragma unroll
            for (int m = 0; m < 2; m++)
#pragma unroll
                for (int n = 0; n < 8; n++) MMA_F16(acc[m][n], fAh[m], fB[n]);
            // lo(A) x hi(B)
#pragma unroll
            for (int t = 0; t < 2; t++) {
                uint32_t a = sb0 + HM_TILE_B
                           + (uint32_t)((wm*32 + t*16 + lr) * HM_LDS + k0 + lc8) * 2;
                LDMATRIX_X4(fAl[t][0], fAl[t][1], fAl[t][2], fAl[t][3], a);
            }
#pragma unroll
            for (int m = 0; m < 2; m++)
#pragma unroll
                for (int n = 0; n < 8; n++) MMA_F16(acc[m][n], fAl[m], fB[n]);
        }
        __syncthreads();
        issue(kt + 3); CP_COMMIT();
    }

    // epilogue
    const int qr = lane >> 2, qc = (lane & 3) * 2;
#pragma unroll
    for (int mt = 0; mt < 2; mt++) {
#pragma unroll
        for (int nt = 0; nt < 8; nt++) {
            const int col = bn + wn*64 + nt*8 + qc;
#pragma unroll
            for (int h = 0; h < 2; h++) {
                const int row = bm + wm*32 + mt*16 + qr + h*8;
                const long long o = co + (long long)row * ldc + col;
                float2 v;
                v.x = alpha * acc[mt][nt][h*2 + 0];
                v.y = alpha * acc[mt][nt][h*2 + 1];
                if (BETA) {
                    float2 c0v = *(const float2*)(C + o);
                    v.x += beta * c0v.x; v.y += beta * c0v.y;
                }
                if (BIAS) { v.x += bp[col]; v.y += bp[col + 1]; }
                if (OUTM == 0 || OUTM == 1) *(float2*)(C + o) = v;
                if (OUTM == 1 || OUTM == 2) {
                    fp16 hx = __float2half_rn(v.x), hy = __float2half_rn(v.y);
                    fp16 lx = __float2half_rn(v.x - __half2float(hx));
                    fp16 ly = __float2half_rn(v.y - __half2float(hy));
                    *(__half2*)(Oh + o) = __halves2half2(hx, hy);
                    *(__half2*)(Ol + o) = __halves2half2(lx, ly);
                }
            }
        }
    }
}

// ---------------- split kernels ----------------------------------------------
template<bool TANH>
__global__ void split_k(const float* __restrict__ x, fp16* __restrict__ h,
                        fp16* __restrict__ l, long long n)
{
    long long i = ((long long)blockIdx.x * blockDim.x + threadIdx.x) * 4;
    if (i >= n) return;
    float4 v = *(const float4*)(x + i);
    if (TANH) { v.x = tanhf(v.x); v.y = tanhf(v.y); v.z = tanhf(v.z); v.w = tanhf(v.w); }
    fp16 h0 = __float2half_rn(v.x), h1 = __float2half_rn(v.y);
    fp16 h2 = __float2half_rn(v.z), h3 = __float2half_rn(v.w);
    fp16 l0 = __float2half_rn(v.x - __half2float(h0));
    fp16 l1 = __float2half_rn(v.y - __half2float(h1));
    fp16 l2 = __float2half_rn(v.z - __half2float(h2));
    fp16 l3 = __float2half_rn(v.w - __half2float(h3));
    __half2* hp = (__half2*)(h + i);
    __half2* lp = (__half2*)(l + i);
    hp[0] = __halves2half2(h0, h1); hp[1] = __halves2half2(h2, h3);
    lp[0] = __halves2half2(l0, l1); lp[1] = __halves2half2(l2, l3);
}

// tanh + pad + split: V [B,SV,E] -> Vp [B,VP,E], rows >= SV are zero
__global__ void padsplitV_k(const float* __restrict__ V, fp16* __restrict__ h,
                            fp16* __restrict__ l)
{
    long long i = ((long long)blockIdx.x * blockDim.x + threadIdx.x) * 4;
    int b = (int)(i / (VP_ * E_));
    int rem = (int)(i % (VP_ * E_));
    int r = rem / E_, e = rem % E_;
    float4 v = make_float4(0.f, 0.f, 0.f, 0.f);
    if (r < SV_) {
        v = *(const float4*)(V + ((long long)(b * SV_ + r)) * E_ + e);
        v.x = tanhf(v.x); v.y = tanhf(v.y); v.z = tanhf(v.z); v.w = tanhf(v.w);
    }
    fp16 h0 = __float2half_rn(v.x), h1 = __float2half_rn(v.y);
    fp16 h2 = __float2half_rn(v.z), h3 = __float2half_rn(v.w);
    fp16 l0 = __float2half_rn(v.x - __half2float(h0));
    fp16 l1 = __float2half_rn(v.y - __half2float(h1));
    fp16 l2 = __float2half_rn(v.z - __half2float(h2));
    fp16 l3 = __float2half_rn(v.w - __half2float(h3));
    __half2* hp = (__half2*)(h + i);
    __half2* lp = (__half2*)(l + i);
    hp[0] = __halves2half2(h0, h1); hp[1] = __halves2half2(h2, h3);
    lp[0] = __halves2half2(l0, l1); lp[1] = __halves2half2(l2, l3);
}

// transpose (hi only — outputs are B operands): in [R,C] -> out [C,Rpad]
__global__ void splitT_k(const float* __restrict__ x, fp16* __restrict__ h,
                         int R, int C, int Rpad, long long sIn, long long sOut)
{
    __shared__ float t[32][33];
    const float* xb = x + blockIdx.z * sIn;
    int r0 = blockIdx.y * 32, c0 = blockIdx.x * 32;
#pragma unroll
    for (int i = 0; i < 4; i++) {
        int r = r0 + threadIdx.y + i * 8;
        t[threadIdx.y + i * 8][threadIdx.x] =
            (r < R) ? xb[(long long)r * C + c0 + threadIdx.x] : 0.f;
    }
    __syncthreads();
#pragma unroll
    for (int i = 0; i < 4; i++) {
        int c = c0 + threadIdx.y + i * 8;
        float v = t[threadIdx.x][threadIdx.y + i * 8];
        long long o = blockIdx.z * sOut + (long long)c * Rpad + r0 + threadIdx.x;
        h[o] = __float2half_rn(v);
    }
}

// ---------------- softmax (+ fused split) / colsum ---------------------------
__global__ void softmax_split(float* __restrict__ x, fp16* __restrict__ h,
                              fp16* __restrict__ l, int cols)
{
    long long r = blockIdx.x;
    float* p = x + r * (long long)cols;
    __shared__ float red[256];
    int t = threadIdx.x;
    float mx = -INFINITY;
    for (int c = t; c < cols; c += 256) mx = fmaxf(mx, p[c]);
    red[t] = mx; __syncthreads();
    for (int s = 128; s > 0; s >>= 1) { if (t < s) red[t] = fmaxf(red[t], red[t + s]); __syncthreads(); }
    mx = red[0]; __syncthreads();
    float sum = 0.f;
    for (int c = t; c < cols; c += 256) { float e = expf(p[c] - mx); p[c] = e; sum += e; }
    red[t] = sum; __syncthreads();
    for (int s = 128; s > 0; s >>= 1) { if (t < s) red[t] += red[t + s]; __syncthreads(); }
    float inv = 1.f / red[0];
    long long base = r * (long long)cols;
    for (int c = t; c < cols; c += 256) {
        float val = p[c] * inv;
        p[c] = val;
        fp16 hh = __float2half_rn(val);
        h[base + c] = hh;
        l[base + c] = __float2half_rn(val - __half2float(hh));
    }
}

__global__ void colsum_kernel(const float* __restrict__ x, float* __restrict__ out,
                              int T, int E)
{
    int e = blockIdx.x * blockDim.x + threadIdx.x;
    int b = blockIdx.y;
    const float* p = x + (long long)b * T * E + e;
    float s = 0.f;
    for (int t = 0; t < T; t++) s += p[(long long)t * E];
    out[(long long)b * E + e] = s;
}

// ---------------- host launcher ----------------------------------------------
extern "C" void kernel_launch(void* const* d_in, const int* in_sizes, int n_in,
                              void* d_out, int out_size)
{
    const float* Q    = (const float*)d_in[0];
    const float* K    = (const float*)d_in[1];
    const float* V    = (const float*)d_in[2];
    const float* W_Q  = (const float*)d_in[3];
    const float* W_K  = (const float*)d_in[4];
    const float* W_v  = (const float*)d_in[5];
    const float* W_vq = (const float*)d_in[6];
    const float* W_vk = (const float*)d_in[7];

    float* out  = (float*)d_out;
    float* outQ = out;
    float* outK = out + (long long)B_ * S_ * E_;
    float* f    = out + 2ll * B_ * S_ * E_;

    float *q, *k, *q2, *k2, *cs, *cs2;
    cudaGetSymbolAddress((void**)&q,   g_q);
    cudaGetSymbolAddress((void**)&k,   g_k);
    cudaGetSymbolAddress((void**)&q2,  g_q2);
    cudaGetSymbolAddress((void**)&k2,  g_k2);
    cudaGetSymbolAddress((void**)&cs,  g_cs);
    cudaGetSymbolAddress((void**)&cs2, g_cs2);

    fp16 *Qsh,*Qsl,*Ksh,*Ksl,*WqTh,*WkTh,*WvTh,*WvqTh,*WvkTh,*Vph,*Vpl,*vh,*vl;
    fp16 *qh,*ql,*kh,*kl,*qTh,*kTh;
    fp16 *vqh,*vql,*vkh,*vkl,*fh,*fl,*q2Th,*k2Th;
    cudaGetSymbolAddress((void**)&Qsh,  g_Qs_h);  cudaGetSymbolAddress((void**)&Qsl,  g_Qs_l);
    cudaGetSymbolAddress((void**)&Ksh,  g_Ks_h);  cudaGetSymbolAddress((void**)&Ksl,  g_Ks_l);
    cudaGetSymbolAddress((void**)&WqTh, g_WqT_h);
    cudaGetSymbolAddress((void**)&WkTh, g_WkT_h);
    cudaGetSymbolAddress((void**)&WvTh, g_WvT_h);
    cudaGetSymbolAddress((void**)&WvqTh,g_WvqT_h);
    cudaGetSymbolAddress((void**)&WvkTh,g_WvkT_h);
    cudaGetSymbolAddress((void**)&Vph,  g_Vp_h);  cudaGetSymbolAddress((void**)&Vpl,  g_Vp_l);
    cudaGetSymbolAddress((void**)&vh,   g_vh);    cudaGetSymbolAddress((void**)&vl,   g_vl);
    cudaGetSymbolAddress((void**)&qh,   g_qh);    cudaGetSymbolAddress((void**)&ql,   g_ql);
    cudaGetSymbolAddress((void**)&kh,   g_kh);    cudaGetSymbolAddress((void**)&kl,   g_kl);
    cudaGetSymbolAddress((void**)&qTh,  g_qTh);
    cudaGetSymbolAddress((void**)&kTh,  g_kTh);
    cudaGetSymbolAddress((void**)&vqh,  g_vqh);   cudaGetSymbolAddress((void**)&vql,  g_vql);
    cudaGetSymbolAddress((void**)&vkh,  g_vkh);   cudaGetSymbolAddress((void**)&vkl,  g_vkl);
    cudaGetSymbolAddress((void**)&fh,   g_fh);    cudaGetSymbolAddress((void**)&fl,   g_fl);
    cudaGetSymbolAddress((void**)&q2Th, g_q2Th);
    cudaGetSymbolAddress((void**)&k2Th, g_k2Th);

    cudaFuncSetAttribute(hmma_nt<0,false,false>, cudaFuncAttributeMaxDynamicSharedMemorySize, HM_SMEM_BYTES);
    cudaFuncSetAttribute(hmma_nt<0,false,true >, cudaFuncAttributeMaxDynamicSharedMemorySize, HM_SMEM_BYTES);
    cudaFuncSetAttribute(hmma_nt<0,true, false>, cudaFuncAttributeMaxDynamicSharedMemorySize, HM_SMEM_BYTES);
    cudaFuncSetAttribute(hmma_nt<1,false,false>, cudaFuncAttributeMaxDynamicSharedMemorySize, HM_SMEM_BYTES);
    cudaFuncSetAttribute(hmma_nt<2,false,false>, cudaFuncAttributeMaxDynamicSharedMemorySize, HM_SMEM_BYTES);

    const float inv = 1.0f / 32.0f;  // 1/sqrt(1024)
    const long long sQE = (long long)S_ * E_;
    const long long sSS = (long long)S_ * S_;
    const long long sVE = (long long)VP_ * E_;
    const long long sSV = (long long)S_ * VP_;
    const long long nQE = (long long)B_ * S_ * E_;

    // ---- stage 0: input splits ---------------------------------------------
    split_k<true><<<(int)(nQE/4/256), 256>>>(Q, Qsh, Qsl, nQE);
    split_k<true><<<(int)(nQE/4/256), 256>>>(K, Ksh, Ksl, nQE);
    splitT_k<<<dim3(32,32,1), dim3(32,8)>>>(W_Q,  WqTh,  E_, E_, E_, 0, 0);
    splitT_k<<<dim3(32,32,1), dim3(32,8)>>>(W_K,  WkTh,  E_, E_, E_, 0, 0);
    splitT_k<<<dim3(32,32,1), dim3(32,8)>>>(W_v,  WvTh,  E_, E_, E_, 0, 0);
    splitT_k<<<dim3(32,2,1),  dim3(32,8)>>>(W_vq, WvqTh, SV_, E_, 64, 0, 0);
    splitT_k<<<dim3(32,2,1),  dim3(32,8)>>>(W_vk, WvkTh, SV_, E_, 64, 0, 0);
    padsplitV_k<<<(int)(B_*VP_*E_/4/256), 256>>>(V, Vph, Vpl);

    // ---- stage 1: projections + v (fused fp16 split in epilogue) -----------
    hmma_nt<1,false,false><<<dim3(8,64,1), 256, HM_SMEM_BYTES>>>(
        Qsh,Qsl, WqTh, q, qh,ql, nullptr,
        B_*S_, E_, E_, E_, E_, E_, 0,0,0,0, 1.f, 0.f);
    hmma_nt<1,false,false><<<dim3(8,64,1), 256, HM_SMEM_BYTES>>>(
        Ksh,Ksl, WkTh, k, kh,kl, nullptr,
        B_*S_, E_, E_, E_, E_, E_, 0,0,0,0, 1.f, 0.f);
    hmma_nt<2,false,false><<<dim3(8,8,1), 256, HM_SMEM_BYTES>>>(
        Vph,Vpl, WvTh, nullptr, vh,vl, nullptr,
        B_*VP_, E_, E_, E_, E_, E_, 0,0,0,0, 1.f, 0.f);

    // ---- stage 2: q/k transposed (hi only), colsum(k) ----------------------
    splitT_k<<<dim3(32,64,B_), dim3(32,8)>>>(q, qTh, S_, E_, S_, sQE, sQE);
    splitT_k<<<dim3(32,64,B_), dim3(32,8)>>>(k, kTh, S_, E_, S_, sQE, sQE);
    colsum_kernel<<<dim3(E_/256,B_), 256>>>(k, cs, S_, E_);

    // ---- stage 3: f = softmax(q@k^T/32) (+ fused split) --------------------
    hmma_nt<0,false,false><<<dim3(16,16,B_), 256, HM_SMEM_BYTES>>>(
        qh,ql, kh, f, nullptr,nullptr, nullptr,
        S_, S_, E_, E_, E_, S_, sQE, sQE, sSS, 0, inv, 0.f);
    softmax_split<<<B_*S_, 256>>>(f, fh, fl, S_);

    // ---- vq/vk + q2/k2 base ------------------------------------------------
    hmma_nt<2,false,false><<<dim3(2,16,B_), 256, HM_SMEM_BYTES>>>(
        qh,ql, vh, nullptr, vqh,vql, nullptr,
        S_, VP_, E_, E_, E_, VP_, sQE, sVE, sSV, 0, inv, 0.f);
    hmma_nt<2,false,false><<<dim3(2,16,B_), 256, HM_SMEM_BYTES>>>(
        kh,kl, vh, nullptr, vkh,vkl, nullptr,
        S_, VP_, E_, E_, E_, VP_, sQE, sVE, sSV, 0, inv, 0.f);
    hmma_nt<0,false,false><<<dim3(8,16,B_), 256, HM_SMEM_BYTES>>>(
        vqh,vql, WvqTh, q2, nullptr,nullptr, nullptr,
        S_, E_, 64, VP_, 64, E_, sSV, 0, sQE, 0, 1.f, 0.f);
    hmma_nt<0,false,true><<<dim3(8,16,B_), 256, HM_SMEM_BYTES>>>(
        vkh,vkl, WvkTh, k2, nullptr,nullptr, cs,
        S_, E_, 64, VP_, 64, E_, sSV, 0, sQE, E_, 1.f, 0.f);

    // ---- stage 4: q2 += f@q ; k2 -= f@k ------------------------------------
    hmma_nt<0,true,false><<<dim3(8,16,B_), 256, HM_SMEM_BYTES>>>(
        fh,fl, qTh, q2, nullptr,nullptr, nullptr,
        S_, E_, S_, S_, S_, E_, sSS, sQE, sQE, 0, 1.f, 1.f);
    hmma_nt<0,true,false><<<dim3(8,16,B_), 256, HM_SMEM_BYTES>>>(
        fh,fl, kTh, k2, nullptr,nullptr, nullptr,
        S_, E_, S_, S_, S_, E_, sSS, sQE, sQE, 0, -1.f, 1.f);

    // ---- stage 5: outputs ---------------------------------------------------
    splitT_k<<<dim3(32,64,B_), dim3(32,8)>>>(q2, q2Th, S_, E_, S_, sQE, sQE);
    splitT_k<<<dim3(32,64,B_), dim3(32,8)>>>(k2, k2Th, S_, E_, S_, sQE, sQE);
    colsum_kernel<<<dim3(E_/256,B_), 256>>>(k2, cs2, S_, E_);

    hmma_nt<0,false,false><<<dim3(8,16,B_), 256, HM_SMEM_BYTES>>>(
        fh,fl, q2Th, outQ, nullptr,nullptr, nullptr,
        S_, E_, S_, S_, S_, E_, sSS, sQE, sQE, 0, 1.f, 0.f);
    hmma_nt<0,false,true><<<dim3(8,16,B_), 256, HM_SMEM_BYTES>>>(
        fh,fl, k2Th, outK, nullptr,nullptr, cs2,
        S_, E_, S_, S_, S_, E_, sSS, sQE, sQE, E_, -1.f, 0.f);

    (void)in_sizes; (void)n_in; (void)out_size;
}

// round 8
// speedup vs baseline: 2.7351x; 1.5634x over previous
#include <cuda_runtime.h>
#include <cuda_fp16.h>
#include <math.h>
#include <stdint.h>

#define B_  4
#define S_  2048
#define SV_ 50
#define E_  1024
#define VP_ 256   // padded v rows per batch

typedef __half fp16;

// ---------------- scratch (device globals) ----------------------------------
__device__ float g_q [B_*S_*E_];
__device__ float g_k [B_*S_*E_];
__device__ float g_q2[B_*S_*E_];
__device__ float g_k2[B_*S_*E_];
__device__ float g_cs [B_*E_];
__device__ float g_cs2[B_*E_];

__device__ fp16 g_Qs_h[B_*S_*E_];
__device__ fp16 g_Ks_h[B_*S_*E_];
__device__ fp16 g_WqT_h[E_*E_];
__device__ fp16 g_WkT_h[E_*E_];
__device__ fp16 g_WvT_h[E_*E_];
__device__ fp16 g_WvqT_h[E_*64];
__device__ fp16 g_WvkT_h[E_*64];
__device__ fp16 g_Vp_h[B_*VP_*E_];
__device__ fp16 g_vh[B_*VP_*E_];
__device__ fp16 g_qh[B_*S_*E_];
__device__ fp16 g_kh[B_*S_*E_];
__device__ fp16 g_qTh[B_*S_*E_];
__device__ fp16 g_kTh[B_*S_*E_];
__device__ fp16 g_vqh[B_*S_*VP_];
__device__ fp16 g_vkh[B_*S_*VP_];
__device__ fp16 g_fh[(size_t)B_*S_*S_];
__device__ fp16 g_q2Th[B_*S_*E_];
__device__ fp16 g_k2Th[B_*S_*E_];

// ---------------- PTX helpers ------------------------------------------------
__device__ __forceinline__ uint32_t smem_u32(const void* p) {
    uint32_t a;
    asm("{ .reg .u64 t; cvta.to.shared.u64 t, %1; cvt.u32.u64 %0, t; }"
        : "=r"(a) : "l"(p));
    return a;
}
__device__ __forceinline__ void cp_async16(uint32_t dst, const void* src) {
    asm volatile("cp.async.cg.shared.global [%0], [%1], 16;"
                 :: "r"(dst), "l"(src) : "memory");
}
#define CP_COMMIT() asm volatile("cp.async.commit_group;" ::: "memory")
#define CP_WAIT(n)  asm volatile("cp.async.wait_group %0;" :: "n"(n) : "memory")

#define LDMATRIX_X4(r0, r1, r2, r3, addr) \
    asm volatile("ldmatrix.sync.aligned.m8n8.x4.shared.b16 {%0,%1,%2,%3}, [%4];" \
        : "=r"(r0), "=r"(r1), "=r"(r2), "=r"(r3) : "r"(addr))

#define MMA_F16(d, a, b) \
    asm volatile("mma.sync.aligned.m16n8k16.row.col.f32.f16.f16.f32 " \
        "{%0,%1,%2,%3},{%4,%5,%6,%7},{%8,%9},{%0,%1,%2,%3};" \
        : "+f"((d)[0]), "+f"((d)[1]), "+f"((d)[2]), "+f"((d)[3]) \
        : "r"((a)[0]), "r"((a)[1]), "r"((a)[2]), "r"((a)[3]), \
          "r"((b)[0]), "r"((b)[1]))

// ---------------- fp16 HMMA NT GEMM (single pass) ----------------------------
// C[z] = alpha * Ah[M,K] @ Bh[N,K]^T (+beta*C) (+bias[n])
// OUTM: 0 = fp32 C; 1 = fp32 C + fp16 Oh; 2 = fp16 Oh only.
// Requires M%128==0, N%128==0, K%32==0 (all call sites satisfy).
constexpr int HM_BM = 128, HM_BN = 128, HM_BK = 32;
constexpr int HM_LDS = HM_BK + 8;              // padded row (elements)
constexpr int HM_TILE = HM_BM * HM_LDS;        // 5120 elems per tile
constexpr int HM_TILE_B = HM_TILE * 2;         // 10240 bytes
constexpr int HM_STAGE_B = 2 * HM_TILE_B;      // A | B = 20480 bytes
constexpr int HM_SMEM_BYTES = 4 * HM_STAGE_B;  // 4-stage ring = 81920

template<int OUTM, bool BETA, bool BIAS>
__global__ void __launch_bounds__(256, 2)
hmma_nt(const fp16* __restrict__ Ah, const fp16* __restrict__ Bh,
        float* __restrict__ C, fp16* __restrict__ Oh,
        const float* __restrict__ bias,
        int M, int N, int K, int lda, int ldb, int ldc,
        long long sA, long long sB, long long sC, long long sBias,
        float alpha, float beta)
{
    extern __shared__ fp16 sm[];
    const uint32_t sbase = smem_u32(sm);

    Ah += blockIdx.z * sA;
    Bh += blockIdx.z * sB;
    const long long co = blockIdx.z * sC;
    const float* bp = BIAS ? (bias + blockIdx.z * sBias) : nullptr;

    const int tid = threadIdx.x;
    const int warp = tid >> 5, lane = tid & 31;
    const int wm = warp & 3, wn = warp >> 2;         // 4x2 warps: 32m x 64n each
    const int bm = blockIdx.y * HM_BM;
    const int bn = blockIdx.x * HM_BN;
    const int NT = K / HM_BK;

    // chunk mapping: 512 x 16B chunks per tile; 2 chunks/thread/tile
    const int c0 = tid, c1 = tid + 256;
    const int r0c = c0 >> 2, e0c = (c0 & 3) * 8;
    const int r1c = c1 >> 2, e1c = (c1 & 3) * 8;

    auto issue = [&](int it) {
        if (it >= NT) return;
        const uint32_t sb0 = sbase + (uint32_t)(it & 3) * HM_STAGE_B;
        const long long ko = (long long)it * HM_BK;
        uint32_t d0 = sb0 + (uint32_t)(r0c * HM_LDS + e0c) * 2;
        uint32_t d1 = sb0 + (uint32_t)(r1c * HM_LDS + e1c) * 2;
        cp_async16(d0,              Ah + (long long)(bm + r0c) * lda + ko + e0c);
        cp_async16(d1,              Ah + (long long)(bm + r1c) * lda + ko + e1c);
        cp_async16(d0 + HM_TILE_B,  Bh + (long long)(bn + r0c) * ldb + ko + e0c);
        cp_async16(d1 + HM_TILE_B,  Bh + (long long)(bn + r1c) * ldb + ko + e1c);
    };

    float acc[2][8][4];
#pragma unroll
    for (int m = 0; m < 2; m++)
#pragma unroll
        for (int n = 0; n < 8; n++)
#pragma unroll
            for (int j = 0; j < 4; j++) acc[m][n][j] = 0.f;

    issue(0); CP_COMMIT();
    issue(1); CP_COMMIT();
    issue(2); CP_COMMIT();

    const int lr  = lane & 15;
    const int lc8 = (lane >> 4) << 3;

    for (int kt = 0; kt < NT; ++kt) {
        CP_WAIT(2);
        __syncthreads();
        const uint32_t sb0 = sbase + (uint32_t)(kt & 3) * HM_STAGE_B;
#pragma unroll
        for (int ks = 0; ks < 2; ks++) {
            const int k0 = ks * 16;
            uint32_t fA[2][4], fB[8][2];
#pragma unroll
            for (int t = 0; t < 2; t++) {
                uint32_t a = sb0 + (uint32_t)((wm*32 + t*16 + lr) * HM_LDS + k0 + lc8) * 2;
                LDMATRIX_X4(fA[t][0], fA[t][1], fA[t][2], fA[t][3], a);
            }
#pragma unroll
            for (int p = 0; p < 4; p++) {
                uint32_t a = sb0 + HM_TILE_B
                           + (uint32_t)((wn*64 + p*16 + lr) * HM_LDS + k0 + lc8) * 2;
                uint32_t r0, r1, r2, r3;
                LDMATRIX_X4(r0, r1, r2, r3, a);
                fB[p*2][0]   = r0; fB[p*2][1]   = r2;
                fB[p*2+1][0] = r1; fB[p*2+1][1] = r3;
            }
#pragma unroll
            for (int m = 0; m < 2; m++)
#pragma unroll
                for (int n = 0; n < 8; n++) MMA_F16(acc[m][n], fA[m], fB[n]);
        }
        __syncthreads();
        issue(kt + 3); CP_COMMIT();
    }

    // epilogue
    const int qr = lane >> 2, qc = (lane & 3) * 2;
#pragma unroll
    for (int mt = 0; mt < 2; mt++) {
#pragma unroll
        for (int nt = 0; nt < 8; nt++) {
            const int col = bn + wn*64 + nt*8 + qc;
#pragma unroll
            for (int h = 0; h < 2; h++) {
                const int row = bm + wm*32 + mt*16 + qr + h*8;
                const long long o = co + (long long)row * ldc + col;
                float2 v;
                v.x = alpha * acc[mt][nt][h*2 + 0];
                v.y = alpha * acc[mt][nt][h*2 + 1];
                if (BETA) {
                    float2 c0v = *(const float2*)(C + o);
                    v.x += beta * c0v.x; v.y += beta * c0v.y;
                }
                if (BIAS) { v.x += bp[col]; v.y += bp[col + 1]; }
                if (OUTM == 0 || OUTM == 1) *(float2*)(C + o) = v;
                if (OUTM == 1 || OUTM == 2) {
                    *(__half2*)(Oh + o) =
                        __halves2half2(__float2half_rn(v.x), __float2half_rn(v.y));
                }
            }
        }
    }
}

// ---------------- convert kernels --------------------------------------------
template<bool TANH>
__global__ void cvt_k(const float* __restrict__ x, fp16* __restrict__ h, long long n)
{
    long long i = ((long long)blockIdx.x * blockDim.x + threadIdx.x) * 4;
    if (i >= n) return;
    float4 v = *(const float4*)(x + i);
    if (TANH) { v.x = tanhf(v.x); v.y = tanhf(v.y); v.z = tanhf(v.z); v.w = tanhf(v.w); }
    __half2* hp = (__half2*)(h + i);
    hp[0] = __halves2half2(__float2half_rn(v.x), __float2half_rn(v.y));
    hp[1] = __halves2half2(__float2half_rn(v.z), __float2half_rn(v.w));
}

// tanh + pad: V [B,SV,E] -> Vp [B,VP,E] fp16, rows >= SV are zero
__global__ void padcvtV_k(const float* __restrict__ V, fp16* __restrict__ h)
{
    long long i = ((long long)blockIdx.x * blockDim.x + threadIdx.x) * 4;
    int b = (int)(i / (VP_ * E_));
    int rem = (int)(i % (VP_ * E_));
    int r = rem / E_, e = rem % E_;
    float4 v = make_float4(0.f, 0.f, 0.f, 0.f);
    if (r < SV_) {
        v = *(const float4*)(V + ((long long)(b * SV_ + r)) * E_ + e);
        v.x = tanhf(v.x); v.y = tanhf(v.y); v.z = tanhf(v.z); v.w = tanhf(v.w);
    }
    __half2* hp = (__half2*)(h + i);
    hp[0] = __halves2half2(__float2half_rn(v.x), __float2half_rn(v.y));
    hp[1] = __halves2half2(__float2half_rn(v.z), __float2half_rn(v.w));
}

// transpose + cvt: in [R,C] -> out [C,Rpad] fp16; rows >= R read as 0
__global__ void cvtT_k(const float* __restrict__ x, fp16* __restrict__ h,
                       int R, int C, int Rpad, long long sIn, long long sOut)
{
    __shared__ float t[32][33];
    const float* xb = x + blockIdx.z * sIn;
    int r0 = blockIdx.y * 32, c0 = blockIdx.x * 32;
#pragma unroll
    for (int i = 0; i < 4; i++) {
        int r = r0 + threadIdx.y + i * 8;
        t[threadIdx.y + i * 8][threadIdx.x] =
            (r < R) ? xb[(long long)r * C + c0 + threadIdx.x] : 0.f;
    }
    __syncthreads();
#pragma unroll
    for (int i = 0; i < 4; i++) {
        int c = c0 + threadIdx.y + i * 8;
        float v = t[threadIdx.x][threadIdx.y + i * 8];
        long long o = blockIdx.z * sOut + (long long)c * Rpad + r0 + threadIdx.x;
        h[o] = __float2half_rn(v);
    }
}

// ---------------- softmax (+ fused cvt) / colsum -----------------------------
__global__ void softmax_cvt(float* __restrict__ x, fp16* __restrict__ h, int cols)
{
    long long r = blockIdx.x;
    float* p = x + r * (long long)cols;
    __shared__ float red[256];
    int t = threadIdx.x;
    float mx = -INFINITY;
    for (int c = t; c < cols; c += 256) mx = fmaxf(mx, p[c]);
    red[t] = mx; __syncthreads();
    for (int s = 128; s > 0; s >>= 1) { if (t < s) red[t] = fmaxf(red[t], red[t + s]); __syncthreads(); }
    mx = red[0]; __syncthreads();
    float sum = 0.f;
    for (int c = t; c < cols; c += 256) { float e = expf(p[c] - mx); p[c] = e; sum += e; }
    red[t] = sum; __syncthreads();
    for (int s = 128; s > 0; s >>= 1) { if (t < s) red[t] += red[t + s]; __syncthreads(); }
    float inv = 1.f / red[0];
    long long base = r * (long long)cols;
    for (int c = t; c < cols; c += 256) {
        float val = p[c] * inv;
        p[c] = val;
        h[base + c] = __float2half_rn(val);
    }
}

__global__ void colsum_kernel(const float* __restrict__ x, float* __restrict__ out,
                              int T, int E)
{
    int e = blockIdx.x * blockDim.x + threadIdx.x;
    int b = blockIdx.y;
    const float* p = x + (long long)b * T * E + e;
    float s = 0.f;
    for (int t = 0; t < T; t++) s += p[(long long)t * E];
    out[(long long)b * E + e] = s;
}

// ---------------- host launcher ----------------------------------------------
extern "C" void kernel_launch(void* const* d_in, const int* in_sizes, int n_in,
                              void* d_out, int out_size)
{
    const float* Q    = (const float*)d_in[0];
    const float* K    = (const float*)d_in[1];
    const float* V    = (const float*)d_in[2];
    const float* W_Q  = (const float*)d_in[3];
    const float* W_K  = (const float*)d_in[4];
    const float* W_v  = (const float*)d_in[5];
    const float* W_vq = (const float*)d_in[6];
    const float* W_vk = (const float*)d_in[7];

    float* out  = (float*)d_out;
    float* outQ = out;
    float* outK = out + (long long)B_ * S_ * E_;
    float* f    = out + 2ll * B_ * S_ * E_;

    float *q, *k, *q2, *k2, *cs, *cs2;
    cudaGetSymbolAddress((void**)&q,   g_q);
    cudaGetSymbolAddress((void**)&k,   g_k);
    cudaGetSymbolAddress((void**)&q2,  g_q2);
    cudaGetSymbolAddress((void**)&k2,  g_k2);
    cudaGetSymbolAddress((void**)&cs,  g_cs);
    cudaGetSymbolAddress((void**)&cs2, g_cs2);

    fp16 *Qsh,*Ksh,*WqTh,*WkTh,*WvTh,*WvqTh,*WvkTh,*Vph,*vh;
    fp16 *qh,*kh,*qTh,*kTh,*vqh,*vkh,*fh,*q2Th,*k2Th;
    cudaGetSymbolAddress((void**)&Qsh,  g_Qs_h);
    cudaGetSymbolAddress((void**)&Ksh,  g_Ks_h);
    cudaGetSymbolAddress((void**)&WqTh, g_WqT_h);
    cudaGetSymbolAddress((void**)&WkTh, g_WkT_h);
    cudaGetSymbolAddress((void**)&WvTh, g_WvT_h);
    cudaGetSymbolAddress((void**)&WvqTh,g_WvqT_h);
    cudaGetSymbolAddress((void**)&WvkTh,g_WvkT_h);
    cudaGetSymbolAddress((void**)&Vph,  g_Vp_h);
    cudaGetSymbolAddress((void**)&vh,   g_vh);
    cudaGetSymbolAddress((void**)&qh,   g_qh);
    cudaGetSymbolAddress((void**)&kh,   g_kh);
    cudaGetSymbolAddress((void**)&qTh,  g_qTh);
    cudaGetSymbolAddress((void**)&kTh,  g_kTh);
    cudaGetSymbolAddress((void**)&vqh,  g_vqh);
    cudaGetSymbolAddress((void**)&vkh,  g_vkh);
    cudaGetSymbolAddress((void**)&fh,   g_fh);
    cudaGetSymbolAddress((void**)&q2Th, g_q2Th);
    cudaGetSymbolAddress((void**)&k2Th, g_k2Th);

    cudaFuncSetAttribute(hmma_nt<0,false,false>, cudaFuncAttributeMaxDynamicSharedMemorySize, HM_SMEM_BYTES);
    cudaFuncSetAttribute(hmma_nt<0,false,true >, cudaFuncAttributeMaxDynamicSharedMemorySize, HM_SMEM_BYTES);
    cudaFuncSetAttribute(hmma_nt<0,true, false>, cudaFuncAttributeMaxDynamicSharedMemorySize, HM_SMEM_BYTES);
    cudaFuncSetAttribute(hmma_nt<1,false,false>, cudaFuncAttributeMaxDynamicSharedMemorySize, HM_SMEM_BYTES);
    cudaFuncSetAttribute(hmma_nt<2,false,false>, cudaFuncAttributeMaxDynamicSharedMemorySize, HM_SMEM_BYTES);

    const float inv = 1.0f / 32.0f;  // 1/sqrt(1024)
    const long long sQE = (long long)S_ * E_;
    const long long sSS = (long long)S_ * S_;
    const long long sVE = (long long)VP_ * E_;
    const long long sSV = (long long)S_ * VP_;
    const long long nQE = (long long)B_ * S_ * E_;

    // ---- stage 0: input conversions ----------------------------------------
    cvt_k<true><<<(int)(nQE/4/256), 256>>>(Q, Qsh, nQE);
    cvt_k<true><<<(int)(nQE/4/256), 256>>>(K, Ksh, nQE);
    cvtT_k<<<dim3(32,32,1), dim3(32,8)>>>(W_Q,  WqTh,  E_, E_, E_, 0, 0);
    cvtT_k<<<dim3(32,32,1), dim3(32,8)>>>(W_K,  WkTh,  E_, E_, E_, 0, 0);
    cvtT_k<<<dim3(32,32,1), dim3(32,8)>>>(W_v,  WvTh,  E_, E_, E_, 0, 0);
    cvtT_k<<<dim3(32,2,1),  dim3(32,8)>>>(W_vq, WvqTh, SV_, E_, 64, 0, 0);
    cvtT_k<<<dim3(32,2,1),  dim3(32,8)>>>(W_vk, WvkTh, SV_, E_, 64, 0, 0);
    padcvtV_k<<<(int)(B_*VP_*E_/4/256), 256>>>(V, Vph);

    // ---- stage 1: projections + v (fused fp16 cvt in epilogue) -------------
    hmma_nt<1,false,false><<<dim3(8,64,1), 256, HM_SMEM_BYTES>>>(
        Qsh, WqTh, q, qh, nullptr,
        B_*S_, E_, E_, E_, E_, E_, 0,0,0,0, 1.f, 0.f);
    hmma_nt<1,false,false><<<dim3(8,64,1), 256, HM_SMEM_BYTES>>>(
        Ksh, WkTh, k, kh, nullptr,
        B_*S_, E_, E_, E_, E_, E_, 0,0,0,0, 1.f, 0.f);
    hmma_nt<2,false,false><<<dim3(8,8,1), 256, HM_SMEM_BYTES>>>(
        Vph, WvTh, nullptr, vh, nullptr,
        B_*VP_, E_, E_, E_, E_, E_, 0,0,0,0, 1.f, 0.f);

    // ---- stage 2: q/k transposed fp16, colsum(k) ---------------------------
    cvtT_k<<<dim3(32,64,B_), dim3(32,8)>>>(q, qTh, S_, E_, S_, sQE, sQE);
    cvtT_k<<<dim3(32,64,B_), dim3(32,8)>>>(k, kTh, S_, E_, S_, sQE, sQE);
    colsum_kernel<<<dim3(E_/256,B_), 256>>>(k, cs, S_, E_);

    // ---- stage 3: f = softmax(q@k^T/32) (+ fused cvt) ----------------------
    hmma_nt<0,false,false><<<dim3(16,16,B_), 256, HM_SMEM_BYTES>>>(
        qh, kh, f, nullptr, nullptr,
        S_, S_, E_, E_, E_, S_, sQE, sQE, sSS, 0, inv, 0.f);
    softmax_cvt<<<B_*S_, 256>>>(f, fh, S_);

    // ---- vq/vk + q2/k2 base ------------------------------------------------
    hmma_nt<2,false,false><<<dim3(2,16,B_), 256, HM_SMEM_BYTES>>>(
        qh, vh, nullptr, vqh, nullptr,
        S_, VP_, E_, E_, E_, VP_, sQE, sVE, sSV, 0, inv, 0.f);
    hmma_nt<2,false,false><<<dim3(2,16,B_), 256, HM_SMEM_BYTES>>>(
        kh, vh, nullptr, vkh, nullptr,
        S_, VP_, E_, E_, E_, VP_, sQE, sVE, sSV, 0, inv, 0.f);
    hmma_nt<0,false,false><<<dim3(8,16,B_), 256, HM_SMEM_BYTES>>>(
        vqh, WvqTh, q2, nullptr, nullptr,
        S_, E_, 64, VP_, 64, E_, sSV, 0, sQE, 0, 1.f, 0.f);
    hmma_nt<0,false,true><<<dim3(8,16,B_), 256, HM_SMEM_BYTES>>>(
        vkh, WvkTh, k2, nullptr, cs,
        S_, E_, 64, VP_, 64, E_, sSV, 0, sQE, E_, 1.f, 0.f);

    // ---- stage 4: q2 += f@q ; k2 -= f@k ------------------------------------
    hmma_nt<0,true,false><<<dim3(8,16,B_), 256, HM_SMEM_BYTES>>>(
        fh, qTh, q2, nullptr, nullptr,
        S_, E_, S_, S_, S_, E_, sSS, sQE, sQE, 0, 1.f, 1.f);
    hmma_nt<0,true,false><<<dim3(8,16,B_), 256, HM_SMEM_BYTES>>>(
        fh, kTh, k2, nullptr, nullptr,
        S_, E_, S_, S_, S_, E_, sSS, sQE, sQE, 0, -1.f, 1.f);

    // ---- stage 5: outputs ---------------------------------------------------
    cvtT_k<<<dim3(32,64,B_), dim3(32,8)>>>(q2, q2Th, S_, E_, S_, sQE, sQE);
    cvtT_k<<<dim3(32,64,B_), dim3(32,8)>>>(k2, k2Th, S_, E_, S_, sQE, sQE);
    colsum_kernel<<<dim3(E_/256,B_), 256>>>(k2, cs2, S_, E_);

    hmma_nt<0,false,false><<<dim3(8,16,B_), 256, HM_SMEM_BYTES>>>(
        fh, q2Th, outQ, nullptr, nullptr,
        S_, E_, S_, S_, S_, E_, sSS, sQE, sQE, 0, 1.f, 0.f);
    hmma_nt<0,false,true><<<dim3(8,16,B_), 256, HM_SMEM_BYTES>>>(
        fh, k2Th, outK, nullptr, cs2,
        S_, E_, S_, S_, S_, E_, sSS, sQE, sQE, E_, -1.f, 0.f);

    (void)in_sizes; (void)n_in; (void)out_size;
}

// round 9
// speedup vs baseline: 3.0236x; 1.1055x over previous
#include <cuda_runtime.h>
#include <cuda_fp16.h>
#include <math.h>
#include <stdint.h>

#define B_  4
#define S_  2048
#define SV_ 50
#define E_  1024
#define VP_ 256   // padded v rows per batch

typedef __half fp16;

// ---------------- scratch (device globals) ----------------------------------
__device__ float g_k [B_*S_*E_];
__device__ float g_q2[B_*S_*E_];
__device__ float g_k2[B_*S_*E_];
__device__ float g_cs [B_*E_];
__device__ float g_cs2[B_*E_];

__device__ fp16 g_Qs[B_*S_*E_];
__device__ fp16 g_Ks[B_*S_*E_];
__device__ fp16 g_Wq16[E_*E_];
__device__ fp16 g_Wk16[E_*E_];
__device__ fp16 g_Wv16[E_*E_];
__device__ fp16 g_Wvq16[64*E_];
__device__ fp16 g_Wvk16[64*E_];
__device__ fp16 g_Vp[B_*VP_*E_];
__device__ fp16 g_vh[B_*VP_*E_];
__device__ fp16 g_qh[B_*S_*E_];
__device__ fp16 g_kh[B_*S_*E_];
__device__ fp16 g_vqh[B_*S_*VP_];
__device__ fp16 g_vkh[B_*S_*VP_];
__device__ fp16 g_fh[(size_t)B_*S_*S_];
__device__ fp16 g_q2h[B_*S_*E_];
__device__ fp16 g_k2h[B_*S_*E_];

// ---------------- PTX helpers ------------------------------------------------
__device__ __forceinline__ uint32_t smem_u32(const void* p) {
    uint32_t a;
    asm("{ .reg .u64 t; cvta.to.shared.u64 t, %1; cvt.u32.u64 %0, t; }"
        : "=r"(a) : "l"(p));
    return a;
}
__device__ __forceinline__ void cp_async16(uint32_t dst, const void* src) {
    asm volatile("cp.async.cg.shared.global [%0], [%1], 16;"
                 :: "r"(dst), "l"(src) : "memory");
}
#define CP_COMMIT() asm volatile("cp.async.commit_group;" ::: "memory")
#define CP_WAIT(n)  asm volatile("cp.async.wait_group %0;" :: "n"(n) : "memory")

#define LDMATRIX_X4(r0, r1, r2, r3, addr) \
    asm volatile("ldmatrix.sync.aligned.m8n8.x4.shared.b16 {%0,%1,%2,%3}, [%4];" \
        : "=r"(r0), "=r"(r1), "=r"(r2), "=r"(r3) : "r"(addr))

#define LDMATRIX_X4_T(r0, r1, r2, r3, addr) \
    asm volatile("ldmatrix.sync.aligned.m8n8.x4.trans.shared.b16 {%0,%1,%2,%3}, [%4];" \
        : "=r"(r0), "=r"(r1), "=r"(r2), "=r"(r3) : "r"(addr))

#define MMA_F16(d, a, b) \
    asm volatile("mma.sync.aligned.m16n8k16.row.col.f32.f16.f16.f32 " \
        "{%0,%1,%2,%3},{%4,%5,%6,%7},{%8,%9},{%0,%1,%2,%3};" \
        : "+f"((d)[0]), "+f"((d)[1]), "+f"((d)[2]), "+f"((d)[3]) \
        : "r"((a)[0]), "r"((a)[1]), "r"((a)[2]), "r"((a)[3]), \
          "r"((b)[0]), "r"((b)[1]))

// ---------------- fp16 HMMA GEMM (NT + NN modes) -----------------------------
// NT=true : C = alpha * A[M,K] @ B[N,K]^T   (B row-major [N,K])
// NT=false: C = alpha * A[M,K] @ B[K,N]     (B row-major [K,N], ldmatrix.trans)
// (+beta*C) (+bias[n]).  OUTM: 0 = fp32 C; 1 = fp32 C + fp16 Oh; 2 = fp16 only.
// Requires M%128==0, N%128==0, K%32==0.
constexpr int HM_BM = 128, HM_BN = 128, HM_BK = 32;
constexpr int HM_LDSA = HM_BK + 8;              // A row stride (elems)
constexpr int HM_TILEA_B = HM_BM * HM_LDSA * 2; // 10240 bytes (also NT B tile)
constexpr int HM_LDSB = HM_BN + 8;              // NN B row stride (elems) = 136
constexpr int HM_STAGE_B = 20480;               // A | B region (fixed)
constexpr int HM_SMEM_BYTES = 4 * HM_STAGE_B;   // 4-stage ring = 81920

template<int OUTM, bool NT, bool BETA, bool BIAS>
__global__ void __launch_bounds__(256, 2)
hmma_g(const fp16* __restrict__ Ah, const fp16* __restrict__ Bh,
       float* __restrict__ C, fp16* __restrict__ Oh,
       const float* __restrict__ bias,
       int M, int N, int K, int lda, int ldb, int ldc,
       long long sA, long long sB, long long sC, long long sBias,
       float alpha, float beta)
{
    extern __shared__ fp16 sm[];
    const uint32_t sbase = smem_u32(sm);

    Ah += blockIdx.z * sA;
    Bh += blockIdx.z * sB;
    const long long co = blockIdx.z * sC;
    const float* bp = BIAS ? (bias + blockIdx.z * sBias) : nullptr;

    const int tid = threadIdx.x;
    const int warp = tid >> 5, lane = tid & 31;
    const int wm = warp & 3, wn = warp >> 2;         // 4x2 warps: 32m x 64n each
    const int bm = blockIdx.y * HM_BM;
    const int bn = blockIdx.x * HM_BN;
    const int NT_ = K / HM_BK;

    // A chunks (512 x 16B per tile; 2/thread). NT B uses same mapping.
    const int c0 = tid, c1 = tid + 256;
    const int r0c = c0 >> 2, e0c = (c0 & 3) * 8;
    const int r1c = c1 >> 2, e1c = (c1 & 3) * 8;
    // NN B chunks: row = c>>4 (0..31), col = (c&15)*8
    const int rB0 = c0 >> 4, eB0 = (c0 & 15) * 8;
    const int rB1 = c1 >> 4, eB1 = (c1 & 15) * 8;

    auto issue = [&](int it) {
        if (it >= NT_) return;
        const uint32_t sb0 = sbase + (uint32_t)(it & 3) * HM_STAGE_B;
        const long long ko = (long long)it * HM_BK;
        cp_async16(sb0 + (uint32_t)(r0c * HM_LDSA + e0c) * 2,
                   Ah + (long long)(bm + r0c) * lda + ko + e0c);
        cp_async16(sb0 + (uint32_t)(r1c * HM_LDSA + e1c) * 2,
                   Ah + (long long)(bm + r1c) * lda + ko + e1c);
        if (NT) {
            cp_async16(sb0 + HM_TILEA_B + (uint32_t)(r0c * HM_LDSA + e0c) * 2,
                       Bh + (long long)(bn + r0c) * ldb + ko + e0c);
            cp_async16(sb0 + HM_TILEA_B + (uint32_t)(r1c * HM_LDSA + e1c) * 2,
                       Bh + (long long)(bn + r1c) * ldb + ko + e1c);
        } else {
            cp_async16(sb0 + HM_TILEA_B + (uint32_t)(rB0 * HM_LDSB + eB0) * 2,
                       Bh + (ko + rB0) * (long long)ldb + bn + eB0);
            cp_async16(sb0 + HM_TILEA_B + (uint32_t)(rB1 * HM_LDSB + eB1) * 2,
                       Bh + (ko + rB1) * (long long)ldb + bn + eB1);
        }
    };

    float acc[2][8][4];
#pragma unroll
    for (int m = 0; m < 2; m++)
#pragma unroll
        for (int n = 0; n < 8; n++)
#pragma unroll
            for (int j = 0; j < 4; j++) acc[m][n][j] = 0.f;

    issue(0); CP_COMMIT();
    issue(1); CP_COMMIT();
    issue(2); CP_COMMIT();

    const int lr  = lane & 15;
    const int lc8 = (lane >> 4) << 3;

    for (int kt = 0; kt < NT_; ++kt) {
        CP_WAIT(2);
        __syncthreads();
        const uint32_t sb0 = sbase + (uint32_t)(kt & 3) * HM_STAGE_B;
#pragma unroll
        for (int ks = 0; ks < 2; ks++) {
            const int k0 = ks * 16;
            uint32_t fA[2][4], fB[8][2];
#pragma unroll
            for (int t = 0; t < 2; t++) {
                uint32_t a = sb0 + (uint32_t)((wm*32 + t*16 + lr) * HM_LDSA + k0 + lc8) * 2;
                LDMATRIX_X4(fA[t][0], fA[t][1], fA[t][2], fA[t][3], a);
            }
            if (NT) {
#pragma unroll
                for (int p = 0; p < 4; p++) {
                    uint32_t a = sb0 + HM_TILEA_B
                               + (uint32_t)((wn*64 + p*16 + lr) * HM_LDSA + k0 + lc8) * 2;
                    uint32_t r0, r1, r2, r3;
                    LDMATRIX_X4(r0, r1, r2, r3, a);
                    fB[p*2][0]   = r0; fB[p*2][1]   = r2;
                    fB[p*2+1][0] = r1; fB[p*2+1][1] = r3;
                }
            } else {
#pragma unroll
                for (int p = 0; p < 4; p++) {
                    uint32_t a = sb0 + HM_TILEA_B
                               + (uint32_t)((k0 + lr) * HM_LDSB + wn*64 + p*16 + lc8) * 2;
                    uint32_t r0, r1, r2, r3;
                    LDMATRIX_X4_T(r0, r1, r2, r3, a);
                    fB[p*2][0]   = r0; fB[p*2][1]   = r1;
                    fB[p*2+1][0] = r2; fB[p*2+1][1] = r3;
                }
            }
#pragma unroll
            for (int m = 0; m < 2; m++)
#pragma unroll
                for (int n = 0; n < 8; n++) MMA_F16(acc[m][n], fA[m], fB[n]);
        }
        __syncthreads();
        issue(kt + 3); CP_COMMIT();
    }

    // epilogue
    const int qr = lane >> 2, qc = (lane & 3) * 2;
#pragma unroll
    for (int mt = 0; mt < 2; mt++) {
#pragma unroll
        for (int nt = 0; nt < 8; nt++) {
            const int col = bn + wn*64 + nt*8 + qc;
#pragma unroll
            for (int h = 0; h < 2; h++) {
                const int row = bm + wm*32 + mt*16 + qr + h*8;
                const long long o = co + (long long)row * ldc + col;
                float2 v;
                v.x = alpha * acc[mt][nt][h*2 + 0];
                v.y = alpha * acc[mt][nt][h*2 + 1];
                if (BETA) {
                    float2 c0v = *(const float2*)(C + o);
                    v.x += beta * c0v.x; v.y += beta * c0v.y;
                }
                if (BIAS) { v.x += bp[col]; v.y += bp[col + 1]; }
                if (OUTM == 0 || OUTM == 1) *(float2*)(C + o) = v;
                if (OUTM == 1 || OUTM == 2) {
                    *(__half2*)(Oh + o) =
                        __halves2half2(__float2half_rn(v.x), __float2half_rn(v.y));
                }
            }
        }
    }
}

// ---------------- convert kernels --------------------------------------------
template<bool TANH>
__global__ void cvt_k(const float* __restrict__ x, fp16* __restrict__ h, long long n)
{
    long long i = ((long long)blockIdx.x * blockDim.x + threadIdx.x) * 4;
    if (i >= n) return;
    float4 v = *(const float4*)(x + i);
    if (TANH) { v.x = tanhf(v.x); v.y = tanhf(v.y); v.z = tanhf(v.z); v.w = tanhf(v.w); }
    __half2* hp = (__half2*)(h + i);
    hp[0] = __halves2half2(__float2half_rn(v.x), __float2half_rn(v.y));
    hp[1] = __halves2half2(__float2half_rn(v.z), __float2half_rn(v.w));
}

// tanh + pad: V [B,SV,E] -> Vp [B,VP,E] fp16, rows >= SV zero
__global__ void padcvtV_k(const float* __restrict__ V, fp16* __restrict__ h)
{
    long long i = ((long long)blockIdx.x * blockDim.x + threadIdx.x) * 4;
    int b = (int)(i / (VP_ * E_));
    int rem = (int)(i % (VP_ * E_));
    int r = rem / E_, e = rem % E_;
    float4 v = make_float4(0.f, 0.f, 0.f, 0.f);
    if (r < SV_) {
        v = *(const float4*)(V + ((long long)(b * SV_ + r)) * E_ + e);
        v.x = tanhf(v.x); v.y = tanhf(v.y); v.z = tanhf(v.z); v.w = tanhf(v.w);
    }
    __half2* hp = (__half2*)(h + i);
    hp[0] = __halves2half2(__float2half_rn(v.x), __float2half_rn(v.y));
    hp[1] = __halves2half2(__float2half_rn(v.z), __float2half_rn(v.w));
}

// pad W [SV,E] -> [64,E] fp16, rows >= SV zero
__global__ void padcvtW_k(const float* __restrict__ W, fp16* __restrict__ h)
{
    long long i = ((long long)blockIdx.x * blockDim.x + threadIdx.x) * 4;
    if (i >= 64 * E_) return;
    int r = (int)(i / E_), e = (int)(i % E_);
    float4 v = make_float4(0.f, 0.f, 0.f, 0.f);
    if (r < SV_) v = *(const float4*)(W + (long long)r * E_ + e);
    __half2* hp = (__half2*)(h + i);
    hp[0] = __halves2half2(__float2half_rn(v.x), __float2half_rn(v.y));
    hp[1] = __halves2half2(__float2half_rn(v.z), __float2half_rn(v.w));
}

// ---------------- softmax (+ fused cvt) / colsum -----------------------------
__global__ void softmax_cvt(float* __restrict__ x, fp16* __restrict__ h, int cols)
{
    long long r = blockIdx.x;
    float* p = x + r * (long long)cols;
    __shared__ float red[256];
    int t = threadIdx.x;
    float mx = -INFINITY;
    for (int c = t; c < cols; c += 256) mx = fmaxf(mx, p[c]);
    red[t] = mx; __syncthreads();
    for (int s = 128; s > 0; s >>= 1) { if (t < s) red[t] = fmaxf(red[t], red[t + s]); __syncthreads(); }
    mx = red[0]; __syncthreads();
    float sum = 0.f;
    for (int c = t; c < cols; c += 256) { float e = expf(p[c] - mx); p[c] = e; sum += e; }
    red[t] = sum; __syncthreads();
    for (int s = 128; s > 0; s >>= 1) { if (t < s) red[t] += red[t + s]; __syncthreads(); }
    float inv = 1.f / red[0];
    long long base = r * (long long)cols;
    for (int c = t; c < cols; c += 256) {
        float val = p[c] * inv;
        p[c] = val;
        h[base + c] = __float2half_rn(val);
    }
}

__global__ void colsum_kernel(const float* __restrict__ x, float* __restrict__ out,
                              int T, int E)
{
    int e = blockIdx.x * blockDim.x + threadIdx.x;
    int b = blockIdx.y;
    const float* p = x + (long long)b * T * E + e;
    float s = 0.f;
    for (int t = 0; t < T; t++) s += p[(long long)t * E];
    out[(long long)b * E + e] = s;
}

// ---------------- host launcher ----------------------------------------------
extern "C" void kernel_launch(void* const* d_in, const int* in_sizes, int n_in,
                              void* d_out, int out_size)
{
    const float* Q    = (const float*)d_in[0];
    const float* K    = (const float*)d_in[1];
    const float* V    = (const float*)d_in[2];
    const float* W_Q  = (const float*)d_in[3];
    const float* W_K  = (const float*)d_in[4];
    const float* W_v  = (const float*)d_in[5];
    const float* W_vq = (const float*)d_in[6];
    const float* W_vk = (const float*)d_in[7];

    float* out  = (float*)d_out;
    float* outQ = out;
    float* outK = out + (long long)B_ * S_ * E_;
    float* f    = out + 2ll * B_ * S_ * E_;

    float *k, *q2, *k2, *cs, *cs2;
    cudaGetSymbolAddress((void**)&k,   g_k);
    cudaGetSymbolAddress((void**)&q2,  g_q2);
    cudaGetSymbolAddress((void**)&k2,  g_k2);
    cudaGetSymbolAddress((void**)&cs,  g_cs);
    cudaGetSymbolAddress((void**)&cs2, g_cs2);

    fp16 *Qs,*Ks,*Wq16,*Wk16,*Wv16,*Wvq16,*Wvk16,*Vp,*vh;
    fp16 *qh,*kh,*vqh,*vkh,*fh,*q2h,*k2h;
    cudaGetSymbolAddress((void**)&Qs,    g_Qs);
    cudaGetSymbolAddress((void**)&Ks,    g_Ks);
    cudaGetSymbolAddress((void**)&Wq16,  g_Wq16);
    cudaGetSymbolAddress((void**)&Wk16,  g_Wk16);
    cudaGetSymbolAddress((void**)&Wv16,  g_Wv16);
    cudaGetSymbolAddress((void**)&Wvq16, g_Wvq16);
    cudaGetSymbolAddress((void**)&Wvk16, g_Wvk16);
    cudaGetSymbolAddress((void**)&Vp,    g_Vp);
    cudaGetSymbolAddress((void**)&vh,    g_vh);
    cudaGetSymbolAddress((void**)&qh,    g_qh);
    cudaGetSymbolAddress((void**)&kh,    g_kh);
    cudaGetSymbolAddress((void**)&vqh,   g_vqh);
    cudaGetSymbolAddress((void**)&vkh,   g_vkh);
    cudaGetSymbolAddress((void**)&fh,    g_fh);
    cudaGetSymbolAddress((void**)&q2h,   g_q2h);
    cudaGetSymbolAddress((void**)&k2h,   g_k2h);

    cudaFuncSetAttribute(hmma_g<2,false,false,false>, cudaFuncAttributeMaxDynamicSharedMemorySize, HM_SMEM_BYTES);
    cudaFuncSetAttribute(hmma_g<1,false,false,false>, cudaFuncAttributeMaxDynamicSharedMemorySize, HM_SMEM_BYTES);
    cudaFuncSetAttribute(hmma_g<0,true, false,false>, cudaFuncAttributeMaxDynamicSharedMemorySize, HM_SMEM_BYTES);
    cudaFuncSetAttribute(hmma_g<2,true, false,false>, cudaFuncAttributeMaxDynamicSharedMemorySize, HM_SMEM_BYTES);
    cudaFuncSetAttribute(hmma_g<0,false,false,false>, cudaFuncAttributeMaxDynamicSharedMemorySize, HM_SMEM_BYTES);
    cudaFuncSetAttribute(hmma_g<0,false,false,true >, cudaFuncAttributeMaxDynamicSharedMemorySize, HM_SMEM_BYTES);
    cudaFuncSetAttribute(hmma_g<1,false,true ,false>, cudaFuncAttributeMaxDynamicSharedMemorySize, HM_SMEM_BYTES);

    const float inv = 1.0f / 32.0f;  // 1/sqrt(1024)
    const long long sQE = (long long)S_ * E_;
    const long long sSS = (long long)S_ * S_;
    const long long sVE = (long long)VP_ * E_;
    const long long sSV = (long long)S_ * VP_;
    const long long nQE = (long long)B_ * S_ * E_;

    // ---- stage 0: input conversions (no transposes) ------------------------
    cvt_k<true ><<<(int)(nQE/4/256), 256>>>(Q, Qs, nQE);
    cvt_k<true ><<<(int)(nQE/4/256), 256>>>(K, Ks, nQE);
    cvt_k<false><<<(int)((long long)E_*E_/4/256), 256>>>(W_Q, Wq16, (long long)E_*E_);
    cvt_k<false><<<(int)((long long)E_*E_/4/256), 256>>>(W_K, Wk16, (long long)E_*E_);
    cvt_k<false><<<(int)((long long)E_*E_/4/256), 256>>>(W_v, Wv16, (long long)E_*E_);
    padcvtW_k<<<64, 256>>>(W_vq, Wvq16);
    padcvtW_k<<<64, 256>>>(W_vk, Wvk16);
    padcvtV_k<<<(int)(B_*VP_*E_/4/256), 256>>>(V, Vp);

    // ---- stage 1: projections + v (NN mode, weights in natural layout) -----
    hmma_g<2,false,false,false><<<dim3(8,64,1), 256, HM_SMEM_BYTES>>>(
        Qs, Wq16, nullptr, qh, nullptr,
        B_*S_, E_, E_, E_, E_, E_, 0,0,0,0, 1.f, 0.f);
    hmma_g<1,false,false,false><<<dim3(8,64,1), 256, HM_SMEM_BYTES>>>(
        Ks, Wk16, k, kh, nullptr,
        B_*S_, E_, E_, E_, E_, E_, 0,0,0,0, 1.f, 0.f);
    hmma_g<2,false,false,false><<<dim3(8,8,1), 256, HM_SMEM_BYTES>>>(
        Vp, Wv16, nullptr, vh, nullptr,
        B_*VP_, E_, E_, E_, E_, E_, 0,0,0,0, 1.f, 0.f);

    colsum_kernel<<<dim3(E_/256,B_), 256>>>(k, cs, S_, E_);

    // ---- stage 3: f = softmax(q@k^T/32) (NT) -------------------------------
    hmma_g<0,true,false,false><<<dim3(16,16,B_), 256, HM_SMEM_BYTES>>>(
        qh, kh, f, nullptr, nullptr,
        S_, S_, E_, E_, E_, S_, sQE, sQE, sSS, 0, inv, 0.f);
    softmax_cvt<<<B_*S_, 256>>>(f, fh, S_);

    // ---- vq/vk (NT) + q2/k2 base (NN) --------------------------------------
    hmma_g<2,true,false,false><<<dim3(2,16,B_), 256, HM_SMEM_BYTES>>>(
        qh, vh, nullptr, vqh, nullptr,
        S_, VP_, E_, E_, E_, VP_, sQE, sVE, sSV, 0, inv, 0.f);
    hmma_g<2,true,false,false><<<dim3(2,16,B_), 256, HM_SMEM_BYTES>>>(
        kh, vh, nullptr, vkh, nullptr,
        S_, VP_, E_, E_, E_, VP_, sQE, sVE, sSV, 0, inv, 0.f);
    hmma_g<0,false,false,false><<<dim3(8,16,B_), 256, HM_SMEM_BYTES>>>(
        vqh, Wvq16, q2, nullptr, nullptr,
        S_, E_, 64, VP_, E_, E_, sSV, 0, sQE, 0, 1.f, 0.f);
    hmma_g<0,false,false,true><<<dim3(8,16,B_), 256, HM_SMEM_BYTES>>>(
        vkh, Wvk16, k2, nullptr, cs,
        S_, E_, 64, VP_, E_, E_, sSV, 0, sQE, E_, 1.f, 0.f);

    // ---- stage 4: q2 += f@q ; k2 -= f@k (NN, fused fp16 out) ---------------
    hmma_g<1,false,true,false><<<dim3(8,16,B_), 256, HM_SMEM_BYTES>>>(
        fh, qh, q2, q2h, nullptr,
        S_, E_, S_, S_, E_, E_, sSS, sQE, sQE, 0, 1.f, 1.f);
    hmma_g<1,false,true,false><<<dim3(8,16,B_), 256, HM_SMEM_BYTES>>>(
        fh, kh, k2, k2h, nullptr,
        S_, E_, S_, S_, E_, E_, sSS, sQE, sQE, 0, -1.f, 1.f);

    colsum_kernel<<<dim3(E_/256,B_), 256>>>(k2, cs2, S_, E_);

    // ---- stage 5: outputs (NN) ---------------------------------------------
    hmma_g<0,false,false,false><<<dim3(8,16,B_), 256, HM_SMEM_BYTES>>>(
        fh, q2h, outQ, nullptr, nullptr,
        S_, E_, S_, S_, E_, E_, sSS, sQE, sQE, 0, 1.f, 0.f);
    hmma_g<0,false,false,true><<<dim3(8,16,B_), 256, HM_SMEM_BYTES>>>(
        fh, k2h, outK, nullptr, cs2,
        S_, E_, S_, S_, E_, E_, sSS, sQE, sQE, E_, -1.f, 0.f);

    (void)in_sizes; (void)n_in; (void)out_size;
}

// round 10
// speedup vs baseline: 3.0330x; 1.0031x over previous
#include <cuda_runtime.h>
#include <cuda_fp16.h>
#include <math.h>
#include <stdint.h>

#define B_  4
#define S_  2048
#define SV_ 50
#define E_  1024
#define VP_ 256   // padded v rows per batch

typedef __half fp16;

// ---------------- scratch (device globals) ----------------------------------
__device__ float g_k [B_*S_*E_];
__device__ float g_q2[B_*S_*E_];
__device__ float g_k2[B_*S_*E_];
__device__ float g_cs [B_*E_];
__device__ float g_cs2[B_*E_];

__device__ fp16 g_Qs[B_*S_*E_];
__device__ fp16 g_Ks[B_*S_*E_];
__device__ fp16 g_Wq16[E_*E_];
__device__ fp16 g_Wk16[E_*E_];
__device__ fp16 g_Wv16[E_*E_];
__device__ fp16 g_Wvq16[64*E_];
__device__ fp16 g_Wvk16[64*E_];
__device__ fp16 g_Vp[B_*VP_*E_];
__device__ fp16 g_vh[B_*VP_*E_];
__device__ fp16 g_qh[B_*S_*E_];
__device__ fp16 g_kh[B_*S_*E_];
__device__ fp16 g_vqh[B_*S_*VP_];
__device__ fp16 g_vkh[B_*S_*VP_];
__device__ fp16 g_fh[(size_t)B_*S_*S_];
__device__ fp16 g_q2h[B_*S_*E_];
__device__ fp16 g_k2h[B_*S_*E_];

// ---------------- PTX helpers ------------------------------------------------
__device__ __forceinline__ uint32_t smem_u32(const void* p) {
    uint32_t a;
    asm("{ .reg .u64 t; cvta.to.shared.u64 t, %1; cvt.u32.u64 %0, t; }"
        : "=r"(a) : "l"(p));
    return a;
}
__device__ __forceinline__ void cp_async16(uint32_t dst, const void* src) {
    asm volatile("cp.async.cg.shared.global [%0], [%1], 16;"
                 :: "r"(dst), "l"(src) : "memory");
}
#define CP_COMMIT() asm volatile("cp.async.commit_group;" ::: "memory")
#define CP_WAIT(n)  asm volatile("cp.async.wait_group %0;" :: "n"(n) : "memory")

#define LDMATRIX_X4(r0, r1, r2, r3, addr) \
    asm volatile("ldmatrix.sync.aligned.m8n8.x4.shared.b16 {%0,%1,%2,%3}, [%4];" \
        : "=r"(r0), "=r"(r1), "=r"(r2), "=r"(r3) : "r"(addr))

#define LDMATRIX_X4_T(r0, r1, r2, r3, addr) \
    asm volatile("ldmatrix.sync.aligned.m8n8.x4.trans.shared.b16 {%0,%1,%2,%3}, [%4];" \
        : "=r"(r0), "=r"(r1), "=r"(r2), "=r"(r3) : "r"(addr))

#define MMA_F16(d, a, b) \
    asm volatile("mma.sync.aligned.m16n8k16.row.col.f32.f16.f16.f32 " \
        "{%0,%1,%2,%3},{%4,%5,%6,%7},{%8,%9},{%0,%1,%2,%3};" \
        : "+f"((d)[0]), "+f"((d)[1]), "+f"((d)[2]), "+f"((d)[3]) \
        : "r"((a)[0]), "r"((a)[1]), "r"((a)[2]), "r"((a)[3]), \
          "r"((b)[0]), "r"((b)[1]))

// ---------------- fp16 HMMA GEMM (NT/NN, optional paired ops) ----------------
// NT=true : C = alpha * A[M,K] @ B[N,K]^T   (B row-major [N,K])
// NT=false: C = alpha * A[M,K] @ B[K,N]     (B row-major [K,N], ldmatrix.trans)
// PAIR: blockIdx.z = 2*batch + sel; parameter-set sel in {0,1}.
// Epilogue runtime: write fp32 if C!=null, fp16 if Oh!=null, add bias if !=null.
constexpr int HM_BM = 128, HM_BN = 128, HM_BK = 32;
constexpr int HM_LDSA = HM_BK + 8;
constexpr int HM_TILEA_B = HM_BM * HM_LDSA * 2; // 10240 bytes (also NT B tile)
constexpr int HM_LDSB = HM_BN + 8;              // NN B row stride (elems)
constexpr int HM_STAGE_B = 20480;
constexpr int HM_SMEM_BYTES = 4 * HM_STAGE_B;   // 81920

template<bool NT, bool BETA, bool PAIR>
__global__ void __launch_bounds__(256, 2)
hmma_g(const fp16* __restrict__ A0, const fp16* __restrict__ A1,
       const fp16* __restrict__ B0, const fp16* __restrict__ B1,
       float* __restrict__ C0, float* __restrict__ C1,
       fp16* __restrict__ O0, fp16* __restrict__ O1,
       const float* __restrict__ bias0, const float* __restrict__ bias1,
       int M, int N, int K, int lda, int ldb, int ldc,
       long long sA, long long sB, long long sC, long long sBias,
       float alpha0, float alpha1, float beta)
{
    extern __shared__ fp16 sm[];
    const uint32_t sbase = smem_u32(sm);

    int sel, zb;
    if (PAIR) { sel = blockIdx.z & 1; zb = blockIdx.z >> 1; }
    else      { sel = 0;              zb = blockIdx.z; }

    const fp16* Ah = (PAIR && sel ? A1 : A0) + (long long)zb * sA;
    const fp16* Bh = (PAIR && sel ? B1 : B0) + (long long)zb * sB;
    float* C  = (PAIR && sel) ? C1 : C0;
    fp16*  Oh = (PAIR && sel) ? O1 : O0;
    const float* bias = (PAIR && sel) ? bias1 : bias0;
    const float alpha = (PAIR && sel) ? alpha1 : alpha0;
    const long long co = (long long)zb * sC;
    const float* bp = bias ? (bias + (long long)zb * sBias) : nullptr;

    const int tid = threadIdx.x;
    const int warp = tid >> 5, lane = tid & 31;
    const int wm = warp & 3, wn = warp >> 2;         // 4x2 warps: 32m x 64n
    const int bm = blockIdx.y * HM_BM;
    const int bn = blockIdx.x * HM_BN;
    const int NT_ = K / HM_BK;

    const int c0 = tid, c1 = tid + 256;
    const int r0c = c0 >> 2, e0c = (c0 & 3) * 8;
    const int r1c = c1 >> 2, e1c = (c1 & 3) * 8;
    const int rB0 = c0 >> 4, eB0 = (c0 & 15) * 8;
    const int rB1 = c1 >> 4, eB1 = (c1 & 15) * 8;

    auto issue = [&](int it) {
        if (it >= NT_) return;
        const uint32_t sb0 = sbase + (uint32_t)(it & 3) * HM_STAGE_B;
        const long long ko = (long long)it * HM_BK;
        cp_async16(sb0 + (uint32_t)(r0c * HM_LDSA + e0c) * 2,
                   Ah + (long long)(bm + r0c) * lda + ko + e0c);
        cp_async16(sb0 + (uint32_t)(r1c * HM_LDSA + e1c) * 2,
                   Ah + (long long)(bm + r1c) * lda + ko + e1c);
        if (NT) {
            cp_async16(sb0 + HM_TILEA_B + (uint32_t)(r0c * HM_LDSA + e0c) * 2,
                       Bh + (long long)(bn + r0c) * ldb + ko + e0c);
            cp_async16(sb0 + HM_TILEA_B + (uint32_t)(r1c * HM_LDSA + e1c) * 2,
                       Bh + (long long)(bn + r1c) * ldb + ko + e1c);
        } else {
            cp_async16(sb0 + HM_TILEA_B + (uint32_t)(rB0 * HM_LDSB + eB0) * 2,
                       Bh + (ko + rB0) * (long long)ldb + bn + eB0);
            cp_async16(sb0 + HM_TILEA_B + (uint32_t)(rB1 * HM_LDSB + eB1) * 2,
                       Bh + (ko + rB1) * (long long)ldb + bn + eB1);
        }
    };

    float acc[2][8][4];
#pragma unroll
    for (int m = 0; m < 2; m++)
#pragma unroll
        for (int n = 0; n < 8; n++)
#pragma unroll
            for (int j = 0; j < 4; j++) acc[m][n][j] = 0.f;

    issue(0); CP_COMMIT();
    issue(1); CP_COMMIT();
    issue(2); CP_COMMIT();

    const int lr  = lane & 15;
    const int lc8 = (lane >> 4) << 3;

    for (int kt = 0; kt < NT_; ++kt) {
        CP_WAIT(2);
        __syncthreads();
        const uint32_t sb0 = sbase + (uint32_t)(kt & 3) * HM_STAGE_B;
#pragma unroll
        for (int ks = 0; ks < 2; ks++) {
            const int k0 = ks * 16;
            uint32_t fA[2][4], fB[8][2];
#pragma unroll
            for (int t = 0; t < 2; t++) {
                uint32_t a = sb0 + (uint32_t)((wm*32 + t*16 + lr) * HM_LDSA + k0 + lc8) * 2;
                LDMATRIX_X4(fA[t][0], fA[t][1], fA[t][2], fA[t][3], a);
            }
            if (NT) {
#pragma unroll
                for (int p = 0; p < 4; p++) {
                    uint32_t a = sb0 + HM_TILEA_B
                               + (uint32_t)((wn*64 + p*16 + lr) * HM_LDSA + k0 + lc8) * 2;
                    uint32_t r0, r1, r2, r3;
                    LDMATRIX_X4(r0, r1, r2, r3, a);
                    fB[p*2][0]   = r0; fB[p*2][1]   = r2;
                    fB[p*2+1][0] = r1; fB[p*2+1][1] = r3;
                }
            } else {
#pragma unroll
                for (int p = 0; p < 4; p++) {
                    uint32_t a = sb0 + HM_TILEA_B
                               + (uint32_t)((k0 + lr) * HM_LDSB + wn*64 + p*16 + lc8) * 2;
                    uint32_t r0, r1, r2, r3;
                    LDMATRIX_X4_T(r0, r1, r2, r3, a);
                    fB[p*2][0]   = r0; fB[p*2][1]   = r1;
                    fB[p*2+1][0] = r2; fB[p*2+1][1] = r3;
                }
            }
#pragma unroll
            for (int m = 0; m < 2; m++)
#pragma unroll
                for (int n = 0; n < 8; n++) MMA_F16(acc[m][n], fA[m], fB[n]);
        }
        __syncthreads();
        issue(kt + 3); CP_COMMIT();
    }

    // epilogue (runtime-selected outputs; branches uniform per block)
    const int qr = lane >> 2, qc = (lane & 3) * 2;
#pragma unroll
    for (int mt = 0; mt < 2; mt++) {
#pragma unroll
        for (int nt = 0; nt < 8; nt++) {
            const int col = bn + wn*64 + nt*8 + qc;
#pragma unroll
            for (int h = 0; h < 2; h++) {
                const int row = bm + wm*32 + mt*16 + qr + h*8;
                const long long o = co + (long long)row * ldc + col;
                float2 v;
                v.x = alpha * acc[mt][nt][h*2 + 0];
                v.y = alpha * acc[mt][nt][h*2 + 1];
                if (BETA) {
                    float2 c0v = *(const float2*)(C + o);
                    v.x += beta * c0v.x; v.y += beta * c0v.y;
                }
                if (bp) { v.x += bp[col]; v.y += bp[col + 1]; }
                if (C)  *(float2*)(C + o) = v;
                if (Oh) *(__half2*)(Oh + o) =
                        __halves2half2(__float2half_rn(v.x), __float2half_rn(v.y));
            }
        }
    }
}

// ---------------- convert kernels --------------------------------------------
// paired cvt: blockIdx.y selects (x0->h0) or (x1->h1)
template<bool TANH>
__global__ void cvt2_k(const float* __restrict__ x0, const float* __restrict__ x1,
                       fp16* __restrict__ h0, fp16* __restrict__ h1, long long n)
{
    const float* x = blockIdx.y ? x1 : x0;
    fp16* h = blockIdx.y ? h1 : h0;
    long long i = ((long long)blockIdx.x * blockDim.x + threadIdx.x) * 4;
    if (i >= n) return;
    float4 v = *(const float4*)(x + i);
    if (TANH) { v.x = tanhf(v.x); v.y = tanhf(v.y); v.z = tanhf(v.z); v.w = tanhf(v.w); }
    __half2* hp = (__half2*)(h + i);
    hp[0] = __halves2half2(__float2half_rn(v.x), __float2half_rn(v.y));
    hp[1] = __halves2half2(__float2half_rn(v.z), __float2half_rn(v.w));
}

__global__ void cvt3_k(const float* __restrict__ x0, const float* __restrict__ x1,
                       const float* __restrict__ x2,
                       fp16* __restrict__ h0, fp16* __restrict__ h1,
                       fp16* __restrict__ h2, long long n)
{
    const float* x = (blockIdx.y == 0) ? x0 : (blockIdx.y == 1) ? x1 : x2;
    fp16* h = (blockIdx.y == 0) ? h0 : (blockIdx.y == 1) ? h1 : h2;
    long long i = ((long long)blockIdx.x * blockDim.x + threadIdx.x) * 4;
    if (i >= n) return;
    float4 v = *(const float4*)(x + i);
    __half2* hp = (__half2*)(h + i);
    hp[0] = __halves2half2(__float2half_rn(v.x), __float2half_rn(v.y));
    hp[1] = __halves2half2(__float2half_rn(v.z), __float2half_rn(v.w));
}

// pad W [SV,E] -> [64,E] fp16 (two weights via blockIdx.y)
__global__ void padcvtW2_k(const float* __restrict__ W0, const float* __restrict__ W1,
                           fp16* __restrict__ h0, fp16* __restrict__ h1)
{
    const float* W = blockIdx.y ? W1 : W0;
    fp16* h = blockIdx.y ? h1 : h0;
    long long i = ((long long)blockIdx.x * blockDim.x + threadIdx.x) * 4;
    if (i >= 64 * E_) return;
    int r = (int)(i / E_), e = (int)(i % E_);
    float4 v = make_float4(0.f, 0.f, 0.f, 0.f);
    if (r < SV_) v = *(const float4*)(W + (long long)r * E_ + e);
    __half2* hp = (__half2*)(h + i);
    hp[0] = __halves2half2(__float2half_rn(v.x), __float2half_rn(v.y));
    hp[1] = __halves2half2(__float2half_rn(v.z), __float2half_rn(v.w));
}

// tanh + pad: V [B,SV,E] -> Vp [B,VP,E] fp16, rows >= SV zero
__global__ void padcvtV_k(const float* __restrict__ V, fp16* __restrict__ h)
{
    long long i = ((long long)blockIdx.x * blockDim.x + threadIdx.x) * 4;
    int b = (int)(i / (VP_ * E_));
    int rem = (int)(i % (VP_ * E_));
    int r = rem / E_, e = rem % E_;
    float4 v = make_float4(0.f, 0.f, 0.f, 0.f);
    if (r < SV_) {
        v = *(const float4*)(V + ((long long)(b * SV_ + r)) * E_ + e);
        v.x = tanhf(v.x); v.y = tanhf(v.y); v.z = tanhf(v.z); v.w = tanhf(v.w);
    }
    __half2* hp = (__half2*)(h + i);
    hp[0] = __halves2half2(__float2half_rn(v.x), __float2half_rn(v.y));
    hp[1] = __halves2half2(__float2half_rn(v.z), __float2half_rn(v.w));
}

// ---------------- softmax (+ fused cvt) / colsum -----------------------------
__global__ void softmax_cvt(float* __restrict__ x, fp16* __restrict__ h, int cols)
{
    long long r = blockIdx.x;
    float* p = x + r * (long long)cols;
    __shared__ float red[256];
    int t = threadIdx.x;
    float mx = -INFINITY;
    for (int c = t; c < cols; c += 256) mx = fmaxf(mx, p[c]);
    red[t] = mx; __syncthreads();
    for (int s = 128; s > 0; s >>= 1) { if (t < s) red[t] = fmaxf(red[t], red[t + s]); __syncthreads(); }
    mx = red[0]; __syncthreads();
    float sum = 0.f;
    for (int c = t; c < cols; c += 256) { float e = expf(p[c] - mx); p[c] = e; sum += e; }
    red[t] = sum; __syncthreads();
    for (int s = 128; s > 0; s >>= 1) { if (t < s) red[t] += red[t + s]; __syncthreads(); }
    float inv = 1.f / red[0];
    long long base = r * (long long)cols;
    for (int c = t; c < cols; c += 256) {
        float val = p[c] * inv;
        p[c] = val;
        h[base + c] = __float2half_rn(val);
    }
}

__global__ void colsum_kernel(const float* __restrict__ x, float* __restrict__ out,
                              int T, int E)
{
    int e = blockIdx.x * blockDim.x + threadIdx.x;
    int b = blockIdx.y;
    const float* p = x + (long long)b * T * E + e;
    float s = 0.f;
    for (int t = 0; t < T; t++) s += p[(long long)t * E];
    out[(long long)b * E + e] = s;
}

// ---------------- host launcher ----------------------------------------------
extern "C" void kernel_launch(void* const* d_in, const int* in_sizes, int n_in,
                              void* d_out, int out_size)
{
    const float* Q    = (const float*)d_in[0];
    const float* K    = (const float*)d_in[1];
    const float* V    = (const float*)d_in[2];
    const float* W_Q  = (const float*)d_in[3];
    const float* W_K  = (const float*)d_in[4];
    const float* W_v  = (const float*)d_in[5];
    const float* W_vq = (const float*)d_in[6];
    const float* W_vk = (const float*)d_in[7];

    float* out  = (float*)d_out;
    float* outQ = out;
    float* outK = out + (long long)B_ * S_ * E_;
    float* f    = out + 2ll * B_ * S_ * E_;

    float *k, *q2, *k2, *cs, *cs2;
    cudaGetSymbolAddress((void**)&k,   g_k);
    cudaGetSymbolAddress((void**)&q2,  g_q2);
    cudaGetSymbolAddress((void**)&k2,  g_k2);
    cudaGetSymbolAddress((void**)&cs,  g_cs);
    cudaGetSymbolAddress((void**)&cs2, g_cs2);

    fp16 *Qs,*Ks,*Wq16,*Wk16,*Wv16,*Wvq16,*Wvk16,*Vp,*vh;
    fp16 *qh,*kh,*vqh,*vkh,*fh,*q2h,*k2h;
    cudaGetSymbolAddress((void**)&Qs,    g_Qs);
    cudaGetSymbolAddress((void**)&Ks,    g_Ks);
    cudaGetSymbolAddress((void**)&Wq16,  g_Wq16);
    cudaGetSymbolAddress((void**)&Wk16,  g_Wk16);
    cudaGetSymbolAddress((void**)&Wv16,  g_Wv16);
    cudaGetSymbolAddress((void**)&Wvq16, g_Wvq16);
    cudaGetSymbolAddress((void**)&Wvk16, g_Wvk16);
    cudaGetSymbolAddress((void**)&Vp,    g_Vp);
    cudaGetSymbolAddress((void**)&vh,    g_vh);
    cudaGetSymbolAddress((void**)&qh,    g_qh);
    cudaGetSymbolAddress((void**)&kh,    g_kh);
    cudaGetSymbolAddress((void**)&vqh,   g_vqh);
    cudaGetSymbolAddress((void**)&vkh,   g_vkh);
    cudaGetSymbolAddress((void**)&fh,    g_fh);
    cudaGetSymbolAddress((void**)&q2h,   g_q2h);
    cudaGetSymbolAddress((void**)&k2h,   g_k2h);

    cudaFuncSetAttribute(hmma_g<false,false,false>, cudaFuncAttributeMaxDynamicSharedMemorySize, HM_SMEM_BYTES);
    cudaFuncSetAttribute(hmma_g<false,false,true >, cudaFuncAttributeMaxDynamicSharedMemorySize, HM_SMEM_BYTES);
    cudaFuncSetAttribute(hmma_g<true ,false,false>, cudaFuncAttributeMaxDynamicSharedMemorySize, HM_SMEM_BYTES);
    cudaFuncSetAttribute(hmma_g<true ,false,true >, cudaFuncAttributeMaxDynamicSharedMemorySize, HM_SMEM_BYTES);
    cudaFuncSetAttribute(hmma_g<false,true ,true >, cudaFuncAttributeMaxDynamicSharedMemorySize, HM_SMEM_BYTES);

    const float inv = 1.0f / 32.0f;  // 1/sqrt(1024)
    const long long sQE = (long long)S_ * E_;
    const long long sSS = (long long)S_ * S_;
    const long long sVE = (long long)VP_ * E_;
    const long long sSV = (long long)S_ * VP_;
    const long long nQE = (long long)B_ * S_ * E_;

    // ---- stage 0: input conversions ----------------------------------------
    cvt2_k<true><<<dim3((int)(nQE/4/256), 2), 256>>>(Q, K, Qs, Ks, nQE);
    cvt3_k<<<dim3((int)((long long)E_*E_/4/256), 3), 256>>>(
        W_Q, W_K, W_v, Wq16, Wk16, Wv16, (long long)E_*E_);
    padcvtW2_k<<<dim3(64, 2), 256>>>(W_vq, W_vk, Wvq16, Wvk16);
    padcvtV_k<<<(int)(B_*VP_*E_/4/256), 256>>>(V, Vp);

    // ---- stage 1: paired Q/K projections (NN) + v projection ---------------
    hmma_g<false,false,true><<<dim3(8,64,2), 256, HM_SMEM_BYTES>>>(
        Qs, Ks, Wq16, Wk16, nullptr, k, qh, kh, nullptr, nullptr,
        B_*S_, E_, E_, E_, E_, E_, 0,0,0,0, 1.f, 1.f, 0.f);
    hmma_g<false,false,false><<<dim3(8,8,1), 256, HM_SMEM_BYTES>>>(
        Vp, nullptr, Wv16, nullptr, nullptr, nullptr, vh, nullptr, nullptr, nullptr,
        B_*VP_, E_, E_, E_, E_, E_, 0,0,0,0, 1.f, 0.f, 0.f);

    colsum_kernel<<<dim3(E_/256,B_), 256>>>(k, cs, S_, E_);

    // ---- stage 3: f = softmax(q@k^T/32) (NT) -------------------------------
    hmma_g<true,false,false><<<dim3(16,16,B_), 256, HM_SMEM_BYTES>>>(
        qh, nullptr, kh, nullptr, f, nullptr, nullptr, nullptr, nullptr, nullptr,
        S_, S_, E_, E_, E_, S_, sQE, sQE, sSS, 0, inv, 0.f, 0.f);
    softmax_cvt<<<B_*S_, 256>>>(f, fh, S_);

    // ---- vq/vk paired (NT) + q2/k2 base paired (NN) ------------------------
    hmma_g<true,false,true><<<dim3(2,16,2*B_), 256, HM_SMEM_BYTES>>>(
        qh, kh, vh, vh, nullptr, nullptr, vqh, vkh, nullptr, nullptr,
        S_, VP_, E_, E_, E_, VP_, sQE, sVE, sSV, 0, inv, inv, 0.f);
    hmma_g<false,false,true><<<dim3(8,16,2*B_), 256, HM_SMEM_BYTES>>>(
        vqh, vkh, Wvq16, Wvk16, q2, k2, nullptr, nullptr, nullptr, cs,
        S_, E_, 64, VP_, E_, E_, sSV, 0, sQE, E_, 1.f, 1.f, 0.f);

    // ---- stage 4: q2 += f@q ; k2 -= f@k (paired NN, fused fp16 out) --------
    hmma_g<false,true,true><<<dim3(8,16,2*B_), 256, HM_SMEM_BYTES>>>(
        fh, fh, qh, kh, q2, k2, q2h, k2h, nullptr, nullptr,
        S_, E_, S_, S_, E_, E_, sSS, sQE, sQE, 0, 1.f, -1.f, 1.f);

    colsum_kernel<<<dim3(E_/256,B_), 256>>>(k2, cs2, S_, E_);

    // ---- stage 5: outputs (paired NN) --------------------------------------
    hmma_g<false,false,true><<<dim3(8,16,2*B_), 256, HM_SMEM_BYTES>>>(
        fh, fh, q2h, k2h, outQ, outK, nullptr, nullptr, nullptr, cs2,
        S_, E_, S_, S_, E_, E_, sSS, sQE, sQE, E_, 1.f, -1.f, 0.f);

    (void)in_sizes; (void)n_in; (void)out_size;
}

// round 11
// speedup vs baseline: 3.2009x; 1.0554x over previous
#include <cuda_runtime.h>
#include <cuda_fp16.h>
#include <math.h>
#include <stdint.h>

#define B_  4
#define S_  2048
#define SV_ 50
#define E_  1024
#define VP_ 256   // padded v rows per batch

typedef __half fp16;

// ---------------- scratch (device globals) ----------------------------------
__device__ float g_cs [B_*E_];
__device__ float g_cs2[B_*E_];

__device__ fp16 g_Qs[B_*S_*E_];
__device__ fp16 g_Ks[B_*S_*E_];
__device__ fp16 g_Wq16[E_*E_];
__device__ fp16 g_Wk16[E_*E_];
__device__ fp16 g_Wv16[E_*E_];
__device__ fp16 g_Wvq16[64*E_];
__device__ fp16 g_Wvk16[64*E_];
__device__ fp16 g_Vp[B_*VP_*E_];
__device__ fp16 g_vh[B_*VP_*E_];
__device__ fp16 g_qh[B_*S_*E_];
__device__ fp16 g_kh[B_*S_*E_];
__device__ fp16 g_vqh[B_*S_*VP_];
__device__ fp16 g_vkh[B_*S_*VP_];
__device__ fp16 g_fh[(size_t)B_*S_*S_];
__device__ fp16 g_q2b[B_*S_*E_];
__device__ fp16 g_k2b[B_*S_*E_];
__device__ fp16 g_q2h[B_*S_*E_];
__device__ fp16 g_k2h[B_*S_*E_];

// ---------------- PTX helpers ------------------------------------------------
__device__ __forceinline__ uint32_t smem_u32(const void* p) {
    uint32_t a;
    asm("{ .reg .u64 t; cvta.to.shared.u64 t, %1; cvt.u32.u64 %0, t; }"
        : "=r"(a) : "l"(p));
    return a;
}
__device__ __forceinline__ void cp_async16(uint32_t dst, const void* src) {
    asm volatile("cp.async.cg.shared.global [%0], [%1], 16;"
                 :: "r"(dst), "l"(src) : "memory");
}
#define CP_COMMIT() asm volatile("cp.async.commit_group;" ::: "memory")
#define CP_WAIT(n)  asm volatile("cp.async.wait_group %0;" :: "n"(n) : "memory")

#define LDMATRIX_X4(r0, r1, r2, r3, addr) \
    asm volatile("ldmatrix.sync.aligned.m8n8.x4.shared.b16 {%0,%1,%2,%3}, [%4];" \
        : "=r"(r0), "=r"(r1), "=r"(r2), "=r"(r3) : "r"(addr))

#define LDMATRIX_X4_T(r0, r1, r2, r3, addr) \
    asm volatile("ldmatrix.sync.aligned.m8n8.x4.trans.shared.b16 {%0,%1,%2,%3}, [%4];" \
        : "=r"(r0), "=r"(r1), "=r"(r2), "=r"(r3) : "r"(addr))

#define MMA_F16(d, a, b) \
    asm volatile("mma.sync.aligned.m16n8k16.row.col.f32.f16.f16.f32 " \
        "{%0,%1,%2,%3},{%4,%5,%6,%7},{%8,%9},{%0,%1,%2,%3};" \
        : "+f"((d)[0]), "+f"((d)[1]), "+f"((d)[2]), "+f"((d)[3]) \
        : "r"((a)[0]), "r"((a)[1]), "r"((a)[2]), "r"((a)[3]), \
          "r"((b)[0]), "r"((b)[1]))

// ---------------- fp16 HMMA GEMM (NT/NN, paired, fp16 beta-base) -------------
// NT=true : C = alpha * A[M,K] @ B[N,K]^T   (B row-major [N,K])
// NT=false: C = alpha * A[M,K] @ B[K,N]     (B row-major [K,N], ldmatrix.trans)
// BM16: epilogue adds beta * P (fp16 matrix, same layout as outputs).
// PAIR: blockIdx.z = 2*batch + sel. Outputs runtime-selected (C fp32, Oh fp16).
constexpr int HM_BM = 128, HM_BN = 128, HM_BK = 32;
constexpr int HM_LDSA = HM_BK + 8;
constexpr int HM_TILEA_B = HM_BM * HM_LDSA * 2; // 10240 bytes (also NT B tile)
constexpr int HM_LDSB = HM_BN + 8;              // NN B row stride (elems)
constexpr int HM_STAGE_B = 20480;
constexpr int HM_SMEM_BYTES = 4 * HM_STAGE_B;   // 81920

template<bool NT, bool BM16, bool PAIR>
__global__ void __launch_bounds__(256, 2)
hmma_g(const fp16* __restrict__ A0, const fp16* __restrict__ A1,
       const fp16* __restrict__ B0, const fp16* __restrict__ B1,
       float* __restrict__ C0, float* __restrict__ C1,
       fp16* __restrict__ O0, fp16* __restrict__ O1,
       const fp16* __restrict__ P0, const fp16* __restrict__ P1,
       const float* __restrict__ bias0, const float* __restrict__ bias1,
       int M, int N, int K, int lda, int ldb, int ldc,
       long long sA, long long sB, long long sC, long long sBias,
       float alpha0, float alpha1, float beta)
{
    extern __shared__ fp16 sm[];
    const uint32_t sbase = smem_u32(sm);

    int sel, zb;
    if (PAIR) { sel = blockIdx.z & 1; zb = blockIdx.z >> 1; }
    else      { sel = 0;              zb = blockIdx.z; }

    const fp16* Ah = (PAIR && sel ? A1 : A0) + (long long)zb * sA;
    const fp16* Bh = (PAIR && sel ? B1 : B0) + (long long)zb * sB;
    float* C  = (PAIR && sel) ? C1 : C0;
    fp16*  Oh = (PAIR && sel) ? O1 : O0;
    const fp16* P = BM16 ? ((PAIR && sel) ? P1 : P0) : nullptr;
    const float* bias = (PAIR && sel) ? bias1 : bias0;
    const float alpha = (PAIR && sel) ? alpha1 : alpha0;
    const long long co = (long long)zb * sC;
    const float* bp = bias ? (bias + (long long)zb * sBias) : nullptr;

    const int tid = threadIdx.x;
    const int warp = tid >> 5, lane = tid & 31;
    const int wm = warp & 3, wn = warp >> 2;         // 4x2 warps: 32m x 64n
    const int bm = blockIdx.y * HM_BM;
    const int bn = blockIdx.x * HM_BN;
    const int NT_ = K / HM_BK;

    const int c0 = tid, c1 = tid + 256;
    const int r0c = c0 >> 2, e0c = (c0 & 3) * 8;
    const int r1c = c1 >> 2, e1c = (c1 & 3) * 8;
    const int rB0 = c0 >> 4, eB0 = (c0 & 15) * 8;
    const int rB1 = c1 >> 4, eB1 = (c1 & 15) * 8;

    auto issue = [&](int it) {
        if (it >= NT_) return;
        const uint32_t sb0 = sbase + (uint32_t)(it & 3) * HM_STAGE_B;
        const long long ko = (long long)it * HM_BK;
        cp_async16(sb0 + (uint32_t)(r0c * HM_LDSA + e0c) * 2,
                   Ah + (long long)(bm + r0c) * lda + ko + e0c);
        cp_async16(sb0 + (uint32_t)(r1c * HM_LDSA + e1c) * 2,
                   Ah + (long long)(bm + r1c) * lda + ko + e1c);
        if (NT) {
            cp_async16(sb0 + HM_TILEA_B + (uint32_t)(r0c * HM_LDSA + e0c) * 2,
                       Bh + (long long)(bn + r0c) * ldb + ko + e0c);
            cp_async16(sb0 + HM_TILEA_B + (uint32_t)(r1c * HM_LDSA + e1c) * 2,
                       Bh + (long long)(bn + r1c) * ldb + ko + e1c);
        } else {
            cp_async16(sb0 + HM_TILEA_B + (uint32_t)(rB0 * HM_LDSB + eB0) * 2,
                       Bh + (ko + rB0) * (long long)ldb + bn + eB0);
            cp_async16(sb0 + HM_TILEA_B + (uint32_t)(rB1 * HM_LDSB + eB1) * 2,
                       Bh + (ko + rB1) * (long long)ldb + bn + eB1);
        }
    };

    float acc[2][8][4];
#pragma unroll
    for (int m = 0; m < 2; m++)
#pragma unroll
        for (int n = 0; n < 8; n++)
#pragma unroll
            for (int j = 0; j < 4; j++) acc[m][n][j] = 0.f;

    issue(0); CP_COMMIT();
    issue(1); CP_COMMIT();
    issue(2); CP_COMMIT();

    const int lr  = lane & 15;
    const int lc8 = (lane >> 4) << 3;

    for (int kt = 0; kt < NT_; ++kt) {
        CP_WAIT(2);
        __syncthreads();                 // single barrier per kt: orders both
        issue(kt + 3); CP_COMMIT();      // refill of buffer (kt-1)&3 is safe here
        const uint32_t sb0 = sbase + (uint32_t)(kt & 3) * HM_STAGE_B;
#pragma unroll
        for (int ks = 0; ks < 2; ks++) {
            const int k0 = ks * 16;
            uint32_t fA[2][4], fB[8][2];
#pragma unroll
            for (int t = 0; t < 2; t++) {
                uint32_t a = sb0 + (uint32_t)((wm*32 + t*16 + lr) * HM_LDSA + k0 + lc8) * 2;
                LDMATRIX_X4(fA[t][0], fA[t][1], fA[t][2], fA[t][3], a);
            }
            if (NT) {
#pragma unroll
                for (int p = 0; p < 4; p++) {
                    uint32_t a = sb0 + HM_TILEA_B
                               + (uint32_t)((wn*64 + p*16 + lr) * HM_LDSA + k0 + lc8) * 2;
                    uint32_t r0, r1, r2, r3;
                    LDMATRIX_X4(r0, r1, r2, r3, a);
                    fB[p*2][0]   = r0; fB[p*2][1]   = r2;
                    fB[p*2+1][0] = r1; fB[p*2+1][1] = r3;
                }
            } else {
#pragma unroll
                for (int p = 0; p < 4; p++) {
                    uint32_t a = sb0 + HM_TILEA_B
                               + (uint32_t)((k0 + lr) * HM_LDSB + wn*64 + p*16 + lc8) * 2;
                    uint32_t r0, r1, r2, r3;
                    LDMATRIX_X4_T(r0, r1, r2, r3, a);
                    fB[p*2][0]   = r0; fB[p*2][1]   = r1;
                    fB[p*2+1][0] = r2; fB[p*2+1][1] = r3;
                }
            }
#pragma unroll
            for (int m = 0; m < 2; m++)
#pragma unroll
                for (int n = 0; n < 8; n++) MMA_F16(acc[m][n], fA[m], fB[n]);
        }
        // no trailing sync: next iteration's barrier provides the ordering
    }

    // epilogue
    const int qr = lane >> 2, qc = (lane & 3) * 2;
#pragma unroll
    for (int mt = 0; mt < 2; mt++) {
#pragma unroll
        for (int nt = 0; nt < 8; nt++) {
            const int col = bn + wn*64 + nt*8 + qc;
#pragma unroll
            for (int h = 0; h < 2; h++) {
                const int row = bm + wm*32 + mt*16 + qr + h*8;
                const long long o = co + (long long)row * ldc + col;
                float2 v;
                v.x = alpha * acc[mt][nt][h*2 + 0];
                v.y = alpha * acc[mt][nt][h*2 + 1];
                if (BM16) {
                    __half2 pb = *(const __half2*)(P + o);
                    v.x += beta * __half2float(__low2half(pb));
                    v.y += beta * __half2float(__high2half(pb));
                }
                if (bp) { v.x += bp[col]; v.y += bp[col + 1]; }
                if (C)  *(float2*)(C + o) = v;
                if (Oh) *(__half2*)(Oh + o) =
                        __halves2half2(__float2half_rn(v.x), __float2half_rn(v.y));
            }
        }
    }
}

// ---------------- convert kernels --------------------------------------------
template<bool TANH>
__global__ void cvt2_k(const float* __restrict__ x0, const float* __restrict__ x1,
                       fp16* __restrict__ h0, fp16* __restrict__ h1, long long n)
{
    const float* x = blockIdx.y ? x1 : x0;
    fp16* h = blockIdx.y ? h1 : h0;
    long long i = ((long long)blockIdx.x * blockDim.x + threadIdx.x) * 4;
    if (i >= n) return;
    float4 v = *(const float4*)(x + i);
    if (TANH) { v.x = tanhf(v.x); v.y = tanhf(v.y); v.z = tanhf(v.z); v.w = tanhf(v.w); }
    __half2* hp = (__half2*)(h + i);
    hp[0] = __halves2half2(__float2half_rn(v.x), __float2half_rn(v.y));
    hp[1] = __halves2half2(__float2half_rn(v.z), __float2half_rn(v.w));
}

__global__ void cvt3_k(const float* __restrict__ x0, const float* __restrict__ x1,
                       const float* __restrict__ x2,
                       fp16* __restrict__ h0, fp16* __restrict__ h1,
                       fp16* __restrict__ h2, long long n)
{
    const float* x = (blockIdx.y == 0) ? x0 : (blockIdx.y == 1) ? x1 : x2;
    fp16* h = (blockIdx.y == 0) ? h0 : (blockIdx.y == 1) ? h1 : h2;
    long long i = ((long long)blockIdx.x * blockDim.x + threadIdx.x) * 4;
    if (i >= n) return;
    float4 v = *(const float4*)(x + i);
    __half2* hp = (__half2*)(h + i);
    hp[0] = __halves2half2(__float2half_rn(v.x), __float2half_rn(v.y));
    hp[1] = __halves2half2(__float2half_rn(v.z), __float2half_rn(v.w));
}

__global__ void padcvtW2_k(const float* __restrict__ W0, const float* __restrict__ W1,
                           fp16* __restrict__ h0, fp16* __restrict__ h1)
{
    const float* W = blockIdx.y ? W1 : W0;
    fp16* h = blockIdx.y ? h1 : h0;
    long long i = ((long long)blockIdx.x * blockDim.x + threadIdx.x) * 4;
    if (i >= 64 * E_) return;
    int r = (int)(i / E_), e = (int)(i % E_);
    float4 v = make_float4(0.f, 0.f, 0.f, 0.f);
    if (r < SV_) v = *(const float4*)(W + (long long)r * E_ + e);
    __half2* hp = (__half2*)(h + i);
    hp[0] = __halves2half2(__float2half_rn(v.x), __float2half_rn(v.y));
    hp[1] = __halves2half2(__float2half_rn(v.z), __float2half_rn(v.w));
}

__global__ void padcvtV_k(const float* __restrict__ V, fp16* __restrict__ h)
{
    long long i = ((long long)blockIdx.x * blockDim.x + threadIdx.x) * 4;
    int b = (int)(i / (VP_ * E_));
    int rem = (int)(i % (VP_ * E_));
    int r = rem / E_, e = rem % E_;
    float4 v = make_float4(0.f, 0.f, 0.f, 0.f);
    if (r < SV_) {
        v = *(const float4*)(V + ((long long)(b * SV_ + r)) * E_ + e);
        v.x = tanhf(v.x); v.y = tanhf(v.y); v.z = tanhf(v.z); v.w = tanhf(v.w);
    }
    __half2* hp = (__half2*)(h + i);
    hp[0] = __halves2half2(__float2half_rn(v.x), __float2half_rn(v.y));
    hp[1] = __halves2half2(__float2half_rn(v.z), __float2half_rn(v.w));
}

// ---------------- softmax (+ fused cvt) / colsum -----------------------------
__global__ void softmax_cvt(float* __restrict__ x, fp16* __restrict__ h, int cols)
{
    long long r = blockIdx.x;
    float* p = x + r * (long long)cols;
    __shared__ float red[256];
    int t = threadIdx.x;
    float mx = -INFINITY;
    for (int c = t; c < cols; c += 256) mx = fmaxf(mx, p[c]);
    red[t] = mx; __syncthreads();
    for (int s = 128; s > 0; s >>= 1) { if (t < s) red[t] = fmaxf(red[t], red[t + s]); __syncthreads(); }
    mx = red[0]; __syncthreads();
    float sum = 0.f;
    for (int c = t; c < cols; c += 256) { float e = expf(p[c] - mx); p[c] = e; sum += e; }
    red[t] = sum; __syncthreads();
    for (int s = 128; s > 0; s >>= 1) { if (t < s) red[t] += red[t + s]; __syncthreads(); }
    float inv = 1.f / red[0];
    long long base = r * (long long)cols;
    for (int c = t; c < cols; c += 256) {
        float val = p[c] * inv;
        p[c] = val;
        h[base + c] = __float2half_rn(val);
    }
}

// colsum over fp16 input: out[b,e] = sum_t x[b,t,e]
__global__ void colsum16_k(const fp16* __restrict__ x, float* __restrict__ out,
                           int T, int E)
{
    int e = blockIdx.x * blockDim.x + threadIdx.x;
    int b = blockIdx.y;
    const fp16* p = x + (long long)b * T * E + e;
    float s = 0.f;
    for (int t = 0; t < T; t++) s += __half2float(p[(long long)t * E]);
    out[(long long)b * E + e] = s;
}

// ---------------- host launcher ----------------------------------------------
extern "C" void kernel_launch(void* const* d_in, const int* in_sizes, int n_in,
                              void* d_out, int out_size)
{
    const float* Q    = (const float*)d_in[0];
    const float* K    = (const float*)d_in[1];
    const float* V    = (const float*)d_in[2];
    const float* W_Q  = (const float*)d_in[3];
    const float* W_K  = (const float*)d_in[4];
    const float* W_v  = (const float*)d_in[5];
    const float* W_vq = (const float*)d_in[6];
    const float* W_vk = (const float*)d_in[7];

    float* out  = (float*)d_out;
    float* outQ = out;
    float* outK = out + (long long)B_ * S_ * E_;
    float* f    = out + 2ll * B_ * S_ * E_;

    float *cs, *cs2;
    cudaGetSymbolAddress((void**)&cs,  g_cs);
    cudaGetSymbolAddress((void**)&cs2, g_cs2);

    fp16 *Qs,*Ks,*Wq16,*Wk16,*Wv16,*Wvq16,*Wvk16,*Vp,*vh;
    fp16 *qh,*kh,*vqh,*vkh,*fh,*q2b,*k2b,*q2h,*k2h;
    cudaGetSymbolAddress((void**)&Qs,    g_Qs);
    cudaGetSymbolAddress((void**)&Ks,    g_Ks);
    cudaGetSymbolAddress((void**)&Wq16,  g_Wq16);
    cudaGetSymbolAddress((void**)&Wk16,  g_Wk16);
    cudaGetSymbolAddress((void**)&Wv16,  g_Wv16);
    cudaGetSymbolAddress((void**)&Wvq16, g_Wvq16);
    cudaGetSymbolAddress((void**)&Wvk16, g_Wvk16);
    cudaGetSymbolAddress((void**)&Vp,    g_Vp);
    cudaGetSymbolAddress((void**)&vh,    g_vh);
    cudaGetSymbolAddress((void**)&qh,    g_qh);
    cudaGetSymbolAddress((void**)&kh,    g_kh);
    cudaGetSymbolAddress((void**)&vqh,   g_vqh);
    cudaGetSymbolAddress((void**)&vkh,   g_vkh);
    cudaGetSymbolAddress((void**)&fh,    g_fh);
    cudaGetSymbolAddress((void**)&q2b,   g_q2b);
    cudaGetSymbolAddress((void**)&k2b,   g_k2b);
    cudaGetSymbolAddress((void**)&q2h,   g_q2h);
    cudaGetSymbolAddress((void**)&k2h,   g_k2h);

    cudaFuncSetAttribute(hmma_g<false,false,false>, cudaFuncAttributeMaxDynamicSharedMemorySize, HM_SMEM_BYTES);
    cudaFuncSetAttribute(hmma_g<false,false,true >, cudaFuncAttributeMaxDynamicSharedMemorySize, HM_SMEM_BYTES);
    cudaFuncSetAttribute(hmma_g<true ,false,false>, cudaFuncAttributeMaxDynamicSharedMemorySize, HM_SMEM_BYTES);
    cudaFuncSetAttribute(hmma_g<true ,false,true >, cudaFuncAttributeMaxDynamicSharedMemorySize, HM_SMEM_BYTES);
    cudaFuncSetAttribute(hmma_g<false,true ,true >, cudaFuncAttributeMaxDynamicSharedMemorySize, HM_SMEM_BYTES);

    const float inv = 1.0f / 32.0f;  // 1/sqrt(1024)
    const long long sQE = (long long)S_ * E_;
    const long long sSS = (long long)S_ * S_;
    const long long sVE = (long long)VP_ * E_;
    const long long sSV = (long long)S_ * VP_;
    const long long nQE = (long long)B_ * S_ * E_;

    // ---- stage 0: input conversions ----------------------------------------
    cvt2_k<true><<<dim3((int)(nQE/4/256), 2), 256>>>(Q, K, Qs, Ks, nQE);
    cvt3_k<<<dim3((int)((long long)E_*E_/4/256), 3), 256>>>(
        W_Q, W_K, W_v, Wq16, Wk16, Wv16, (long long)E_*E_);
    padcvtW2_k<<<dim3(64, 2), 256>>>(W_vq, W_vk, Wvq16, Wvk16);
    padcvtV_k<<<(int)(B_*VP_*E_/4/256), 256>>>(V, Vp);

    // ---- stage 1: paired Q/K projections (NN, fp16 out only) + v -----------
    hmma_g<false,false,true><<<dim3(8,64,2), 256, HM_SMEM_BYTES>>>(
        Qs, Ks, Wq16, Wk16, nullptr, nullptr, qh, kh, nullptr, nullptr,
        nullptr, nullptr,
        B_*S_, E_, E_, E_, E_, E_, 0,0,0,0, 1.f, 1.f, 0.f);
    hmma_g<false,false,false><<<dim3(8,8,1), 256, HM_SMEM_BYTES>>>(
        Vp, nullptr, Wv16, nullptr, nullptr, nullptr, vh, nullptr, nullptr, nullptr,
        nullptr, nullptr,
        B_*VP_, E_, E_, E_, E_, E_, 0,0,0,0, 1.f, 0.f, 0.f);

    colsum16_k<<<dim3(E_/256,B_), 256>>>(kh, cs, S_, E_);

    // ---- stage 3: f = softmax(q@k^T/32) (NT) -------------------------------
    hmma_g<true,false,false><<<dim3(16,16,B_), 256, HM_SMEM_BYTES>>>(
        qh, nullptr, kh, nullptr, f, nullptr, nullptr, nullptr, nullptr, nullptr,
        nullptr, nullptr,
        S_, S_, E_, E_, E_, S_, sQE, sQE, sSS, 0, inv, 0.f, 0.f);
    softmax_cvt<<<B_*S_, 256>>>(f, fh, S_);

    // ---- vq/vk paired (NT) + q2/k2 base paired (NN, fp16 out) --------------
    hmma_g<true,false,true><<<dim3(2,16,2*B_), 256, HM_SMEM_BYTES>>>(
        qh, kh, vh, vh, nullptr, nullptr, vqh, vkh, nullptr, nullptr,
        nullptr, nullptr,
        S_, VP_, E_, E_, E_, VP_, sQE, sVE, sSV, 0, inv, inv, 0.f);
    hmma_g<false,false,true><<<dim3(8,16,2*B_), 256, HM_SMEM_BYTES>>>(
        vqh, vkh, Wvq16, Wvk16, nullptr, nullptr, q2b, k2b, nullptr, nullptr,
        nullptr, cs,
        S_, E_, 64, VP_, E_, E_, sSV, 0, sQE, E_, 1.f, 1.f, 0.f);

    // ---- stage 4: q2 = f@q + q2b ; k2 = -(f@k) + k2b (fp16 base + out) -----
    hmma_g<false,true,true><<<dim3(8,16,2*B_), 256, HM_SMEM_BYTES>>>(
        fh, fh, qh, kh, nullptr, nullptr, q2h, k2h, q2b, k2b,
        nullptr, nullptr,
        S_, E_, S_, S_, E_, E_, sSS, sQE, sQE, 0, 1.f, -1.f, 1.f);

    colsum16_k<<<dim3(E_/256,B_), 256>>>(k2h, cs2, S_, E_);

    // ---- stage 5: outputs (paired NN) --------------------------------------
    hmma_g<false,false,true><<<dim3(8,16,2*B_), 256, HM_SMEM_BYTES>>>(
        fh, fh, q2h, k2h, outQ, outK, nullptr, nullptr, nullptr, nullptr,
        nullptr, cs2,
        S_, E_, S_, S_, E_, E_, sSS, sQE, sQE, E_, 1.f, -1.f, 0.f);

    (void)in_sizes; (void)n_in; (void)out_size;
}

// round 12
// speedup vs baseline: 3.2306x; 1.0093x over previous
#include <cuda_runtime.h>
#include <cuda_fp16.h>
#include <math.h>
#include <stdint.h>

#define B_  4
#define S_  2048
#define SV_ 50
#define E_  1024
#define VP_ 128   // padded v rows per batch (>=64 needed; 128 = BN)

typedef __half fp16;

// ---------------- scratch (device globals) ----------------------------------
__device__ float g_cs [B_*E_];
__device__ float g_cs2[B_*E_];

__device__ fp16 g_Qs[B_*S_*E_];
__device__ fp16 g_Ks[B_*S_*E_];
__device__ fp16 g_Wq16[E_*E_];
__device__ fp16 g_Wk16[E_*E_];
__device__ fp16 g_Wv16[E_*E_];
__device__ fp16 g_Wvq16[64*E_];
__device__ fp16 g_Wvk16[64*E_];
__device__ fp16 g_Vp[B_*VP_*E_];
__device__ fp16 g_vh[B_*VP_*E_];
__device__ fp16 g_qh[B_*S_*E_];
__device__ fp16 g_kh[B_*S_*E_];
__device__ fp16 g_vqh[B_*S_*VP_];
__device__ fp16 g_vkh[B_*S_*VP_];
__device__ fp16 g_fh[(size_t)B_*S_*S_];
__device__ fp16 g_q2b[B_*S_*E_];
__device__ fp16 g_k2b[B_*S_*E_];
__device__ fp16 g_q2h[B_*S_*E_];
__device__ fp16 g_k2h[B_*S_*E_];

// ---------------- PTX helpers ------------------------------------------------
__device__ __forceinline__ uint32_t smem_u32(const void* p) {
    uint32_t a;
    asm("{ .reg .u64 t; cvta.to.shared.u64 t, %1; cvt.u32.u64 %0, t; }"
        : "=r"(a) : "l"(p));
    return a;
}
__device__ __forceinline__ void cp_async16(uint32_t dst, const void* src) {
    asm volatile("cp.async.cg.shared.global [%0], [%1], 16;"
                 :: "r"(dst), "l"(src) : "memory");
}
#define CP_COMMIT() asm volatile("cp.async.commit_group;" ::: "memory")
#define CP_WAIT(n)  asm volatile("cp.async.wait_group %0;" :: "n"(n) : "memory")

#define LDMATRIX_X4(r0, r1, r2, r3, addr) \
    asm volatile("ldmatrix.sync.aligned.m8n8.x4.shared.b16 {%0,%1,%2,%3}, [%4];" \
        : "=r"(r0), "=r"(r1), "=r"(r2), "=r"(r3) : "r"(addr))

#define LDMATRIX_X4_T(r0, r1, r2, r3, addr) \
    asm volatile("ldmatrix.sync.aligned.m8n8.x4.trans.shared.b16 {%0,%1,%2,%3}, [%4];" \
        : "=r"(r0), "=r"(r1), "=r"(r2), "=r"(r3) : "r"(addr))

#define MMA_F16(d, a, b) \
    asm volatile("mma.sync.aligned.m16n8k16.row.col.f32.f16.f16.f32 " \
        "{%0,%1,%2,%3},{%4,%5,%6,%7},{%8,%9},{%0,%1,%2,%3};" \
        : "+f"((d)[0]), "+f"((d)[1]), "+f"((d)[2]), "+f"((d)[3]) \
        : "r"((a)[0]), "r"((a)[1]), "r"((a)[2]), "r"((a)[3]), \
          "r"((b)[0]), "r"((b)[1]))

// ---------------- fp16 HMMA GEMM (NT/NN, paired, fp16 beta-base) -------------
// NT=true : C = alpha * A[M,K] @ B[N,K]^T   (B row-major [N,K])
// NT=false: C = alpha * A[M,K] @ B[K,N]     (B row-major [K,N], ldmatrix.trans)
// BM16: epilogue adds beta * P (fp16 matrix, same layout as outputs).
// PAIR: blockIdx.z = 2*batch + sel. Outputs runtime-selected (C fp32, Oh fp16).
constexpr int HM_BM = 128, HM_BN = 128, HM_BK = 32;
constexpr int HM_LDSA = HM_BK + 8;
constexpr int HM_TILEA_B = HM_BM * HM_LDSA * 2; // 10240 bytes (also NT B tile)
constexpr int HM_LDSB = HM_BN + 8;              // NN B row stride (elems)
constexpr int HM_STAGE_B = 20480;
constexpr int HM_SMEM_BYTES = 4 * HM_STAGE_B;   // 81920

template<bool NT, bool BM16, bool PAIR>
__global__ void __launch_bounds__(256, 2)
hmma_g(const fp16* __restrict__ A0, const fp16* __restrict__ A1,
       const fp16* __restrict__ B0, const fp16* __restrict__ B1,
       float* __restrict__ C0, float* __restrict__ C1,
       fp16* __restrict__ O0, fp16* __restrict__ O1,
       const fp16* __restrict__ P0, const fp16* __restrict__ P1,
       const float* __restrict__ bias0, const float* __restrict__ bias1,
       int M, int N, int K, int lda, int ldb, int ldc,
       long long sA, long long sB, long long sC, long long sBias,
       float alpha0, float alpha1, float beta)
{
    extern __shared__ fp16 sm[];
    const uint32_t sbase = smem_u32(sm);

    int sel, zb;
    if (PAIR) { sel = blockIdx.z & 1; zb = blockIdx.z >> 1; }
    else      { sel = 0;              zb = blockIdx.z; }

    const fp16* Ah = (PAIR && sel ? A1 : A0) + (long long)zb * sA;
    const fp16* Bh = (PAIR && sel ? B1 : B0) + (long long)zb * sB;
    float* C  = (PAIR && sel) ? C1 : C0;
    fp16*  Oh = (PAIR && sel) ? O1 : O0;
    const fp16* P = BM16 ? ((PAIR && sel) ? P1 : P0) : nullptr;
    const float* bias = (PAIR && sel) ? bias1 : bias0;
    const float alpha = (PAIR && sel) ? alpha1 : alpha0;
    const long long co = (long long)zb * sC;
    const float* bp = bias ? (bias + (long long)zb * sBias) : nullptr;

    const int tid = threadIdx.x;
    const int warp = tid >> 5, lane = tid & 31;
    const int wm = warp & 3, wn = warp >> 2;         // 4x2 warps: 32m x 64n
    const int bm = blockIdx.y * HM_BM;
    const int bn = blockIdx.x * HM_BN;
    const int NT_ = K / HM_BK;

    const int c0 = tid, c1 = tid + 256;
    const int r0c = c0 >> 2, e0c = (c0 & 3) * 8;
    const int r1c = c1 >> 2, e1c = (c1 & 3) * 8;
    const int rB0 = c0 >> 4, eB0 = (c0 & 15) * 8;
    const int rB1 = c1 >> 4, eB1 = (c1 & 15) * 8;

    auto issue = [&](int it) {
        if (it >= NT_) return;
        const uint32_t sb0 = sbase + (uint32_t)(it & 3) * HM_STAGE_B;
        const long long ko = (long long)it * HM_BK;
        cp_async16(sb0 + (uint32_t)(r0c * HM_LDSA + e0c) * 2,
                   Ah + (long long)(bm + r0c) * lda + ko + e0c);
        cp_async16(sb0 + (uint32_t)(r1c * HM_LDSA + e1c) * 2,
                   Ah + (long long)(bm + r1c) * lda + ko + e1c);
        if (NT) {
            cp_async16(sb0 + HM_TILEA_B + (uint32_t)(r0c * HM_LDSA + e0c) * 2,
                       Bh + (long long)(bn + r0c) * ldb + ko + e0c);
            cp_async16(sb0 + HM_TILEA_B + (uint32_t)(r1c * HM_LDSA + e1c) * 2,
                       Bh + (long long)(bn + r1c) * ldb + ko + e1c);
        } else {
            cp_async16(sb0 + HM_TILEA_B + (uint32_t)(rB0 * HM_LDSB + eB0) * 2,
                       Bh + (ko + rB0) * (long long)ldb + bn + eB0);
            cp_async16(sb0 + HM_TILEA_B + (uint32_t)(rB1 * HM_LDSB + eB1) * 2,
                       Bh + (ko + rB1) * (long long)ldb + bn + eB1);
        }
    };

    float acc[2][8][4];
#pragma unroll
    for (int m = 0; m < 2; m++)
#pragma unroll
        for (int n = 0; n < 8; n++)
#pragma unroll
            for (int j = 0; j < 4; j++) acc[m][n][j] = 0.f;

    issue(0); CP_COMMIT();
    issue(1); CP_COMMIT();
    issue(2); CP_COMMIT();

    const int lr  = lane & 15;
    const int lc8 = (lane >> 4) << 3;

    for (int kt = 0; kt < NT_; ++kt) {
        CP_WAIT(2);
        __syncthreads();                 // single barrier per kt
        issue(kt + 3); CP_COMMIT();      // refill of retired buffer is safe here
        const uint32_t sb0 = sbase + (uint32_t)(kt & 3) * HM_STAGE_B;
#pragma unroll
        for (int ks = 0; ks < 2; ks++) {
            const int k0 = ks * 16;
            uint32_t fA[2][4], fB[8][2];
#pragma unroll
            for (int t = 0; t < 2; t++) {
                uint32_t a = sb0 + (uint32_t)((wm*32 + t*16 + lr) * HM_LDSA + k0 + lc8) * 2;
                LDMATRIX_X4(fA[t][0], fA[t][1], fA[t][2], fA[t][3], a);
            }
            if (NT) {
#pragma unroll
                for (int p = 0; p < 4; p++) {
                    uint32_t a = sb0 + HM_TILEA_B
                               + (uint32_t)((wn*64 + p*16 + lr) * HM_LDSA + k0 + lc8) * 2;
                    uint32_t r0, r1, r2, r3;
                    LDMATRIX_X4(r0, r1, r2, r3, a);
                    fB[p*2][0]   = r0; fB[p*2][1]   = r2;
                    fB[p*2+1][0] = r1; fB[p*2+1][1] = r3;
                }
            } else {
#pragma unroll
                for (int p = 0; p < 4; p++) {
                    uint32_t a = sb0 + HM_TILEA_B
                               + (uint32_t)((k0 + lr) * HM_LDSB + wn*64 + p*16 + lc8) * 2;
                    uint32_t r0, r1, r2, r3;
                    LDMATRIX_X4_T(r0, r1, r2, r3, a);
                    fB[p*2][0]   = r0; fB[p*2][1]   = r1;
                    fB[p*2+1][0] = r2; fB[p*2+1][1] = r3;
                }
            }
#pragma unroll
            for (int m = 0; m < 2; m++)
#pragma unroll
                for (int n = 0; n < 8; n++) MMA_F16(acc[m][n], fA[m], fB[n]);
        }
    }

    // epilogue
    const int qr = lane >> 2, qc = (lane & 3) * 2;
#pragma unroll
    for (int mt = 0; mt < 2; mt++) {
#pragma unroll
        for (int nt = 0; nt < 8; nt++) {
            const int col = bn + wn*64 + nt*8 + qc;
#pragma unroll
            for (int h = 0; h < 2; h++) {
                const int row = bm + wm*32 + mt*16 + qr + h*8;
                const long long o = co + (long long)row * ldc + col;
                float2 v;
                v.x = alpha * acc[mt][nt][h*2 + 0];
                v.y = alpha * acc[mt][nt][h*2 + 1];
                if (BM16) {
                    __half2 pb = *(const __half2*)(P + o);
                    v.x += beta * __half2float(__low2half(pb));
                    v.y += beta * __half2float(__high2half(pb));
                }
                if (bp) { v.x += bp[col]; v.y += bp[col + 1]; }
                if (C)  *(float2*)(C + o) = v;
                if (Oh) *(__half2*)(Oh + o) =
                        __halves2half2(__float2half_rn(v.x), __float2half_rn(v.y));
            }
        }
    }
}

// ---------------- convert kernels --------------------------------------------
template<bool TANH>
__global__ void cvt2_k(const float* __restrict__ x0, const float* __restrict__ x1,
                       fp16* __restrict__ h0, fp16* __restrict__ h1, long long n)
{
    const float* x = blockIdx.y ? x1 : x0;
    fp16* h = blockIdx.y ? h1 : h0;
    long long i = ((long long)blockIdx.x * blockDim.x + threadIdx.x) * 4;
    if (i >= n) return;
    float4 v = *(const float4*)(x + i);
    if (TANH) { v.x = tanhf(v.x); v.y = tanhf(v.y); v.z = tanhf(v.z); v.w = tanhf(v.w); }
    __half2* hp = (__half2*)(h + i);
    hp[0] = __halves2half2(__float2half_rn(v.x), __float2half_rn(v.y));
    hp[1] = __halves2half2(__float2half_rn(v.z), __float2half_rn(v.w));
}

__global__ void cvt3_k(const float* __restrict__ x0, const float* __restrict__ x1,
                       const float* __restrict__ x2,
                       fp16* __restrict__ h0, fp16* __restrict__ h1,
                       fp16* __restrict__ h2, long long n)
{
    const float* x = (blockIdx.y == 0) ? x0 : (blockIdx.y == 1) ? x1 : x2;
    fp16* h = (blockIdx.y == 0) ? h0 : (blockIdx.y == 1) ? h1 : h2;
    long long i = ((long long)blockIdx.x * blockDim.x + threadIdx.x) * 4;
    if (i >= n) return;
    float4 v = *(const float4*)(x + i);
    __half2* hp = (__half2*)(h + i);
    hp[0] = __halves2half2(__float2half_rn(v.x), __float2half_rn(v.y));
    hp[1] = __halves2half2(__float2half_rn(v.z), __float2half_rn(v.w));
}

__global__ void padcvtW2_k(const float* __restrict__ W0, const float* __restrict__ W1,
                           fp16* __restrict__ h0, fp16* __restrict__ h1)
{
    const float* W = blockIdx.y ? W1 : W0;
    fp16* h = blockIdx.y ? h1 : h0;
    long long i = ((long long)blockIdx.x * blockDim.x + threadIdx.x) * 4;
    if (i >= 64 * E_) return;
    int r = (int)(i / E_), e = (int)(i % E_);
    float4 v = make_float4(0.f, 0.f, 0.f, 0.f);
    if (r < SV_) v = *(const float4*)(W + (long long)r * E_ + e);
    __half2* hp = (__half2*)(h + i);
    hp[0] = __halves2half2(__float2half_rn(v.x), __float2half_rn(v.y));
    hp[1] = __halves2half2(__float2half_rn(v.z), __float2half_rn(v.w));
}

__global__ void padcvtV_k(const float* __restrict__ V, fp16* __restrict__ h)
{
    long long i = ((long long)blockIdx.x * blockDim.x + threadIdx.x) * 4;
    if (i >= (long long)B_ * VP_ * E_) return;
    int b = (int)(i / (VP_ * E_));
    int rem = (int)(i % (VP_ * E_));
    int r = rem / E_, e = rem % E_;
    float4 v = make_float4(0.f, 0.f, 0.f, 0.f);
    if (r < SV_) {
        v = *(const float4*)(V + ((long long)(b * SV_ + r)) * E_ + e);
        v.x = tanhf(v.x); v.y = tanhf(v.y); v.z = tanhf(v.z); v.w = tanhf(v.w);
    }
    __half2* hp = (__half2*)(h + i);
    hp[0] = __halves2half2(__float2half_rn(v.x), __float2half_rn(v.y));
    hp[1] = __halves2half2(__float2half_rn(v.z), __float2half_rn(v.w));
}

// ---------------- softmax (register-resident, fused cvt) ---------------------
// cols must equal 8*256 = 2048
__global__ void softmax_cvt(float* __restrict__ x, fp16* __restrict__ h, int cols)
{
    long long r = blockIdx.x;
    float* p = x + r * (long long)cols;
    __shared__ float red[256];
    const int t = threadIdx.x;

    float vals[8];
#pragma unroll
    for (int i = 0; i < 8; i++) vals[i] = p[t + i * 256];

    float mx = vals[0];
#pragma unroll
    for (int i = 1; i < 8; i++) mx = fmaxf(mx, vals[i]);
    red[t] = mx; __syncthreads();
    for (int s = 128; s > 0; s >>= 1) { if (t < s) red[t] = fmaxf(red[t], red[t + s]); __syncthreads(); }
    mx = red[0]; __syncthreads();

    float sum = 0.f;
#pragma unroll
    for (int i = 0; i < 8; i++) { vals[i] = expf(vals[i] - mx); sum += vals[i]; }
    red[t] = sum; __syncthreads();
    for (int s = 128; s > 0; s >>= 1) { if (t < s) red[t] += red[t + s]; __syncthreads(); }
    const float inv = 1.f / red[0];

    fp16* hp = h + r * (long long)cols;
#pragma unroll
    for (int i = 0; i < 8; i++) {
        float val = vals[i] * inv;
        p[t + i * 256] = val;
        hp[t + i * 256] = __float2half_rn(val);
    }
}

// colsum over fp16 input: out[b,e] = sum_t x[b,t,e]
__global__ void colsum16_k(const fp16* __restrict__ x, float* __restrict__ out,
                           int T, int E)
{
    int e = blockIdx.x * blockDim.x + threadIdx.x;
    int b = blockIdx.y;
    const fp16* p = x + (long long)b * T * E + e;
    float s = 0.f;
    for (int t = 0; t < T; t++) s += __half2float(p[(long long)t * E]);
    out[(long long)b * E + e] = s;
}

// ---------------- host launcher ----------------------------------------------
extern "C" void kernel_launch(void* const* d_in, const int* in_sizes, int n_in,
                              void* d_out, int out_size)
{
    const float* Q    = (const float*)d_in[0];
    const float* K    = (const float*)d_in[1];
    const float* V    = (const float*)d_in[2];
    const float* W_Q  = (const float*)d_in[3];
    const float* W_K  = (const float*)d_in[4];
    const float* W_v  = (const float*)d_in[5];
    const float* W_vq = (const float*)d_in[6];
    const float* W_vk = (const float*)d_in[7];

    float* out  = (float*)d_out;
    float* outQ = out;
    float* outK = out + (long long)B_ * S_ * E_;
    float* f    = out + 2ll * B_ * S_ * E_;

    float *cs, *cs2;
    cudaGetSymbolAddress((void**)&cs,  g_cs);
    cudaGetSymbolAddress((void**)&cs2, g_cs2);

    fp16 *Qs,*Ks,*Wq16,*Wk16,*Wv16,*Wvq16,*Wvk16,*Vp,*vh;
    fp16 *qh,*kh,*vqh,*vkh,*fh,*q2b,*k2b,*q2h,*k2h;
    cudaGetSymbolAddress((void**)&Qs,    g_Qs);
    cudaGetSymbolAddress((void**)&Ks,    g_Ks);
    cudaGetSymbolAddress((void**)&Wq16,  g_Wq16);
    cudaGetSymbolAddress((void**)&Wk16,  g_Wk16);
    cudaGetSymbolAddress((void**)&Wv16,  g_Wv16);
    cudaGetSymbolAddress((void**)&Wvq16, g_Wvq16);
    cudaGetSymbolAddress((void**)&Wvk16, g_Wvk16);
    cudaGetSymbolAddress((void**)&Vp,    g_Vp);
    cudaGetSymbolAddress((void**)&vh,    g_vh);
    cudaGetSymbolAddress((void**)&qh,    g_qh);
    cudaGetSymbolAddress((void**)&kh,    g_kh);
    cudaGetSymbolAddress((void**)&vqh,   g_vqh);
    cudaGetSymbolAddress((void**)&vkh,   g_vkh);
    cudaGetSymbolAddress((void**)&fh,    g_fh);
    cudaGetSymbolAddress((void**)&q2b,   g_q2b);
    cudaGetSymbolAddress((void**)&k2b,   g_k2b);
    cudaGetSymbolAddress((void**)&q2h,   g_q2h);
    cudaGetSymbolAddress((void**)&k2h,   g_k2h);

    cudaFuncSetAttribute(hmma_g<false,false,false>, cudaFuncAttributeMaxDynamicSharedMemorySize, HM_SMEM_BYTES);
    cudaFuncSetAttribute(hmma_g<false,false,true >, cudaFuncAttributeMaxDynamicSharedMemorySize, HM_SMEM_BYTES);
    cudaFuncSetAttribute(hmma_g<true ,false,false>, cudaFuncAttributeMaxDynamicSharedMemorySize, HM_SMEM_BYTES);
    cudaFuncSetAttribute(hmma_g<true ,false,true >, cudaFuncAttributeMaxDynamicSharedMemorySize, HM_SMEM_BYTES);
    cudaFuncSetAttribute(hmma_g<false,true ,true >, cudaFuncAttributeMaxDynamicSharedMemorySize, HM_SMEM_BYTES);

    const float inv = 1.0f / 32.0f;  // 1/sqrt(1024)
    const long long sQE = (long long)S_ * E_;
    const long long sSS = (long long)S_ * S_;
    const long long sVE = (long long)VP_ * E_;
    const long long sSV = (long long)S_ * VP_;
    const long long nQE = (long long)B_ * S_ * E_;

    // ---- stage 0: input conversions ----------------------------------------
    cvt2_k<true><<<dim3((int)(nQE/4/256), 2), 256>>>(Q, K, Qs, Ks, nQE);
    cvt3_k<<<dim3((int)((long long)E_*E_/4/256), 3), 256>>>(
        W_Q, W_K, W_v, Wq16, Wk16, Wv16, (long long)E_*E_);
    padcvtW2_k<<<dim3(64, 2), 256>>>(W_vq, W_vk, Wvq16, Wvk16);
    padcvtV_k<<<(int)((long long)B_*VP_*E_/4/256), 256>>>(V, Vp);

    // ---- stage 1: paired Q/K projections (NN, fp16 out only) + v -----------
    hmma_g<false,false,true><<<dim3(8,64,2), 256, HM_SMEM_BYTES>>>(
        Qs, Ks, Wq16, Wk16, nullptr, nullptr, qh, kh, nullptr, nullptr,
        nullptr, nullptr,
        B_*S_, E_, E_, E_, E_, E_, 0,0,0,0, 1.f, 1.f, 0.f);
    hmma_g<false,false,false><<<dim3(8,(B_*VP_)/128,1), 256, HM_SMEM_BYTES>>>(
        Vp, nullptr, Wv16, nullptr, nullptr, nullptr, vh, nullptr, nullptr, nullptr,
        nullptr, nullptr,
        B_*VP_, E_, E_, E_, E_, E_, 0,0,0,0, 1.f, 0.f, 0.f);

    colsum16_k<<<dim3(E_/256,B_), 256>>>(kh, cs, S_, E_);

    // ---- stage 3: f = softmax(q@k^T/32) (NT) -------------------------------
    hmma_g<true,false,false><<<dim3(16,16,B_), 256, HM_SMEM_BYTES>>>(
        qh, nullptr, kh, nullptr, f, nullptr, nullptr, nullptr, nullptr, nullptr,
        nullptr, nullptr,
        S_, S_, E_, E_, E_, S_, sQE, sQE, sSS, 0, inv, 0.f, 0.f);
    softmax_cvt<<<B_*S_, 256>>>(f, fh, S_);

    // ---- vq/vk paired (NT, N=VP=128) + q2/k2 base paired (NN) --------------
    hmma_g<true,false,true><<<dim3(VP_/128,16,2*B_), 256, HM_SMEM_BYTES>>>(
        qh, kh, vh, vh, nullptr, nullptr, vqh, vkh, nullptr, nullptr,
        nullptr, nullptr,
        S_, VP_, E_, E_, E_, VP_, sQE, sVE, sSV, 0, inv, inv, 0.f);
    hmma_g<false,false,true><<<dim3(8,16,2*B_), 256, HM_SMEM_BYTES>>>(
        vqh, vkh, Wvq16, Wvk16, nullptr, nullptr, q2b, k2b, nullptr, nullptr,
        nullptr, cs,
        S_, E_, 64, VP_, E_, E_, sSV, 0, sQE, E_, 1.f, 1.f, 0.f);

    // ---- stage 4: q2 = f@q + q2b ; k2 = -(f@k) + k2b (fp16 base + out) -----
    hmma_g<false,true,true><<<dim3(8,16,2*B_), 256, HM_SMEM_BYTES>>>(
        fh, fh, qh, kh, nullptr, nullptr, q2h, k2h, q2b, k2b,
        nullptr, nullptr,
        S_, E_, S_, S_, E_, E_, sSS, sQE, sQE, 0, 1.f, -1.f, 1.f);

    colsum16_k<<<dim3(E_/256,B_), 256>>>(k2h, cs2, S_, E_);

    // ---- stage 5: outputs (paired NN) --------------------------------------
    hmma_g<false,false,true><<<dim3(8,16,2*B_), 256, HM_SMEM_BYTES>>>(
        fh, fh, q2h, k2h, outQ, outK, nullptr, nullptr, nullptr, nullptr,
        nullptr, cs2,
        S_, E_, S_, S_, E_, E_, sSS, sQE, sQE, E_, 1.f, -1.f, 0.f);

    (void)in_sizes; (void)n_in; (void)out_size;
}